// round 2
// baseline (speedup 1.0000x reference)
#include <cuda_runtime.h>
#include <math.h>

#define Bn 256
#define Ldim 64
#define Sn 12
#define Dn 100
#define NUM_NODE 43098
#define NOUT 43097
#define NEGV -9000000000000000.0f

// ---------------- scratch (device globals; no allocation) ----------------
__device__ float g_h[Bn*Ldim*Dn];
__device__ float g_hlocal[Bn*Ldim*Dn];
__device__ float g_sess[Bn*Dn];
__device__ float g_nb[Bn*Ldim*Dn];
__device__ float g_hcomb[Bn*Ldim*Dn];
__device__ float g_seq[Bn*Ldim*Dn];
__device__ float g_nh[Bn*Ldim*Dn];
__device__ float g_hsg[Bn*Dn];
__device__ float g_select[Bn*Dn];
__device__ float g_rmax[Bn];
__device__ float g_rsuminv[Bn];

// ---------------- K1: gather h, local graph attention, h_local ----------------
__global__ __launch_bounds__(256) void k_local(
    const int* __restrict__ items, const int* __restrict__ adj,
    const float* __restrict__ emb,
    const float* __restrict__ a0, const float* __restrict__ a1,
    const float* __restrict__ a2, const float* __restrict__ a3)
{
    int b = blockIdx.x;
    __shared__ float hs[Ldim][101];       // padded (odd stride -> conflict free)
    __shared__ float alpha[Ldim][Ldim+1];
    __shared__ float As[Dn][4];
    int tid = threadIdx.x;

    for (int i = tid; i < Dn; i += 256) {
        As[i][0] = a0[i]; As[i][1] = a1[i]; As[i][2] = a2[i]; As[i][3] = a3[i];
    }
    for (int idx = tid; idx < Ldim*Dn; idx += 256) {
        int l = idx / Dn, d = idx % Dn;
        float v = emb[(size_t)items[b*Ldim + l]*Dn + d];
        hs[l][d] = v;
        g_h[((size_t)b*Ldim + l)*Dn + d] = v;
    }
    __syncthreads();

    // raw alpha: only the adj-selected head needs computing
    for (int p = tid; p < Ldim*Ldim; p += 256) {
        int i = p / Ldim, j = p % Ldim;
        int a = adj[((size_t)b*Ldim + i)*Ldim + j];
        float val = NEGV;
        if (a >= 1 && a <= 4) {
            float acc = 0.f;
            int k = a - 1;
            for (int d = 0; d < Dn; d++)
                acc += hs[i][d] * hs[j][d] * As[d][k];
            val = acc > 0.f ? acc : 0.2f * acc;
        }
        alpha[i][j] = val;
    }
    __syncthreads();

    // row softmax: 8 warps x 8 rows, 2 elems/lane
    int warp = tid >> 5, lane = tid & 31;
    for (int i = warp; i < Ldim; i += 8) {
        float x0 = alpha[i][lane], x1 = alpha[i][lane+32];
        float m = fmaxf(x0, x1);
        #pragma unroll
        for (int o = 16; o > 0; o >>= 1) m = fmaxf(m, __shfl_xor_sync(0xffffffffu, m, o));
        float e0 = __expf(fmaxf(x0 - m, -87.f));
        float e1 = __expf(fmaxf(x1 - m, -87.f));
        float s = e0 + e1;
        #pragma unroll
        for (int o = 16; o > 0; o >>= 1) s += __shfl_xor_sync(0xffffffffu, s, o);
        float inv = 1.f / s;
        alpha[i][lane] = e0 * inv;
        alpha[i][lane+32] = e1 * inv;
    }
    __syncthreads();

    // h_local = alpha @ h
    for (int idx = tid; idx < Ldim*Dn; idx += 256) {
        int i = idx / Dn, d = idx % Dn;
        float acc = 0.f;
        for (int j = 0; j < Ldim; j++) acc += alpha[i][j] * hs[j][d];
        g_hlocal[((size_t)b*Ldim + i)*Dn + d] = acc;
    }
}

// ---------------- K2: sess mean ----------------
__global__ __launch_bounds__(128) void k_sess(
    const int* __restrict__ seq_features, const float* __restrict__ mask,
    const float* __restrict__ emb)
{
    int b = blockIdx.x, tid = threadIdx.x;
    if (tid >= Dn) return;
    float acc = 0.f, msum = 0.f;
    for (int l = 0; l < Ldim; l++) {
        float mk = mask[b*Ldim + l];
        acc += emb[(size_t)seq_features[b*Ldim + l]*Dn + tid] * mk;
        msum += mk;
    }
    g_sess[b*Dn + tid] = acc / msum;
}

// ---------------- K3: global neighbor aggregation (dominant kernel) ----------------
__global__ __launch_bounds__(256) void k_global(
    const int* __restrict__ items, const int* __restrict__ adj_all,
    const float* __restrict__ num_w, const float* __restrict__ emb,
    const float* __restrict__ g_w1, const float* __restrict__ g_w2)
{
    int blk = blockIdx.x;              // 1024 blocks: 4 per batch row
    int b = blk >> 2;
    int l0 = (blk & 3) * 16;
    __shared__ float w1s[101*100];
    __shared__ float w2s[Dn];
    __shared__ float sesss[Dn];
    __shared__ float feat[Sn][104];    // [s][0..99]=sess*nv, [s][100]=num_w
    __shared__ int   nbrs[Sn];
    __shared__ float alsc[Sn];
    __shared__ float red[256];
    int tid = threadIdx.x;

    for (int i = tid; i < 101*100; i += 256) w1s[i] = g_w1[i];
    if (tid < Dn) { w2s[tid] = g_w2[tid]; sesss[tid] = g_sess[b*Dn + tid]; }
    __syncthreads();

    for (int l = l0; l < l0 + 16; l++) {
        int node = items[b*Ldim + l];
        if (tid < Sn) {
            nbrs[tid] = adj_all[(size_t)node*Sn + tid];
            feat[tid][100] = num_w[(size_t)node*Sn + tid];
        }
        __syncthreads();
        for (int idx = tid; idx < Sn*Dn; idx += 256) {
            int s = idx / Dn, c = idx % Dn;
            feat[s][c] = sesss[c] * emb[(size_t)nbrs[s]*Dn + c];
        }
        __syncthreads();

        float acc = 0.f;
        if (tid < 240) {                // thread -> (s, 5 d-columns)
            int s = tid / 20, dg = tid % 20;
            float al[5] = {0,0,0,0,0};
            const float* gw = w1s + dg*5;
            for (int c = 0; c <= 100; c++) {
                float f = feat[s][c];
                const float* gr = gw + c*100;
                #pragma unroll
                for (int i = 0; i < 5; i++) al[i] += f * gr[i];
            }
            #pragma unroll
            for (int i = 0; i < 5; i++) {
                float v = al[i];
                v = v > 0.f ? v : 0.2f * v;
                acc += v * w2s[dg*5 + i];
            }
        }
        red[tid] = acc;
        __syncthreads();
        if (tid < Sn) {
            float s_ = 0.f;
            #pragma unroll
            for (int k = 0; k < 20; k++) s_ += red[tid*20 + k];
            alsc[tid] = s_;
        }
        __syncthreads();
        if (tid == 0) {                 // softmax over 12
            float m = alsc[0];
            #pragma unroll
            for (int s = 1; s < Sn; s++) m = fmaxf(m, alsc[s]);
            float e[Sn]; float ssum = 0.f;
            #pragma unroll
            for (int s = 0; s < Sn; s++) { e[s] = __expf(alsc[s] - m); ssum += e[s]; }
            float inv = 1.f / ssum;
            #pragma unroll
            for (int s = 0; s < Sn; s++) alsc[s] = e[s] * inv;
        }
        __syncthreads();
        if (tid < Dn) {                 // nb = sum_s alpha_s * nv_s (re-gather, L2 hits)
            float a = 0.f;
            #pragma unroll
            for (int s = 0; s < Sn; s++) a += alsc[s] * emb[(size_t)nbrs[s]*Dn + tid];
            g_nb[((size_t)b*Ldim + l)*Dn + tid] = a;
        }
        __syncthreads();
    }
}

// ---------------- K4: h_combine = relu([h,nb]@g_w3) + h_local ----------------
__global__ __launch_bounds__(256) void k_combine(const float* __restrict__ g_w3)
{
    int row0 = blockIdx.x * 32;
    __shared__ float ins[32][200];
    int tid = threadIdx.x;
    for (int idx = tid; idx < 32*200; idx += 256) {
        int r = idx / 200, k = idx % 200;
        size_t row = row0 + r;
        ins[r][k] = (k < 100) ? g_h[row*Dn + k] : g_nb[row*Dn + (k-100)];
    }
    __syncthreads();
    int lane = tid & 31, ty = tid >> 5;
    int r0 = ty * 4;
    float acc[4][4] = {};
    for (int k = 0; k < 200; k++) {
        float a0 = ins[r0][k], a1 = ins[r0+1][k], a2 = ins[r0+2][k], a3 = ins[r0+3][k];
        float w0 = __ldg(&g_w3[k*100 + lane]);
        float w1 = __ldg(&g_w3[k*100 + lane + 32]);
        float w2 = __ldg(&g_w3[k*100 + lane + 64]);
        float w3 = (lane < 4) ? __ldg(&g_w3[k*100 + lane + 96]) : 0.f;
        acc[0][0] += a0*w0; acc[0][1] += a0*w1; acc[0][2] += a0*w2; acc[0][3] += a0*w3;
        acc[1][0] += a1*w0; acc[1][1] += a1*w1; acc[1][2] += a1*w2; acc[1][3] += a1*w3;
        acc[2][0] += a2*w0; acc[2][1] += a2*w1; acc[2][2] += a2*w2; acc[2][3] += a2*w3;
        acc[3][0] += a3*w0; acc[3][1] += a3*w1; acc[3][2] += a3*w2; acc[3][3] += a3*w3;
    }
    #pragma unroll
    for (int i = 0; i < 4; i++) {
        size_t row = row0 + r0 + i;
        #pragma unroll
        for (int q = 0; q < 4; q++) {
            int c = lane + 32*q;
            if (c < 100)
                g_hcomb[row*Dn + c] = g_hlocal[row*Dn + c] + fmaxf(acc[i][q], 0.f);
        }
    }
}

// ---------------- K5a: seq_hidden gather, hs, hsg = hs@glu2_w + glu2_b ----------------
__global__ __launch_bounds__(128) void k_seqhs(
    const int* __restrict__ alias, const float* __restrict__ mask,
    const float* __restrict__ glu2_w, const float* __restrict__ glu2_b)
{
    int b = blockIdx.x, tid = threadIdx.x;
    __shared__ float hs_s[Dn];
    __shared__ int alias_s[Ldim];
    __shared__ float mk_s[Ldim];
    if (tid < Ldim) { alias_s[tid] = alias[b*Ldim + tid]; mk_s[tid] = mask[b*Ldim + tid]; }
    __syncthreads();
    if (tid < Dn) {
        float acc = 0.f, msum = 0.f;
        for (int l = 0; l < Ldim; l++) {
            float v = g_hcomb[((size_t)b*Ldim + alias_s[l])*Dn + tid];
            g_seq[((size_t)b*Ldim + l)*Dn + tid] = v;
            acc += v * mk_s[l];
            msum += mk_s[l];
        }
        hs_s[tid] = acc / msum;
    }
    __syncthreads();
    if (tid < Dn) {
        float t = glu2_b[tid];
        for (int c = 0; c < Dn; c++) t += hs_s[c] * __ldg(&glu2_w[c*Dn + tid]);
        g_hsg[b*Dn + tid] = t;
    }
}

// ---------------- K5b: nh = tanh([pe, seq]@w_1) ----------------
__global__ __launch_bounds__(256) void k_nh(
    const float* __restrict__ pos_emb, const float* __restrict__ w_1)
{
    int row0 = blockIdx.x * 32;
    __shared__ float ins[32][200];
    int tid = threadIdx.x;
    for (int idx = tid; idx < 32*200; idx += 256) {
        int r = idx / 200, k = idx % 200;
        size_t row = row0 + r;
        int l = (int)(row % Ldim);
        ins[r][k] = (k < 100) ? pos_emb[l*Dn + k] : g_seq[row*Dn + (k-100)];
    }
    __syncthreads();
    int lane = tid & 31, ty = tid >> 5;
    int r0 = ty * 4;
    float acc[4][4] = {};
    for (int k = 0; k < 200; k++) {
        float a0 = ins[r0][k], a1 = ins[r0+1][k], a2 = ins[r0+2][k], a3 = ins[r0+3][k];
        float w0 = __ldg(&w_1[k*100 + lane]);
        float w1 = __ldg(&w_1[k*100 + lane + 32]);
        float w2 = __ldg(&w_1[k*100 + lane + 64]);
        float w3 = (lane < 4) ? __ldg(&w_1[k*100 + lane + 96]) : 0.f;
        acc[0][0] += a0*w0; acc[0][1] += a0*w1; acc[0][2] += a0*w2; acc[0][3] += a0*w3;
        acc[1][0] += a1*w0; acc[1][1] += a1*w1; acc[1][2] += a1*w2; acc[1][3] += a1*w3;
        acc[2][0] += a2*w0; acc[2][1] += a2*w1; acc[2][2] += a2*w2; acc[2][3] += a2*w3;
        acc[3][0] += a3*w0; acc[3][1] += a3*w1; acc[3][2] += a3*w2; acc[3][3] += a3*w3;
    }
    #pragma unroll
    for (int i = 0; i < 4; i++) {
        size_t row = row0 + r0 + i;
        #pragma unroll
        for (int q = 0; q < 4; q++) {
            int c = lane + 32*q;
            if (c < 100) g_nh[row*Dn + c] = tanhf(acc[i][q]);
        }
    }
}

// ---------------- K5c: GLU sigmoid, beta, select ----------------
__global__ __launch_bounds__(128) void k_select(
    const float* __restrict__ glu1_w, const float* __restrict__ glu1_b,
    const float* __restrict__ w_2, const float* __restrict__ mask)
{
    int b = blockIdx.x, tid = threadIdx.x;
    __shared__ float w1s[100*100];
    __shared__ float nh_s[Dn], seq_s[Dn], red[128];
    __shared__ float w2s[Dn], hb_s[Dn];
    for (int i = tid; i < 100*100; i += 128) w1s[i] = glu1_w[i];
    if (tid < Dn) { w2s[tid] = w_2[tid]; hb_s[tid] = glu1_b[tid] + g_hsg[b*Dn + tid]; }
    __syncthreads();
    float sel = 0.f;
    for (int l = 0; l < Ldim; l++) {
        if (tid < Dn) {
            nh_s[tid]  = g_nh[((size_t)b*Ldim + l)*Dn + tid];
            seq_s[tid] = g_seq[((size_t)b*Ldim + l)*Dn + tid];
        }
        __syncthreads();
        float contrib = 0.f;
        if (tid < Dn) {
            float t = hb_s[tid];
            for (int c = 0; c < Dn; c++) t += nh_s[c] * w1s[c*100 + tid];
            float sg = 1.f / (1.f + __expf(-t));
            contrib = sg * w2s[tid];
        }
        red[tid] = contrib;
        __syncthreads();
        for (int st = 64; st > 0; st >>= 1) {
            if (tid < st) red[tid] += red[tid + st];
            __syncthreads();
        }
        float beta = red[0] * mask[b*Ldim + l];
        if (tid < Dn) sel += beta * seq_s[tid];
        __syncthreads();
    }
    if (tid < Dn) g_select[b*Dn + tid] = sel;
}

// ---------------- K6a: score = select @ emb[1:]^T ----------------
__global__ __launch_bounds__(256) void k_score(
    const float* __restrict__ emb, float* __restrict__ out)
{
    int n0 = blockIdx.x * 64, b0 = blockIdx.y * 32;
    __shared__ float sel_s[32][101];
    __shared__ float emb_s[64][101];
    int tid = threadIdx.x;
    for (int idx = tid; idx < 32*100; idx += 256) {
        int r = idx / 100, c = idx % 100;
        sel_s[r][c] = __ldg(&g_select[(b0 + r)*Dn + c]);
    }
    for (int idx = tid; idx < 64*100; idx += 256) {
        int r = idx / 100, c = idx % 100;
        int n = n0 + r;
        emb_s[r][c] = (n < NOUT) ? emb[(size_t)(n + 1)*Dn + c] : 0.f;
    }
    __syncthreads();
    int lane = tid & 31, ty = tid >> 5;
    int rb = ty * 4;
    float acc[4][2] = {};
    for (int k = 0; k < 100; k++) {
        float e0 = emb_s[lane][k], e1 = emb_s[lane + 32][k];
        float s0 = sel_s[rb][k], s1 = sel_s[rb+1][k], s2 = sel_s[rb+2][k], s3 = sel_s[rb+3][k];
        acc[0][0] += s0*e0; acc[0][1] += s0*e1;
        acc[1][0] += s1*e0; acc[1][1] += s1*e1;
        acc[2][0] += s2*e0; acc[2][1] += s2*e1;
        acc[3][0] += s3*e0; acc[3][1] += s3*e1;
    }
    #pragma unroll
    for (int i = 0; i < 4; i++) {
        #pragma unroll
        for (int q = 0; q < 2; q++) {
            int n = n0 + lane + 32*q;
            if (n < NOUT)
                out[(size_t)(b0 + rb + i)*NOUT + n] = acc[i][q];
        }
    }
}

// ---------------- K6b: per-row online max/sum ----------------
__global__ __launch_bounds__(256) void k_rowstat(const float* __restrict__ out)
{
    int b = blockIdx.x, tid = threadIdx.x;
    float m = -3.0e38f, s = 0.f;
    for (int n = tid; n < NOUT; n += 256) {
        float x = out[(size_t)b*NOUT + n];
        if (x > m) { s = s * __expf(m - x) + 1.f; m = x; }
        else       { s += __expf(x - m); }
    }
    __shared__ float ms[256], ss[256];
    ms[tid] = m; ss[tid] = s;
    __syncthreads();
    for (int st = 128; st > 0; st >>= 1) {
        if (tid < st) {
            float mo = ms[tid], so = ss[tid];
            float m2 = ms[tid + st], s2 = ss[tid + st];
            float mn = fmaxf(mo, m2);
            ms[tid] = mn;
            ss[tid] = so * __expf(mo - mn) + s2 * __expf(m2 - mn);
        }
        __syncthreads();
    }
    if (tid == 0) { g_rmax[b] = ms[0]; g_rsuminv[b] = 1.f / ss[0]; }
}

// ---------------- K6c: normalize ----------------
__global__ __launch_bounds__(256) void k_norm(float* __restrict__ out)
{
    int b = blockIdx.y;
    int n = blockIdx.x * 256 + threadIdx.x;
    if (n < NOUT) {
        size_t idx = (size_t)b*NOUT + n;
        out[idx] = __expf(out[idx] - g_rmax[b]) * g_rsuminv[b];
    }
}

// ---------------- launch ----------------
extern "C" void kernel_launch(void* const* d_in, const int* in_sizes, int n_in,
                              void* d_out, int out_size)
{
    const int*   alias_inputs = (const int*)  d_in[0];
    const int*   items        = (const int*)  d_in[1];
    const int*   adj          = (const int*)  d_in[2];
    const float* mask_item    = (const float*)d_in[3];
    const int*   seq_features = (const int*)  d_in[4];
    const int*   adj_all      = (const int*)  d_in[5];
    const float* num_w        = (const float*)d_in[6];
    const float* emb          = (const float*)d_in[7];
    const float* pos_emb      = (const float*)d_in[8];
    const float* a0           = (const float*)d_in[9];
    const float* a1           = (const float*)d_in[10];
    const float* a2           = (const float*)d_in[11];
    const float* a3           = (const float*)d_in[12];
    const float* g_w1         = (const float*)d_in[13];
    const float* g_w2         = (const float*)d_in[14];
    const float* g_w3         = (const float*)d_in[15];
    const float* w_1          = (const float*)d_in[16];
    const float* w_2          = (const float*)d_in[17];
    const float* glu1_w       = (const float*)d_in[18];
    const float* glu1_b       = (const float*)d_in[19];
    const float* glu2_w       = (const float*)d_in[20];
    const float* glu2_b       = (const float*)d_in[21];
    float* out = (float*)d_out;

    k_local  <<<Bn, 256>>>(items, adj, emb, a0, a1, a2, a3);
    k_sess   <<<Bn, 128>>>(seq_features, mask_item, emb);
    k_global <<<Bn*4, 256>>>(items, adj_all, num_w, emb, g_w1, g_w2);
    k_combine<<<(Bn*Ldim)/32, 256>>>(g_w3);
    k_seqhs  <<<Bn, 128>>>(alias_inputs, mask_item, glu2_w, glu2_b);
    k_nh     <<<(Bn*Ldim)/32, 256>>>(pos_emb, w_1);
    k_select <<<Bn, 128>>>(glu1_w, glu1_b, w_2, mask_item);
    dim3 gs((NOUT + 63)/64, Bn/32);
    k_score  <<<gs, 256>>>(emb, out);
    k_rowstat<<<Bn, 256>>>(out);
    dim3 gn((NOUT + 255)/256, Bn);
    k_norm   <<<gn, 256>>>(out);
}

// round 3
// speedup vs baseline: 1.1263x; 1.1263x over previous
#include <cuda_runtime.h>
#include <math.h>

#define Bn 256
#define Ldim 64
#define Sn 12
#define Dn 100
#define NUM_NODE 43098
#define NOUT 43097
#define NEGV -9000000000000000.0f
#define NCHUNK 8
#define CHUNKSZ 5388   // ceil(43097/8)

// ---------------- scratch (device globals; no allocation) ----------------
__device__ float g_h[Bn*Ldim*Dn];
__device__ float g_hlocal[Bn*Ldim*Dn];
__device__ float g_sess[Bn*Dn];
__device__ float g_nb[Bn*Ldim*Dn];
__device__ float g_hcomb[Bn*Ldim*Dn];
__device__ float g_seq[Bn*Ldim*Dn];
__device__ float g_nh[Bn*Ldim*Dn];
__device__ float g_hsg[Bn*Dn];
__device__ float g_select[Bn*Dn];
__device__ unsigned g_rmaxbits[Bn];
__device__ float g_rpart[Bn*NCHUNK];

// monotonic float->uint key for atomicMax over signed floats
__device__ __forceinline__ unsigned fkey(float f) {
    unsigned u = __float_as_uint(f);
    return (u & 0x80000000u) ? ~u : (u | 0x80000000u);
}
__device__ __forceinline__ float funkey(unsigned k) {
    return (k & 0x80000000u) ? __uint_as_float(k ^ 0x80000000u)
                             : __uint_as_float(~k);
}

// fast exp via FMA-pipe polynomial (x <= 0 expected; clamped below -126*ln2)
__device__ __forceinline__ float fexp(float x) {
    float y = x * 1.44269504088896340736f;
    y = fmaxf(y, -126.0f);
    float t = y + 12582912.0f;          // round to nearest int
    float i = t - 12582912.0f;
    float f = y - i;
    int ii = (int)i;
    float p = 1.54035303933816e-4f;
    p = fmaf(p, f, 1.33335581464284e-3f);
    p = fmaf(p, f, 9.61812910762848e-3f);
    p = fmaf(p, f, 5.55041086648216e-2f);
    p = fmaf(p, f, 2.40226506959101e-1f);
    p = fmaf(p, f, 6.93147180559945e-1f);
    p = fmaf(p, f, 1.0f);
    return p * __int_as_float((ii + 127) << 23);
}

// ---------------- K0: zero per-row stats ----------------
__global__ void k_init() {
    int t = threadIdx.x;
    if (t < Bn) g_rmaxbits[t] = 0u;
}

// ---------------- K1: gather h, local graph attention, h_local ----------------
__global__ __launch_bounds__(256) void k_local(
    const int* __restrict__ items, const int* __restrict__ adj,
    const float* __restrict__ emb,
    const float* __restrict__ a0, const float* __restrict__ a1,
    const float* __restrict__ a2, const float* __restrict__ a3)
{
    int b = blockIdx.x;
    __shared__ float hs[Ldim][101];
    __shared__ float alpha[Ldim][Ldim+1];
    __shared__ float As[Dn][4];
    int tid = threadIdx.x;

    for (int i = tid; i < Dn; i += 256) {
        As[i][0] = a0[i]; As[i][1] = a1[i]; As[i][2] = a2[i]; As[i][3] = a3[i];
    }
    for (int idx = tid; idx < Ldim*Dn; idx += 256) {
        int l = idx / Dn, d = idx % Dn;
        float v = emb[(size_t)items[b*Ldim + l]*Dn + d];
        hs[l][d] = v;
        g_h[((size_t)b*Ldim + l)*Dn + d] = v;
    }
    __syncthreads();

    for (int p = tid; p < Ldim*Ldim; p += 256) {
        int i = p / Ldim, j = p % Ldim;
        int a = adj[((size_t)b*Ldim + i)*Ldim + j];
        float val = NEGV;
        if (a >= 1 && a <= 4) {
            float acc = 0.f;
            int k = a - 1;
            for (int d = 0; d < Dn; d++)
                acc += hs[i][d] * hs[j][d] * As[d][k];
            val = acc > 0.f ? acc : 0.2f * acc;
        }
        alpha[i][j] = val;
    }
    __syncthreads();

    int warp = tid >> 5, lane = tid & 31;
    for (int i = warp; i < Ldim; i += 8) {
        float x0 = alpha[i][lane], x1 = alpha[i][lane+32];
        float m = fmaxf(x0, x1);
        #pragma unroll
        for (int o = 16; o > 0; o >>= 1) m = fmaxf(m, __shfl_xor_sync(0xffffffffu, m, o));
        float e0 = __expf(fmaxf(x0 - m, -87.f));
        float e1 = __expf(fmaxf(x1 - m, -87.f));
        float s = e0 + e1;
        #pragma unroll
        for (int o = 16; o > 0; o >>= 1) s += __shfl_xor_sync(0xffffffffu, s, o);
        float inv = 1.f / s;
        alpha[i][lane] = e0 * inv;
        alpha[i][lane+32] = e1 * inv;
    }
    __syncthreads();

    for (int idx = tid; idx < Ldim*Dn; idx += 256) {
        int i = idx / Dn, d = idx % Dn;
        float acc = 0.f;
        for (int j = 0; j < Ldim; j++) acc += alpha[i][j] * hs[j][d];
        g_hlocal[((size_t)b*Ldim + i)*Dn + d] = acc;
    }
}

// ---------------- K2: sess mean ----------------
__global__ __launch_bounds__(128) void k_sess(
    const int* __restrict__ seq_features, const float* __restrict__ mask,
    const float* __restrict__ emb)
{
    int b = blockIdx.x, tid = threadIdx.x;
    if (tid >= Dn) return;
    float acc = 0.f, msum = 0.f;
    for (int l = 0; l < Ldim; l++) {
        float mk = mask[b*Ldim + l];
        acc += emb[(size_t)seq_features[b*Ldim + l]*Dn + tid] * mk;
        msum += mk;
    }
    g_sess[b*Dn + tid] = acc / msum;
}

// ---------------- K3: global neighbor aggregation ----------------
// dyn smem: w1s[10100] w2s[100] sess[100] feat[48*105] alsc[48] red[960] nbrs[48]
#define G_W1S 0
#define G_W2S 10100
#define G_SESS 10200
#define G_FEAT 10300
#define G_ALSC 15340
#define G_RED  15388
#define G_NBR  16348
#define G_SMEM_FLOATS 16396
__global__ __launch_bounds__(256) void k_global(
    const int* __restrict__ items, const int* __restrict__ adj_all,
    const float* __restrict__ num_w, const float* __restrict__ emb,
    const float* __restrict__ g_w1, const float* __restrict__ g_w2)
{
    extern __shared__ float sm[];
    float* w1s   = sm + G_W1S;
    float* w2s   = sm + G_W2S;
    float* sesss = sm + G_SESS;
    float* feat  = sm + G_FEAT;   // 48 rows x 105 stride, cols 0..100 used
    float* alsc  = sm + G_ALSC;
    float* red   = sm + G_RED;    // [48][20]
    int*   nbrs  = (int*)(sm + G_NBR);

    int blk = blockIdx.x;
    int b = blk >> 2;
    int l0 = (blk & 3) * 16;
    int tid = threadIdx.x;

    for (int i = tid; i < 101*100; i += 256) w1s[i] = g_w1[i];
    if (tid < Dn) { w2s[tid] = g_w2[tid]; sesss[tid] = g_sess[b*Dn + tid]; }
    __syncthreads();

    for (int lquad = 0; lquad < 4; lquad++) {
        int lbase = l0 + lquad*4;
        // neighbor ids + num_w for 4 l x 12 s
        if (tid < 48) {
            int lsl = tid / 12, s = tid % 12;
            int node = items[b*Ldim + lbase + lsl];
            nbrs[tid] = adj_all[(size_t)node*Sn + s];
            feat[tid*105 + 100] = num_w[(size_t)node*Sn + s];
        }
        __syncthreads();
        for (int idx = tid; idx < 48*100; idx += 256) {
            int row = idx / 100, c = idx % 100;
            feat[row*105 + c] = sesss[c] * emb[(size_t)nbrs[row]*Dn + c];
        }
        __syncthreads();

        // GEMM: 240 threads = 4 l x (3 s-groups of 4) x (20 col-groups of 5)
        if (tid < 240) {
            int lsl = tid / 60;
            int rr = tid % 60;
            int sg = rr / 20, cg = rr % 20;
            float al[4][5];
            #pragma unroll
            for (int t = 0; t < 4; t++)
                #pragma unroll
                for (int j = 0; j < 5; j++) al[t][j] = 0.f;
            const float* wbase = w1s + cg*5;
            for (int c = 0; c <= 100; c++) {
                float w[5];
                #pragma unroll
                for (int j = 0; j < 5; j++) w[j] = wbase[c*100 + j];
                #pragma unroll
                for (int t = 0; t < 4; t++) {
                    float f = feat[(lsl*12 + sg*4 + t)*105 + c];
                    #pragma unroll
                    for (int j = 0; j < 5; j++) al[t][j] = fmaf(f, w[j], al[t][j]);
                }
            }
            #pragma unroll
            for (int t = 0; t < 4; t++) {
                float pt = 0.f;
                #pragma unroll
                for (int j = 0; j < 5; j++) {
                    float v = al[t][j];
                    v = v > 0.f ? v : 0.2f * v;
                    pt = fmaf(v, w2s[cg*5 + j], pt);
                }
                red[(lsl*12 + sg*4 + t)*20 + cg] = pt;
            }
        }
        __syncthreads();
        if (tid < 48) {
            float s_ = 0.f;
            #pragma unroll
            for (int k = 0; k < 20; k++) s_ += red[tid*20 + k];
            alsc[tid] = s_;
        }
        __syncthreads();
        if (tid < 4) {
            float* a = alsc + tid*12;
            float m = a[0];
            #pragma unroll
            for (int s = 1; s < Sn; s++) m = fmaxf(m, a[s]);
            float ssum = 0.f;
            float e[Sn];
            #pragma unroll
            for (int s = 0; s < Sn; s++) { e[s] = __expf(a[s] - m); ssum += e[s]; }
            float inv = 1.f / ssum;
            #pragma unroll
            for (int s = 0; s < Sn; s++) a[s] = e[s] * inv;
        }
        __syncthreads();
        for (int idx = tid; idx < 400; idx += 256) {
            int lsl = idx / 100, c = idx % 100;
            float acc = 0.f;
            #pragma unroll
            for (int s = 0; s < Sn; s++)
                acc = fmaf(alsc[lsl*12 + s], emb[(size_t)nbrs[lsl*12 + s]*Dn + c], acc);
            g_nb[((size_t)b*Ldim + lbase + lsl)*Dn + c] = acc;
        }
        __syncthreads();
    }
}

// ---------------- K4: h_combine = relu([h,nb]@g_w3) + h_local ----------------
// dyn smem: w[200*100] + ins[32*200]
__global__ __launch_bounds__(256) void k_combine(const float* __restrict__ g_w3)
{
    extern __shared__ float sm[];
    float* w_s = sm;            // 20000
    float* ins = sm + 20000;    // 32 x 200
    int tid = threadIdx.x;
    int row0 = blockIdx.x * 32;
    for (int i = tid; i < 200*100; i += 256) w_s[i] = g_w3[i];
    for (int idx = tid; idx < 32*200; idx += 256) {
        int r = idx / 200, k = idx % 200;
        size_t row = row0 + r;
        ins[r*200 + k] = (k < 100) ? g_h[row*Dn + k] : g_nb[row*Dn + (k-100)];
    }
    __syncthreads();
    int lane = tid & 31, ty = tid >> 5;
    int r0 = ty * 4;
    float acc[4][4] = {};
    for (int k = 0; k < 200; k++) {
        float w0 = w_s[k*100 + lane];
        float w1 = w_s[k*100 + lane + 32];
        float w2 = w_s[k*100 + lane + 64];
        float w3 = (lane < 4) ? w_s[k*100 + lane + 96] : 0.f;
        #pragma unroll
        for (int i = 0; i < 4; i++) {
            float a = ins[(r0+i)*200 + k];
            acc[i][0] = fmaf(a, w0, acc[i][0]);
            acc[i][1] = fmaf(a, w1, acc[i][1]);
            acc[i][2] = fmaf(a, w2, acc[i][2]);
            acc[i][3] = fmaf(a, w3, acc[i][3]);
        }
    }
    #pragma unroll
    for (int i = 0; i < 4; i++) {
        size_t row = row0 + r0 + i;
        #pragma unroll
        for (int q = 0; q < 4; q++) {
            int c = lane + 32*q;
            if (c < 100)
                g_hcomb[row*Dn + c] = g_hlocal[row*Dn + c] + fmaxf(acc[i][q], 0.f);
        }
    }
}

// ---------------- K5a: seq gather, hs, hsg ----------------
__global__ __launch_bounds__(128) void k_seqhs(
    const int* __restrict__ alias, const float* __restrict__ mask,
    const float* __restrict__ glu2_w, const float* __restrict__ glu2_b)
{
    int b = blockIdx.x, tid = threadIdx.x;
    __shared__ float hs_s[Dn];
    __shared__ int alias_s[Ldim];
    __shared__ float mk_s[Ldim];
    if (tid < Ldim) { alias_s[tid] = alias[b*Ldim + tid]; mk_s[tid] = mask[b*Ldim + tid]; }
    __syncthreads();
    if (tid < Dn) {
        float acc = 0.f, msum = 0.f;
        for (int l = 0; l < Ldim; l++) {
            float v = g_hcomb[((size_t)b*Ldim + alias_s[l])*Dn + tid];
            g_seq[((size_t)b*Ldim + l)*Dn + tid] = v;
            acc += v * mk_s[l];
            msum += mk_s[l];
        }
        hs_s[tid] = acc / msum;
    }
    __syncthreads();
    if (tid < Dn) {
        float t = glu2_b[tid];
        for (int c = 0; c < Dn; c++) t = fmaf(hs_s[c], __ldg(&glu2_w[c*Dn + tid]), t);
        g_hsg[b*Dn + tid] = t;
    }
}

// ---------------- K5b: nh = tanh([pe, seq]@w_1) ----------------
__global__ __launch_bounds__(256) void k_nh(
    const float* __restrict__ pos_emb, const float* __restrict__ w_1)
{
    extern __shared__ float sm[];
    float* w_s = sm;            // 20000
    float* ins = sm + 20000;    // 32 x 200
    int tid = threadIdx.x;
    int row0 = blockIdx.x * 32;
    for (int i = tid; i < 200*100; i += 256) w_s[i] = w_1[i];
    for (int idx = tid; idx < 32*200; idx += 256) {
        int r = idx / 200, k = idx % 200;
        size_t row = row0 + r;
        int l = (int)(row % Ldim);
        ins[r*200 + k] = (k < 100) ? pos_emb[l*Dn + k] : g_seq[row*Dn + (k-100)];
    }
    __syncthreads();
    int lane = tid & 31, ty = tid >> 5;
    int r0 = ty * 4;
    float acc[4][4] = {};
    for (int k = 0; k < 200; k++) {
        float w0 = w_s[k*100 + lane];
        float w1 = w_s[k*100 + lane + 32];
        float w2 = w_s[k*100 + lane + 64];
        float w3 = (lane < 4) ? w_s[k*100 + lane + 96] : 0.f;
        #pragma unroll
        for (int i = 0; i < 4; i++) {
            float a = ins[(r0+i)*200 + k];
            acc[i][0] = fmaf(a, w0, acc[i][0]);
            acc[i][1] = fmaf(a, w1, acc[i][1]);
            acc[i][2] = fmaf(a, w2, acc[i][2]);
            acc[i][3] = fmaf(a, w3, acc[i][3]);
        }
    }
    #pragma unroll
    for (int i = 0; i < 4; i++) {
        size_t row = row0 + r0 + i;
        #pragma unroll
        for (int q = 0; q < 4; q++) {
            int c = lane + 32*q;
            if (c < 100) g_nh[row*Dn + c] = tanhf(acc[i][q]);
        }
    }
}

// ---------------- K5c: GLU sigmoid, beta, select ----------------
__global__ __launch_bounds__(128) void k_select(
    const float* __restrict__ glu1_w, const float* __restrict__ glu1_b,
    const float* __restrict__ w_2, const float* __restrict__ mask)
{
    int b = blockIdx.x, tid = threadIdx.x;
    __shared__ float w1s[100*100];
    __shared__ float nh_s[Dn], seq_s[Dn], red[128];
    __shared__ float w2s[Dn], hb_s[Dn];
    for (int i = tid; i < 100*100; i += 128) w1s[i] = glu1_w[i];
    if (tid < Dn) { w2s[tid] = w_2[tid]; hb_s[tid] = glu1_b[tid] + g_hsg[b*Dn + tid]; }
    __syncthreads();
    float sel = 0.f;
    for (int l = 0; l < Ldim; l++) {
        if (tid < Dn) {
            nh_s[tid]  = g_nh[((size_t)b*Ldim + l)*Dn + tid];
            seq_s[tid] = g_seq[((size_t)b*Ldim + l)*Dn + tid];
        }
        __syncthreads();
        float contrib = 0.f;
        if (tid < Dn) {
            float t = hb_s[tid];
            for (int c = 0; c < Dn; c++) t = fmaf(nh_s[c], w1s[c*100 + tid], t);
            float sg = 1.f / (1.f + __expf(-t));
            contrib = sg * w2s[tid];
        }
        red[tid] = contrib;
        __syncthreads();
        for (int st = 64; st > 0; st >>= 1) {
            if (tid < st) red[tid] += red[tid + st];
            __syncthreads();
        }
        float beta = red[0] * mask[b*Ldim + l];
        if (tid < Dn) sel += beta * seq_s[tid];
        __syncthreads();
    }
    if (tid < Dn) g_select[b*Dn + tid] = sel;
}

// ---------------- K6a: score = select @ emb[1:]^T, + row-max atomics ----------
// dyn smem: sel[32*101] + emb[128*101]
__global__ __launch_bounds__(256) void k_score(
    const float* __restrict__ emb, float* __restrict__ out)
{
    extern __shared__ float sm[];
    float* sel_s = sm;            // 32 x 101
    float* emb_s = sm + 32*101;   // 128 x 101
    int n0 = blockIdx.x * 128, b0 = blockIdx.y * 32;
    int tid = threadIdx.x;
    for (int idx = tid; idx < 32*100; idx += 256) {
        int r = idx / 100, c = idx % 100;
        sel_s[r*101 + c] = g_select[(b0 + r)*Dn + c];
    }
    for (int idx = tid; idx < 128*100; idx += 256) {
        int r = idx / 100, c = idx % 100;
        int n = n0 + r;
        emb_s[r*101 + c] = (n < NOUT) ? emb[(size_t)(n + 1)*Dn + c] : 0.f;
    }
    __syncthreads();
    int lane = tid & 31, ty = tid >> 5;
    int rb = ty * 4;
    float acc[4][4] = {};
    for (int k = 0; k < 100; k++) {
        float e0 = emb_s[lane*101 + k];
        float e1 = emb_s[(lane+32)*101 + k];
        float e2 = emb_s[(lane+64)*101 + k];
        float e3 = emb_s[(lane+96)*101 + k];
        #pragma unroll
        for (int i = 0; i < 4; i++) {
            float s = sel_s[(rb+i)*101 + k];
            acc[i][0] = fmaf(s, e0, acc[i][0]);
            acc[i][1] = fmaf(s, e1, acc[i][1]);
            acc[i][2] = fmaf(s, e2, acc[i][2]);
            acc[i][3] = fmaf(s, e3, acc[i][3]);
        }
    }
    float rowmax[4] = {-3.0e38f, -3.0e38f, -3.0e38f, -3.0e38f};
    #pragma unroll
    for (int i = 0; i < 4; i++) {
        #pragma unroll
        for (int q = 0; q < 4; q++) {
            int n = n0 + lane + 32*q;
            if (n < NOUT) {
                out[(size_t)(b0 + rb + i)*NOUT + n] = acc[i][q];
                rowmax[i] = fmaxf(rowmax[i], acc[i][q]);
            }
        }
    }
    #pragma unroll
    for (int i = 0; i < 4; i++) {
        float m = rowmax[i];
        #pragma unroll
        for (int o = 16; o > 0; o >>= 1) m = fmaxf(m, __shfl_xor_sync(0xffffffffu, m, o));
        if (lane == 0) atomicMax(&g_rmaxbits[b0 + rb + i], fkey(m));
    }
}

// ---------------- K6b: per-chunk sum of exp (deterministic partials) --------
__global__ __launch_bounds__(256) void k_expsum(const float* __restrict__ out)
{
    int b = blockIdx.y, chunk = blockIdx.x, tid = threadIdx.x;
    int start = chunk * CHUNKSZ;
    int end = start + CHUNKSZ; if (end > NOUT) end = NOUT;
    float m = funkey(g_rmaxbits[b]);
    float s = 0.f;
    for (int n = start + tid; n < end; n += 256)
        s += fexp(out[(size_t)b*NOUT + n] - m);
    __shared__ float red[256];
    red[tid] = s;
    __syncthreads();
    for (int st = 128; st > 0; st >>= 1) {
        if (tid < st) red[tid] += red[tid + st];
        __syncthreads();
    }
    if (tid == 0) g_rpart[b*NCHUNK + chunk] = red[0];
}

// ---------------- K6c: exp + scale ----------------
__global__ __launch_bounds__(256) void k_scale(float* __restrict__ out)
{
    int b = blockIdx.y;
    int n = blockIdx.x * 256 + threadIdx.x;
    if (n < NOUT) {
        float ssum = 0.f;
        #pragma unroll
        for (int j = 0; j < NCHUNK; j++) ssum += g_rpart[b*NCHUNK + j];
        float m = funkey(g_rmaxbits[b]);
        float inv = __fdividef(1.f, ssum);
        size_t idx = (size_t)b*NOUT + n;
        out[idx] = fexp(out[idx] - m) * inv;
    }
}

// ---------------- launch ----------------
extern "C" void kernel_launch(void* const* d_in, const int* in_sizes, int n_in,
                              void* d_out, int out_size)
{
    const int*   alias_inputs = (const int*)  d_in[0];
    const int*   items        = (const int*)  d_in[1];
    const int*   adj          = (const int*)  d_in[2];
    const float* mask_item    = (const float*)d_in[3];
    const int*   seq_features = (const int*)  d_in[4];
    const int*   adj_all      = (const int*)  d_in[5];
    const float* num_w        = (const float*)d_in[6];
    const float* emb          = (const float*)d_in[7];
    const float* pos_emb      = (const float*)d_in[8];
    const float* a0           = (const float*)d_in[9];
    const float* a1           = (const float*)d_in[10];
    const float* a2           = (const float*)d_in[11];
    const float* a3           = (const float*)d_in[12];
    const float* g_w1         = (const float*)d_in[13];
    const float* g_w2         = (const float*)d_in[14];
    const float* g_w3         = (const float*)d_in[15];
    const float* w_1          = (const float*)d_in[16];
    const float* w_2          = (const float*)d_in[17];
    const float* glu1_w       = (const float*)d_in[18];
    const float* glu1_b       = (const float*)d_in[19];
    const float* glu2_w       = (const float*)d_in[20];
    const float* glu2_b       = (const float*)d_in[21];
    float* out = (float*)d_out;

    const int GSMEM = G_SMEM_FLOATS * 4;           // ~65.6 KB
    const int CSMEM = (20000 + 32*200) * 4;        // ~105.6 KB
    const int SSMEM = (32*101 + 128*101) * 4;      // ~64.6 KB
    cudaFuncSetAttribute(k_global,  cudaFuncAttributeMaxDynamicSharedMemorySize, GSMEM);
    cudaFuncSetAttribute(k_combine, cudaFuncAttributeMaxDynamicSharedMemorySize, CSMEM);
    cudaFuncSetAttribute(k_nh,      cudaFuncAttributeMaxDynamicSharedMemorySize, CSMEM);
    cudaFuncSetAttribute(k_score,   cudaFuncAttributeMaxDynamicSharedMemorySize, SSMEM);

    k_init   <<<1, 256>>>();
    k_local  <<<Bn, 256>>>(items, adj, emb, a0, a1, a2, a3);
    k_sess   <<<Bn, 128>>>(seq_features, mask_item, emb);
    k_global <<<Bn*4, 256, GSMEM>>>(items, adj_all, num_w, emb, g_w1, g_w2);
    k_combine<<<(Bn*Ldim)/32, 256, CSMEM>>>(g_w3);
    k_seqhs  <<<Bn, 128>>>(alias_inputs, mask_item, glu2_w, glu2_b);
    k_nh     <<<(Bn*Ldim)/32, 256, CSMEM>>>(pos_emb, w_1);
    k_select <<<Bn, 128>>>(glu1_w, glu1_b, w_2, mask_item);
    dim3 gs((NOUT + 127)/128, Bn/32);
    k_score  <<<gs, 256, SSMEM>>>(emb, out);
    dim3 ge(NCHUNK, Bn);
    k_expsum <<<ge, 256>>>(out);
    dim3 gn((NOUT + 255)/256, Bn);
    k_scale  <<<gn, 256>>>(out);
}

// round 4
// speedup vs baseline: 1.2554x; 1.1146x over previous
#include <cuda_runtime.h>
#include <math.h>

#define Bn 256
#define Ldim 64
#define Sn 12
#define Dn 100
#define NUM_NODE 43098
#define NOUT 43097
#define NEGV -9000000000000000.0f
#define NCHUNK 8
#define CHUNKSZ 5388   // ceil(43097/8)

// ---------------- scratch (device globals; no allocation) ----------------
__device__ float g_h[Bn*Ldim*Dn];
__device__ float g_hlocal[Bn*Ldim*Dn];
__device__ float g_sess[Bn*Dn];
__device__ float g_nb[Bn*Ldim*Dn];
__device__ float g_hcomb[Bn*Ldim*Dn];
__device__ float g_seq[Bn*Ldim*Dn];
__device__ float g_nh[Bn*Ldim*Dn];
__device__ float g_hsg[Bn*Dn];
__device__ float g_select[Bn*Dn];
__device__ unsigned g_rmaxbits[Bn];
__device__ float g_rpart[Bn*NCHUNK];

// monotonic float->uint key for atomicMax over signed floats
__device__ __forceinline__ unsigned fkey(float f) {
    unsigned u = __float_as_uint(f);
    return (u & 0x80000000u) ? ~u : (u | 0x80000000u);
}
__device__ __forceinline__ float funkey(unsigned k) {
    return (k & 0x80000000u) ? __uint_as_float(k ^ 0x80000000u)
                             : __uint_as_float(~k);
}

// fast exp via FMA-pipe polynomial (x <= 0 expected)
__device__ __forceinline__ float fexp(float x) {
    float y = x * 1.44269504088896340736f;
    y = fmaxf(y, -126.0f);
    float t = y + 12582912.0f;
    float i = t - 12582912.0f;
    float f = y - i;
    int ii = (int)i;
    float p = 1.54035303933816e-4f;
    p = fmaf(p, f, 1.33335581464284e-3f);
    p = fmaf(p, f, 9.61812910762848e-3f);
    p = fmaf(p, f, 5.55041086648216e-2f);
    p = fmaf(p, f, 2.40226506959101e-1f);
    p = fmaf(p, f, 6.93147180559945e-1f);
    p = fmaf(p, f, 1.0f);
    return p * __int_as_float((ii + 127) << 23);
}

// ---------------- K0: zero per-row stats ----------------
__global__ void k_init() {
    int t = threadIdx.x;
    if (t < Bn) g_rmaxbits[t] = 0u;
}

// ---------------- K1: gather h, local graph attention, h_local ----------------
__global__ __launch_bounds__(256) void k_local(
    const int* __restrict__ items, const int* __restrict__ adj,
    const float* __restrict__ emb,
    const float* __restrict__ a0, const float* __restrict__ a1,
    const float* __restrict__ a2, const float* __restrict__ a3)
{
    int b = blockIdx.x;
    __shared__ float hs[Ldim][101];
    __shared__ float alpha[Ldim][Ldim+1];
    __shared__ float As[Dn][4];
    int tid = threadIdx.x;

    for (int i = tid; i < Dn; i += 256) {
        As[i][0] = a0[i]; As[i][1] = a1[i]; As[i][2] = a2[i]; As[i][3] = a3[i];
    }
    for (int idx = tid; idx < Ldim*Dn; idx += 256) {
        int l = idx / Dn, d = idx % Dn;
        float v = emb[(size_t)items[b*Ldim + l]*Dn + d];
        hs[l][d] = v;
        g_h[((size_t)b*Ldim + l)*Dn + d] = v;
    }
    __syncthreads();

    for (int p = tid; p < Ldim*Ldim; p += 256) {
        int i = p / Ldim, j = p % Ldim;
        int a = adj[((size_t)b*Ldim + i)*Ldim + j];
        float val = NEGV;
        if (a >= 1 && a <= 4) {
            float acc = 0.f;
            int k = a - 1;
            for (int d = 0; d < Dn; d++)
                acc += hs[i][d] * hs[j][d] * As[d][k];
            val = acc > 0.f ? acc : 0.2f * acc;
        }
        alpha[i][j] = val;
    }
    __syncthreads();

    int warp = tid >> 5, lane = tid & 31;
    for (int i = warp; i < Ldim; i += 8) {
        float x0 = alpha[i][lane], x1 = alpha[i][lane+32];
        float m = fmaxf(x0, x1);
        #pragma unroll
        for (int o = 16; o > 0; o >>= 1) m = fmaxf(m, __shfl_xor_sync(0xffffffffu, m, o));
        float e0 = __expf(fmaxf(x0 - m, -87.f));
        float e1 = __expf(fmaxf(x1 - m, -87.f));
        float s = e0 + e1;
        #pragma unroll
        for (int o = 16; o > 0; o >>= 1) s += __shfl_xor_sync(0xffffffffu, s, o);
        float inv = 1.f / s;
        alpha[i][lane] = e0 * inv;
        alpha[i][lane+32] = e1 * inv;
    }
    __syncthreads();

    for (int idx = tid; idx < Ldim*Dn; idx += 256) {
        int i = idx / Dn, d = idx % Dn;
        float acc = 0.f;
        for (int j = 0; j < Ldim; j++) acc += alpha[i][j] * hs[j][d];
        g_hlocal[((size_t)b*Ldim + i)*Dn + d] = acc;
    }
}

// ---------------- K2: sess mean ----------------
__global__ __launch_bounds__(128) void k_sess(
    const int* __restrict__ seq_features, const float* __restrict__ mask,
    const float* __restrict__ emb)
{
    int b = blockIdx.x, tid = threadIdx.x;
    if (tid >= Dn) return;
    float acc = 0.f, msum = 0.f;
    for (int l = 0; l < Ldim; l++) {
        float mk = mask[b*Ldim + l];
        acc += emb[(size_t)seq_features[b*Ldim + l]*Dn + tid] * mk;
        msum += mk;
    }
    g_sess[b*Dn + tid] = acc / msum;
}

// ---------------- K3: global neighbor aggregation (float4-tiled GEMM) -------
// dyn smem float offsets (keep FEAT 16B-aligned)
#define G_W1S  0        // 10100
#define G_W2S  10100    // 100
#define G_SESS 10200    // 100
#define G_FEAT 10304    // 48 rows x 104 stride = 4992
#define G_ALSC 15296    // 48
#define G_RED  15344    // 48 x 25 = 1200
#define G_NBR  16544    // 48 ints
#define G_SMEM_FLOATS 16592
__global__ __launch_bounds__(256) void k_global(
    const int* __restrict__ items, const int* __restrict__ adj_all,
    const float* __restrict__ num_w, const float* __restrict__ emb,
    const float* __restrict__ g_w1, const float* __restrict__ g_w2)
{
    extern __shared__ float sm[];
    float* w1s   = sm + G_W1S;
    float* w2s   = sm + G_W2S;
    float* sesss = sm + G_SESS;
    float* feat  = sm + G_FEAT;   // stride 104
    float* alsc  = sm + G_ALSC;
    float* red   = sm + G_RED;    // [48][25]
    int*   nbrs  = (int*)(sm + G_NBR);

    int blk = blockIdx.x;
    int b = blk >> 2;
    int l0 = (blk & 3) * 16;
    int tid = threadIdx.x;

    for (int i = tid; i < 101*100; i += 256) w1s[i] = g_w1[i];
    if (tid < Dn) { w2s[tid] = g_w2[tid]; sesss[tid] = g_sess[b*Dn + tid]; }
    __syncthreads();

    // thread GEMM mapping: 200 active: rg in 0..7 (6 rows), cg in 0..24 (4 cols)
    int rg = tid / 25, cg = tid % 25;
    bool gact = (tid < 200);

    for (int lquad = 0; lquad < 4; lquad++) {
        int lbase = l0 + lquad*4;
        if (tid < 48) {
            int lsl = tid / 12, s = tid % 12;
            int node = items[b*Ldim + lbase + lsl];
            nbrs[tid] = adj_all[(size_t)node*Sn + s];
            feat[tid*104 + 100] = num_w[(size_t)node*Sn + s];
        }
        __syncthreads();
        for (int idx = tid; idx < 48*100; idx += 256) {
            int row = idx / 100, c = idx % 100;
            feat[row*104 + c] = sesss[c] * emb[(size_t)nbrs[row]*Dn + c];
        }
        __syncthreads();

        if (gact) {
            float al[6][4];
            #pragma unroll
            for (int r = 0; r < 6; r++)
                #pragma unroll
                for (int j = 0; j < 4; j++) al[r][j] = 0.f;

            const float* wcol = w1s + cg*4;
            const float* frow = feat + rg*6*104;
            #pragma unroll 5
            for (int cb = 0; cb < 100; cb += 4) {
                float4 w0 = *(const float4*)(wcol + (cb+0)*100);
                float4 w1 = *(const float4*)(wcol + (cb+1)*100);
                float4 w2 = *(const float4*)(wcol + (cb+2)*100);
                float4 w3 = *(const float4*)(wcol + (cb+3)*100);
                #pragma unroll
                for (int r = 0; r < 6; r++) {
                    float4 f = *(const float4*)(frow + r*104 + cb);
                    al[r][0] = fmaf(f.x, w0.x, al[r][0]);
                    al[r][1] = fmaf(f.x, w0.y, al[r][1]);
                    al[r][2] = fmaf(f.x, w0.z, al[r][2]);
                    al[r][3] = fmaf(f.x, w0.w, al[r][3]);
                    al[r][0] = fmaf(f.y, w1.x, al[r][0]);
                    al[r][1] = fmaf(f.y, w1.y, al[r][1]);
                    al[r][2] = fmaf(f.y, w1.z, al[r][2]);
                    al[r][3] = fmaf(f.y, w1.w, al[r][3]);
                    al[r][0] = fmaf(f.z, w2.x, al[r][0]);
                    al[r][1] = fmaf(f.z, w2.y, al[r][1]);
                    al[r][2] = fmaf(f.z, w2.z, al[r][2]);
                    al[r][3] = fmaf(f.z, w2.w, al[r][3]);
                    al[r][0] = fmaf(f.w, w3.x, al[r][0]);
                    al[r][1] = fmaf(f.w, w3.y, al[r][1]);
                    al[r][2] = fmaf(f.w, w3.z, al[r][2]);
                    al[r][3] = fmaf(f.w, w3.w, al[r][3]);
                }
            }
            // c = 100 (num_w column)
            float4 wl = *(const float4*)(wcol + 100*100);
            float4 wv = *(const float4*)(w2s + cg*4);
            #pragma unroll
            for (int r = 0; r < 6; r++) {
                float f = frow[r*104 + 100];
                al[r][0] = fmaf(f, wl.x, al[r][0]);
                al[r][1] = fmaf(f, wl.y, al[r][1]);
                al[r][2] = fmaf(f, wl.z, al[r][2]);
                al[r][3] = fmaf(f, wl.w, al[r][3]);
                float v0 = al[r][0] > 0.f ? al[r][0] : 0.2f*al[r][0];
                float v1 = al[r][1] > 0.f ? al[r][1] : 0.2f*al[r][1];
                float v2 = al[r][2] > 0.f ? al[r][2] : 0.2f*al[r][2];
                float v3 = al[r][3] > 0.f ? al[r][3] : 0.2f*al[r][3];
                red[(rg*6 + r)*25 + cg] =
                    fmaf(v0, wv.x, fmaf(v1, wv.y, fmaf(v2, wv.z, v3*wv.w)));
            }
        }
        __syncthreads();
        if (tid < 48) {
            float s_ = 0.f;
            #pragma unroll
            for (int k = 0; k < 25; k++) s_ += red[tid*25 + k];
            alsc[tid] = s_;
        }
        __syncthreads();
        if (tid < 4) {
            float* a = alsc + tid*12;
            float m = a[0];
            #pragma unroll
            for (int s = 1; s < Sn; s++) m = fmaxf(m, a[s]);
            float ssum = 0.f;
            float e[Sn];
            #pragma unroll
            for (int s = 0; s < Sn; s++) { e[s] = __expf(a[s] - m); ssum += e[s]; }
            float inv = 1.f / ssum;
            #pragma unroll
            for (int s = 0; s < Sn; s++) a[s] = e[s] * inv;
        }
        __syncthreads();
        for (int idx = tid; idx < 400; idx += 256) {
            int lsl = idx / 100, c = idx % 100;
            float acc = 0.f;
            #pragma unroll
            for (int s = 0; s < Sn; s++)
                acc = fmaf(alsc[lsl*12 + s], emb[(size_t)nbrs[lsl*12 + s]*Dn + c], acc);
            g_nb[((size_t)b*Ldim + lbase + lsl)*Dn + c] = acc;
        }
        __syncthreads();
    }
}

// ---------------- K4: h_combine = relu([h,nb]@g_w3) + h_local ----------------
__global__ __launch_bounds__(256) void k_combine(const float* __restrict__ g_w3)
{
    extern __shared__ float sm[];
    float* w_s = sm;            // 20000
    float* ins = sm + 20000;    // 32 x 200
    int tid = threadIdx.x;
    int row0 = blockIdx.x * 32;
    for (int i = tid; i < 200*100; i += 256) w_s[i] = g_w3[i];
    for (int idx = tid; idx < 32*200; idx += 256) {
        int r = idx / 200, k = idx % 200;
        size_t row = row0 + r;
        ins[r*200 + k] = (k < 100) ? g_h[row*Dn + k] : g_nb[row*Dn + (k-100)];
    }
    __syncthreads();
    int lane = tid & 31, ty = tid >> 5;
    int r0 = ty * 4;
    float acc[4][4] = {};
    for (int k = 0; k < 200; k++) {
        float w0 = w_s[k*100 + lane];
        float w1 = w_s[k*100 + lane + 32];
        float w2 = w_s[k*100 + lane + 64];
        float w3 = (lane < 4) ? w_s[k*100 + lane + 96] : 0.f;
        #pragma unroll
        for (int i = 0; i < 4; i++) {
            float a = ins[(r0+i)*200 + k];
            acc[i][0] = fmaf(a, w0, acc[i][0]);
            acc[i][1] = fmaf(a, w1, acc[i][1]);
            acc[i][2] = fmaf(a, w2, acc[i][2]);
            acc[i][3] = fmaf(a, w3, acc[i][3]);
        }
    }
    #pragma unroll
    for (int i = 0; i < 4; i++) {
        size_t row = row0 + r0 + i;
        #pragma unroll
        for (int q = 0; q < 4; q++) {
            int c = lane + 32*q;
            if (c < 100)
                g_hcomb[row*Dn + c] = g_hlocal[row*Dn + c] + fmaxf(acc[i][q], 0.f);
        }
    }
}

// ---------------- K5a: seq gather, hs, hsg ----------------
__global__ __launch_bounds__(128) void k_seqhs(
    const int* __restrict__ alias, const float* __restrict__ mask,
    const float* __restrict__ glu2_w, const float* __restrict__ glu2_b)
{
    int b = blockIdx.x, tid = threadIdx.x;
    __shared__ float hs_s[Dn];
    __shared__ int alias_s[Ldim];
    __shared__ float mk_s[Ldim];
    if (tid < Ldim) { alias_s[tid] = alias[b*Ldim + tid]; mk_s[tid] = mask[b*Ldim + tid]; }
    __syncthreads();
    if (tid < Dn) {
        float acc = 0.f, msum = 0.f;
        for (int l = 0; l < Ldim; l++) {
            float v = g_hcomb[((size_t)b*Ldim + alias_s[l])*Dn + tid];
            g_seq[((size_t)b*Ldim + l)*Dn + tid] = v;
            acc += v * mk_s[l];
            msum += mk_s[l];
        }
        hs_s[tid] = acc / msum;
    }
    __syncthreads();
    if (tid < Dn) {
        float t = glu2_b[tid];
        for (int c = 0; c < Dn; c++) t = fmaf(hs_s[c], __ldg(&glu2_w[c*Dn + tid]), t);
        g_hsg[b*Dn + tid] = t;
    }
}

// ---------------- K5b: nh = tanh([pe, seq]@w_1) ----------------
__global__ __launch_bounds__(256) void k_nh(
    const float* __restrict__ pos_emb, const float* __restrict__ w_1)
{
    extern __shared__ float sm[];
    float* w_s = sm;            // 20000
    float* ins = sm + 20000;    // 32 x 200
    int tid = threadIdx.x;
    int row0 = blockIdx.x * 32;
    for (int i = tid; i < 200*100; i += 256) w_s[i] = w_1[i];
    for (int idx = tid; idx < 32*200; idx += 256) {
        int r = idx / 200, k = idx % 200;
        size_t row = row0 + r;
        int l = (int)(row % Ldim);
        ins[r*200 + k] = (k < 100) ? pos_emb[l*Dn + k] : g_seq[row*Dn + (k-100)];
    }
    __syncthreads();
    int lane = tid & 31, ty = tid >> 5;
    int r0 = ty * 4;
    float acc[4][4] = {};
    for (int k = 0; k < 200; k++) {
        float w0 = w_s[k*100 + lane];
        float w1 = w_s[k*100 + lane + 32];
        float w2 = w_s[k*100 + lane + 64];
        float w3 = (lane < 4) ? w_s[k*100 + lane + 96] : 0.f;
        #pragma unroll
        for (int i = 0; i < 4; i++) {
            float a = ins[(r0+i)*200 + k];
            acc[i][0] = fmaf(a, w0, acc[i][0]);
            acc[i][1] = fmaf(a, w1, acc[i][1]);
            acc[i][2] = fmaf(a, w2, acc[i][2]);
            acc[i][3] = fmaf(a, w3, acc[i][3]);
        }
    }
    #pragma unroll
    for (int i = 0; i < 4; i++) {
        size_t row = row0 + r0 + i;
        #pragma unroll
        for (int q = 0; q < 4; q++) {
            int c = lane + 32*q;
            if (c < 100) g_nh[row*Dn + c] = tanhf(acc[i][q]);
        }
    }
}

// ---------------- K5c: GLU sigmoid, beta, select ----------------
__global__ __launch_bounds__(128) void k_select(
    const float* __restrict__ glu1_w, const float* __restrict__ glu1_b,
    const float* __restrict__ w_2, const float* __restrict__ mask)
{
    int b = blockIdx.x, tid = threadIdx.x;
    __shared__ float w1s[100*100];
    __shared__ float nh_s[Dn], seq_s[Dn], red[128];
    __shared__ float w2s[Dn], hb_s[Dn];
    for (int i = tid; i < 100*100; i += 128) w1s[i] = glu1_w[i];
    if (tid < Dn) { w2s[tid] = w_2[tid]; hb_s[tid] = glu1_b[tid] + g_hsg[b*Dn + tid]; }
    __syncthreads();
    float sel = 0.f;
    for (int l = 0; l < Ldim; l++) {
        if (tid < Dn) {
            nh_s[tid]  = g_nh[((size_t)b*Ldim + l)*Dn + tid];
            seq_s[tid] = g_seq[((size_t)b*Ldim + l)*Dn + tid];
        }
        __syncthreads();
        float contrib = 0.f;
        if (tid < Dn) {
            float t = hb_s[tid];
            for (int c = 0; c < Dn; c++) t = fmaf(nh_s[c], w1s[c*100 + tid], t);
            float sg = 1.f / (1.f + __expf(-t));
            contrib = sg * w2s[tid];
        }
        red[tid] = contrib;
        __syncthreads();
        for (int st = 64; st > 0; st >>= 1) {
            if (tid < st) red[tid] += red[tid + st];
            __syncthreads();
        }
        float beta = red[0] * mask[b*Ldim + l];
        if (tid < Dn) sel += beta * seq_s[tid];
        __syncthreads();
    }
    if (tid < Dn) g_select[b*Dn + tid] = sel;
}

// ---------------- K6a: score = select @ emb[1:]^T (float4), row-max atomics --
// dyn smem: sel 32x104 + emb 128x104
__global__ __launch_bounds__(256) void k_score(
    const float* __restrict__ emb, float* __restrict__ out)
{
    extern __shared__ float sm[];
    float* sel_s = sm;            // 32 x 104
    float* emb_s = sm + 32*104;   // 128 x 104
    int n0 = blockIdx.x * 128, b0 = blockIdx.y * 32;
    int tid = threadIdx.x;
    // float4 loads: 32x25 and 128x25 float4s
    for (int idx = tid; idx < 32*25; idx += 256) {
        int r = idx / 25, c4 = idx % 25;
        float4 v = *(const float4*)(g_select + (b0 + r)*Dn + c4*4);
        *(float4*)(sel_s + r*104 + c4*4) = v;
    }
    for (int idx = tid; idx < 128*25; idx += 256) {
        int r = idx / 25, c4 = idx % 25;
        int n = n0 + r;
        float4 v = make_float4(0.f,0.f,0.f,0.f);
        if (n < NOUT) v = *(const float4*)(emb + (size_t)(n + 1)*Dn + c4*4);
        *(float4*)(emb_s + r*104 + c4*4) = v;
    }
    __syncthreads();
    int lane = tid & 31, ty = tid >> 5;
    int rb = ty * 4;
    float acc[4][4] = {};
    #pragma unroll 5
    for (int k = 0; k < 100; k += 4) {
        float4 e0 = *(const float4*)(emb_s + lane*104 + k);
        float4 e1 = *(const float4*)(emb_s + (lane+32)*104 + k);
        float4 e2 = *(const float4*)(emb_s + (lane+64)*104 + k);
        float4 e3 = *(const float4*)(emb_s + (lane+96)*104 + k);
        #pragma unroll
        for (int i = 0; i < 4; i++) {
            float4 s = *(const float4*)(sel_s + (rb+i)*104 + k);
            acc[i][0] = fmaf(s.x, e0.x, acc[i][0]);
            acc[i][1] = fmaf(s.x, e1.x, acc[i][1]);
            acc[i][2] = fmaf(s.x, e2.x, acc[i][2]);
            acc[i][3] = fmaf(s.x, e3.x, acc[i][3]);
            acc[i][0] = fmaf(s.y, e0.y, acc[i][0]);
            acc[i][1] = fmaf(s.y, e1.y, acc[i][1]);
            acc[i][2] = fmaf(s.y, e2.y, acc[i][2]);
            acc[i][3] = fmaf(s.y, e3.y, acc[i][3]);
            acc[i][0] = fmaf(s.z, e0.z, acc[i][0]);
            acc[i][1] = fmaf(s.z, e1.z, acc[i][1]);
            acc[i][2] = fmaf(s.z, e2.z, acc[i][2]);
            acc[i][3] = fmaf(s.z, e3.z, acc[i][3]);
            acc[i][0] = fmaf(s.w, e0.w, acc[i][0]);
            acc[i][1] = fmaf(s.w, e1.w, acc[i][1]);
            acc[i][2] = fmaf(s.w, e2.w, acc[i][2]);
            acc[i][3] = fmaf(s.w, e3.w, acc[i][3]);
        }
    }
    float rowmax[4] = {-3.0e38f, -3.0e38f, -3.0e38f, -3.0e38f};
    #pragma unroll
    for (int i = 0; i < 4; i++) {
        #pragma unroll
        for (int q = 0; q < 4; q++) {
            int n = n0 + lane + 32*q;
            if (n < NOUT) {
                out[(size_t)(b0 + rb + i)*NOUT + n] = acc[i][q];
                rowmax[i] = fmaxf(rowmax[i], acc[i][q]);
            }
        }
    }
    #pragma unroll
    for (int i = 0; i < 4; i++) {
        float m = rowmax[i];
        #pragma unroll
        for (int o = 16; o > 0; o >>= 1) m = fmaxf(m, __shfl_xor_sync(0xffffffffu, m, o));
        if (lane == 0) atomicMax(&g_rmaxbits[b0 + rb + i], fkey(m));
    }
}

// ---------------- K6b: per-chunk sum of exp ----------------
__global__ __launch_bounds__(256) void k_expsum(const float* __restrict__ out)
{
    int b = blockIdx.y, chunk = blockIdx.x, tid = threadIdx.x;
    int start = chunk * CHUNKSZ;
    int end = start + CHUNKSZ; if (end > NOUT) end = NOUT;
    float m = funkey(g_rmaxbits[b]);
    float s = 0.f;
    for (int n = start + tid; n < end; n += 256)
        s += fexp(out[(size_t)b*NOUT + n] - m);
    __shared__ float red[256];
    red[tid] = s;
    __syncthreads();
    for (int st = 128; st > 0; st >>= 1) {
        if (tid < st) red[tid] += red[tid + st];
        __syncthreads();
    }
    if (tid == 0) g_rpart[b*NCHUNK + chunk] = red[0];
}

// ---------------- K6c: exp + scale ----------------
__global__ __launch_bounds__(256) void k_scale(float* __restrict__ out)
{
    int b = blockIdx.y;
    int n = blockIdx.x * 256 + threadIdx.x;
    if (n < NOUT) {
        float ssum = 0.f;
        #pragma unroll
        for (int j = 0; j < NCHUNK; j++) ssum += g_rpart[b*NCHUNK + j];
        float m = funkey(g_rmaxbits[b]);
        float inv = __fdividef(1.f, ssum);
        size_t idx = (size_t)b*NOUT + n;
        out[idx] = fexp(out[idx] - m) * inv;
    }
}

// ---------------- launch ----------------
extern "C" void kernel_launch(void* const* d_in, const int* in_sizes, int n_in,
                              void* d_out, int out_size)
{
    const int*   alias_inputs = (const int*)  d_in[0];
    const int*   items        = (const int*)  d_in[1];
    const int*   adj          = (const int*)  d_in[2];
    const float* mask_item    = (const float*)d_in[3];
    const int*   seq_features = (const int*)  d_in[4];
    const int*   adj_all      = (const int*)  d_in[5];
    const float* num_w        = (const float*)d_in[6];
    const float* emb          = (const float*)d_in[7];
    const float* pos_emb      = (const float*)d_in[8];
    const float* a0           = (const float*)d_in[9];
    const float* a1           = (const float*)d_in[10];
    const float* a2           = (const float*)d_in[11];
    const float* a3           = (const float*)d_in[12];
    const float* g_w1         = (const float*)d_in[13];
    const float* g_w2         = (const float*)d_in[14];
    const float* g_w3         = (const float*)d_in[15];
    const float* w_1          = (const float*)d_in[16];
    const float* w_2          = (const float*)d_in[17];
    const float* glu1_w       = (const float*)d_in[18];
    const float* glu1_b       = (const float*)d_in[19];
    const float* glu2_w       = (const float*)d_in[20];
    const float* glu2_b       = (const float*)d_in[21];
    float* out = (float*)d_out;

    const int GSMEM = G_SMEM_FLOATS * 4;           // ~66.4 KB
    const int CSMEM = (20000 + 32*200) * 4;        // ~105.6 KB
    const int SSMEM = (32*104 + 128*104) * 4;      // ~66.6 KB
    cudaFuncSetAttribute(k_global,  cudaFuncAttributeMaxDynamicSharedMemorySize, GSMEM);
    cudaFuncSetAttribute(k_combine, cudaFuncAttributeMaxDynamicSharedMemorySize, CSMEM);
    cudaFuncSetAttribute(k_nh,      cudaFuncAttributeMaxDynamicSharedMemorySize, CSMEM);
    cudaFuncSetAttribute(k_score,   cudaFuncAttributeMaxDynamicSharedMemorySize, SSMEM);

    k_init   <<<1, 256>>>();
    k_local  <<<Bn, 256>>>(items, adj, emb, a0, a1, a2, a3);
    k_sess   <<<Bn, 128>>>(seq_features, mask_item, emb);
    k_global <<<Bn*4, 256, GSMEM>>>(items, adj_all, num_w, emb, g_w1, g_w2);
    k_combine<<<(Bn*Ldim)/32, 256, CSMEM>>>(g_w3);
    k_seqhs  <<<Bn, 128>>>(alias_inputs, mask_item, glu2_w, glu2_b);
    k_nh     <<<(Bn*Ldim)/32, 256, CSMEM>>>(pos_emb, w_1);
    k_select <<<Bn, 128>>>(glu1_w, glu1_b, w_2, mask_item);
    dim3 gs((NOUT + 127)/128, Bn/32);
    k_score  <<<gs, 256, SSMEM>>>(emb, out);
    dim3 ge(NCHUNK, Bn);
    k_expsum <<<ge, 256>>>(out);
    dim3 gn((NOUT + 255)/256, Bn);
    k_scale  <<<gn, 256>>>(out);
}

// round 5
// speedup vs baseline: 1.3909x; 1.1080x over previous
#include <cuda_runtime.h>
#include <math.h>
#include <stdint.h>

#define Bn 256
#define Ldim 64
#define Sn 12
#define Dn 100
#define NUM_NODE 43098
#define NOUT 43097
#define NEGV -9000000000000000.0f
#define NCHUNK 8
#define CHUNKSZ 5388   // ceil(43097/8)

// ---------------- scratch (device globals; no allocation) ----------------
__device__ float g_h[Bn*Ldim*Dn];
__device__ float g_hlocal[Bn*Ldim*Dn];
__device__ float g_sess[Bn*Dn];
__device__ float g_nb[Bn*Ldim*Dn];
__device__ float g_hcomb[Bn*Ldim*Dn];
__device__ float g_seq[Bn*Ldim*Dn];
__device__ float g_nh[Bn*Ldim*Dn];
__device__ float g_hsg[Bn*Dn];
__device__ float g_select[Bn*Dn];
__device__ unsigned g_rmaxbits[Bn];
__device__ float g_rpart[Bn*NCHUNK];

// monotonic float->uint key for atomicMax over signed floats
__device__ __forceinline__ unsigned fkey(float f) {
    unsigned u = __float_as_uint(f);
    return (u & 0x80000000u) ? ~u : (u | 0x80000000u);
}
__device__ __forceinline__ float funkey(unsigned k) {
    return (k & 0x80000000u) ? __uint_as_float(k ^ 0x80000000u)
                             : __uint_as_float(~k);
}

// fast exp via FMA-pipe polynomial (x <= 0 expected)
__device__ __forceinline__ float fexp(float x) {
    float y = x * 1.44269504088896340736f;
    y = fmaxf(y, -126.0f);
    float t = y + 12582912.0f;
    float i = t - 12582912.0f;
    float f = y - i;
    int ii = (int)i;
    float p = 1.54035303933816e-4f;
    p = fmaf(p, f, 1.33335581464284e-3f);
    p = fmaf(p, f, 9.61812910762848e-3f);
    p = fmaf(p, f, 5.55041086648216e-2f);
    p = fmaf(p, f, 2.40226506959101e-1f);
    p = fmaf(p, f, 6.93147180559945e-1f);
    p = fmaf(p, f, 1.0f);
    return p * __int_as_float((ii + 127) << 23);
}

__device__ __forceinline__ float to_tf32(float x) {
    uint32_t r;
    asm("cvt.rna.tf32.f32 %0, %1;" : "=r"(r) : "f"(x));
    return __uint_as_float(r);
}

// ---------------- K0: zero per-row stats ----------------
__global__ void k_init() {
    int t = threadIdx.x;
    if (t < Bn) g_rmaxbits[t] = 0u;
}

// ---------------- K1: gather h, local graph attention, h_local ----------------
__global__ __launch_bounds__(256) void k_local(
    const int* __restrict__ items, const int* __restrict__ adj,
    const float* __restrict__ emb,
    const float* __restrict__ a0, const float* __restrict__ a1,
    const float* __restrict__ a2, const float* __restrict__ a3)
{
    int b = blockIdx.x;
    __shared__ float hs[Ldim][101];
    __shared__ float alpha[Ldim][Ldim+1];
    __shared__ float As[Dn][4];
    int tid = threadIdx.x;

    for (int i = tid; i < Dn; i += 256) {
        As[i][0] = a0[i]; As[i][1] = a1[i]; As[i][2] = a2[i]; As[i][3] = a3[i];
    }
    for (int idx = tid; idx < Ldim*Dn; idx += 256) {
        int l = idx / Dn, d = idx % Dn;
        float v = emb[(size_t)items[b*Ldim + l]*Dn + d];
        hs[l][d] = v;
        g_h[((size_t)b*Ldim + l)*Dn + d] = v;
    }
    __syncthreads();

    for (int p = tid; p < Ldim*Ldim; p += 256) {
        int i = p / Ldim, j = p % Ldim;
        int a = adj[((size_t)b*Ldim + i)*Ldim + j];
        float val = NEGV;
        if (a >= 1 && a <= 4) {
            float acc = 0.f;
            int k = a - 1;
            for (int d = 0; d < Dn; d++)
                acc += hs[i][d] * hs[j][d] * As[d][k];
            val = acc > 0.f ? acc : 0.2f * acc;
        }
        alpha[i][j] = val;
    }
    __syncthreads();

    int warp = tid >> 5, lane = tid & 31;
    for (int i = warp; i < Ldim; i += 8) {
        float x0 = alpha[i][lane], x1 = alpha[i][lane+32];
        float m = fmaxf(x0, x1);
        #pragma unroll
        for (int o = 16; o > 0; o >>= 1) m = fmaxf(m, __shfl_xor_sync(0xffffffffu, m, o));
        float e0 = __expf(fmaxf(x0 - m, -87.f));
        float e1 = __expf(fmaxf(x1 - m, -87.f));
        float s = e0 + e1;
        #pragma unroll
        for (int o = 16; o > 0; o >>= 1) s += __shfl_xor_sync(0xffffffffu, s, o);
        float inv = 1.f / s;
        alpha[i][lane] = e0 * inv;
        alpha[i][lane+32] = e1 * inv;
    }
    __syncthreads();

    for (int idx = tid; idx < Ldim*Dn; idx += 256) {
        int i = idx / Dn, d = idx % Dn;
        float acc = 0.f;
        for (int j = 0; j < Ldim; j++) acc += alpha[i][j] * hs[j][d];
        g_hlocal[((size_t)b*Ldim + i)*Dn + d] = acc;
    }
}

// ---------------- K2: sess mean ----------------
__global__ __launch_bounds__(128) void k_sess(
    const int* __restrict__ seq_features, const float* __restrict__ mask,
    const float* __restrict__ emb)
{
    int b = blockIdx.x, tid = threadIdx.x;
    if (tid >= Dn) return;
    float acc = 0.f, msum = 0.f;
    for (int l = 0; l < Ldim; l++) {
        float mk = mask[b*Ldim + l];
        acc += emb[(size_t)seq_features[b*Ldim + l]*Dn + tid] * mk;
        msum += mk;
    }
    g_sess[b*Dn + tid] = acc / msum;
}

// ---------------- K3: global neighbor aggregation (tf32 mma.sync) ----------
// A = feat [96 x 104(k)] tf32, stride 108 (conflict-free fragment loads)
// B = g_w1 [104(k) x 104(n)] tf32 padded
// smem float offsets:
#define GT_W1   0        // 104*104 = 10816
#define GT_FEAT 10816    // 96*108  = 10368
#define GT_W2   21184    // 104
#define GT_SESS 21288    // 100
#define GT_ALSC 21388    // 96
#define GT_NBR  21484    // 96 ints
#define GT_TOT  21580
__global__ __launch_bounds__(192) void k_global(
    const int* __restrict__ items, const int* __restrict__ adj_all,
    const float* __restrict__ num_w, const float* __restrict__ emb,
    const float* __restrict__ g_w1, const float* __restrict__ g_w2)
{
    extern __shared__ float sm[];
    float* w1s   = sm + GT_W1;
    float* feat  = sm + GT_FEAT;
    float* w2s   = sm + GT_W2;
    float* sesss = sm + GT_SESS;
    float* alsc  = sm + GT_ALSC;
    int*   nbrs  = (int*)(sm + GT_NBR);

    int blk = blockIdx.x;
    int b = blk >> 3;
    int l0 = (blk & 7) * 8;
    int tid = threadIdx.x;
    int lane = tid & 31, warp = tid >> 5;

    // zero + fill B (tf32)
    for (int i = tid; i < 104*104; i += 192) w1s[i] = 0.f;
    if (tid < 104) w2s[tid] = (tid < Dn) ? g_w2[tid] : 0.f;
    if (tid < Dn) sesss[tid] = g_sess[b*Dn + tid];
    // neighbor ids + num_w column (96 rows = 8 l x 12 s)
    if (tid < 96) {
        int l = tid / 12, s = tid % 12;
        int node = items[b*Ldim + l0 + l];
        nbrs[tid] = adj_all[(size_t)node*Sn + s];
        feat[tid*108 + 100] = to_tf32(num_w[(size_t)node*Sn + s]);
        feat[tid*108 + 101] = 0.f;
        feat[tid*108 + 102] = 0.f;
        feat[tid*108 + 103] = 0.f;
    }
    __syncthreads();
    for (int i = tid; i < 101*100; i += 192) {
        int k = i / 100, n = i % 100;
        w1s[k*104 + n] = to_tf32(g_w1[i]);
    }
    // gather feat = tf32(sess * emb[nbr])
    for (int idx = tid; idx < 96*25; idx += 192) {
        int r = idx / 25, c4 = (idx % 25) * 4;
        float4 e = *(const float4*)(emb + (size_t)nbrs[r]*Dn + c4);
        float* dst = feat + r*108 + c4;
        dst[0] = to_tf32(e.x * sesss[c4+0]);
        dst[1] = to_tf32(e.y * sesss[c4+1]);
        dst[2] = to_tf32(e.z * sesss[c4+2]);
        dst[3] = to_tf32(e.w * sesss[c4+3]);
    }
    __syncthreads();

    // warp w handles rows [w*16, w*16+16)
    int g = lane >> 2, tg = lane & 3;
    const float* Ab = feat + warp*16*108;
    float score_a = 0.f, score_b = 0.f;   // rows g and g+8 (partial over cols)
    #pragma unroll 1
    for (int nt = 0; nt < 13; nt++) {
        float c0 = 0.f, c1 = 0.f, c2 = 0.f, c3 = 0.f;
        #pragma unroll
        for (int kt = 0; kt < 13; kt++) {
            int ak = kt*8;
            uint32_t a0 = __float_as_uint(Ab[ g     *108 + ak + tg    ]);
            uint32_t a1 = __float_as_uint(Ab[(g+8)  *108 + ak + tg    ]);
            uint32_t a2 = __float_as_uint(Ab[ g     *108 + ak + tg + 4]);
            uint32_t a3 = __float_as_uint(Ab[(g+8)  *108 + ak + tg + 4]);
            uint32_t b0 = __float_as_uint(w1s[(ak + tg    )*104 + nt*8 + g]);
            uint32_t b1 = __float_as_uint(w1s[(ak + tg + 4)*104 + nt*8 + g]);
            asm volatile(
                "mma.sync.aligned.m16n8k8.row.col.f32.tf32.tf32.f32 "
                "{%0,%1,%2,%3}, {%4,%5,%6,%7}, {%8,%9}, {%0,%1,%2,%3};"
                : "+f"(c0), "+f"(c1), "+f"(c2), "+f"(c3)
                : "r"(a0), "r"(a1), "r"(a2), "r"(a3), "r"(b0), "r"(b1));
        }
        int j0 = nt*8 + tg*2;
        float w20 = w2s[j0], w21 = w2s[j0+1];
        float v0 = c0 > 0.f ? c0 : 0.2f*c0;
        float v1 = c1 > 0.f ? c1 : 0.2f*c1;
        float v2 = c2 > 0.f ? c2 : 0.2f*c2;
        float v3 = c3 > 0.f ? c3 : 0.2f*c3;
        score_a = fmaf(v0, w20, fmaf(v1, w21, score_a));
        score_b = fmaf(v2, w20, fmaf(v3, w21, score_b));
    }
    // reduce col partials over the 4 lanes of each row group
    score_a += __shfl_xor_sync(0xffffffffu, score_a, 1);
    score_a += __shfl_xor_sync(0xffffffffu, score_a, 2);
    score_b += __shfl_xor_sync(0xffffffffu, score_b, 1);
    score_b += __shfl_xor_sync(0xffffffffu, score_b, 2);
    if (tg == 0) {
        alsc[warp*16 + g]     = score_a;
        alsc[warp*16 + g + 8] = score_b;
    }
    __syncthreads();

    // softmax over 12 per l
    if (tid < 8) {
        float* a = alsc + tid*12;
        float m = a[0];
        #pragma unroll
        for (int s = 1; s < Sn; s++) m = fmaxf(m, a[s]);
        float ssum = 0.f;
        float e[Sn];
        #pragma unroll
        for (int s = 0; s < Sn; s++) { e[s] = __expf(a[s] - m); ssum += e[s]; }
        float inv = 1.f / ssum;
        #pragma unroll
        for (int s = 0; s < Sn; s++) a[s] = e[s] * inv;
    }
    __syncthreads();

    // nb = sum_s alpha_s * emb[nbr_s]  (fp32, raw emb)
    for (int idx = tid; idx < 800; idx += 192) {
        int l = idx / 100, c = idx % 100;
        float acc = 0.f;
        #pragma unroll
        for (int s = 0; s < Sn; s++)
            acc = fmaf(alsc[l*12 + s], emb[(size_t)nbrs[l*12 + s]*Dn + c], acc);
        g_nb[((size_t)b*Ldim + l0 + l)*Dn + c] = acc;
    }
}

// ---------------- K4: h_combine = relu([h,nb]@g_w3) + h_local ----------------
__global__ __launch_bounds__(256) void k_combine(const float* __restrict__ g_w3)
{
    extern __shared__ float sm[];
    float* w_s = sm;            // 20000
    float* ins = sm + 20000;    // 32 x 200
    int tid = threadIdx.x;
    int row0 = blockIdx.x * 32;
    for (int i = tid; i < 200*100; i += 256) w_s[i] = g_w3[i];
    for (int idx = tid; idx < 32*200; idx += 256) {
        int r = idx / 200, k = idx % 200;
        size_t row = row0 + r;
        ins[r*200 + k] = (k < 100) ? g_h[row*Dn + k] : g_nb[row*Dn + (k-100)];
    }
    __syncthreads();
    int lane = tid & 31, ty = tid >> 5;
    int r0 = ty * 4;
    float acc[4][4] = {};
    for (int k = 0; k < 200; k++) {
        float w0 = w_s[k*100 + lane];
        float w1 = w_s[k*100 + lane + 32];
        float w2 = w_s[k*100 + lane + 64];
        float w3 = (lane < 4) ? w_s[k*100 + lane + 96] : 0.f;
        #pragma unroll
        for (int i = 0; i < 4; i++) {
            float a = ins[(r0+i)*200 + k];
            acc[i][0] = fmaf(a, w0, acc[i][0]);
            acc[i][1] = fmaf(a, w1, acc[i][1]);
            acc[i][2] = fmaf(a, w2, acc[i][2]);
            acc[i][3] = fmaf(a, w3, acc[i][3]);
        }
    }
    #pragma unroll
    for (int i = 0; i < 4; i++) {
        size_t row = row0 + r0 + i;
        #pragma unroll
        for (int q = 0; q < 4; q++) {
            int c = lane + 32*q;
            if (c < 100)
                g_hcomb[row*Dn + c] = g_hlocal[row*Dn + c] + fmaxf(acc[i][q], 0.f);
        }
    }
}

// ---------------- K5a: seq gather, hs, hsg ----------------
__global__ __launch_bounds__(128) void k_seqhs(
    const int* __restrict__ alias, const float* __restrict__ mask,
    const float* __restrict__ glu2_w, const float* __restrict__ glu2_b)
{
    int b = blockIdx.x, tid = threadIdx.x;
    __shared__ float hs_s[Dn];
    __shared__ int alias_s[Ldim];
    __shared__ float mk_s[Ldim];
    if (tid < Ldim) { alias_s[tid] = alias[b*Ldim + tid]; mk_s[tid] = mask[b*Ldim + tid]; }
    __syncthreads();
    if (tid < Dn) {
        float acc = 0.f, msum = 0.f;
        for (int l = 0; l < Ldim; l++) {
            float v = g_hcomb[((size_t)b*Ldim + alias_s[l])*Dn + tid];
            g_seq[((size_t)b*Ldim + l)*Dn + tid] = v;
            acc += v * mk_s[l];
            msum += mk_s[l];
        }
        hs_s[tid] = acc / msum;
    }
    __syncthreads();
    if (tid < Dn) {
        float t = glu2_b[tid];
        for (int c = 0; c < Dn; c++) t = fmaf(hs_s[c], __ldg(&glu2_w[c*Dn + tid]), t);
        g_hsg[b*Dn + tid] = t;
    }
}

// ---------------- K5b: nh = tanh([pe, seq]@w_1) ----------------
__global__ __launch_bounds__(256) void k_nh(
    const float* __restrict__ pos_emb, const float* __restrict__ w_1)
{
    extern __shared__ float sm[];
    float* w_s = sm;            // 20000
    float* ins = sm + 20000;    // 32 x 200
    int tid = threadIdx.x;
    int row0 = blockIdx.x * 32;
    for (int i = tid; i < 200*100; i += 256) w_s[i] = w_1[i];
    for (int idx = tid; idx < 32*200; idx += 256) {
        int r = idx / 200, k = idx % 200;
        size_t row = row0 + r;
        int l = (int)(row % Ldim);
        ins[r*200 + k] = (k < 100) ? pos_emb[l*Dn + k] : g_seq[row*Dn + (k-100)];
    }
    __syncthreads();
    int lane = tid & 31, ty = tid >> 5;
    int r0 = ty * 4;
    float acc[4][4] = {};
    for (int k = 0; k < 200; k++) {
        float w0 = w_s[k*100 + lane];
        float w1 = w_s[k*100 + lane + 32];
        float w2 = w_s[k*100 + lane + 64];
        float w3 = (lane < 4) ? w_s[k*100 + lane + 96] : 0.f;
        #pragma unroll
        for (int i = 0; i < 4; i++) {
            float a = ins[(r0+i)*200 + k];
            acc[i][0] = fmaf(a, w0, acc[i][0]);
            acc[i][1] = fmaf(a, w1, acc[i][1]);
            acc[i][2] = fmaf(a, w2, acc[i][2]);
            acc[i][3] = fmaf(a, w3, acc[i][3]);
        }
    }
    #pragma unroll
    for (int i = 0; i < 4; i++) {
        size_t row = row0 + r0 + i;
        #pragma unroll
        for (int q = 0; q < 4; q++) {
            int c = lane + 32*q;
            if (c < 100) g_nh[row*Dn + c] = tanhf(acc[i][q]);
        }
    }
}

// ---------------- K5c: GLU sigmoid, beta, select ----------------
__global__ __launch_bounds__(128) void k_select(
    const float* __restrict__ glu1_w, const float* __restrict__ glu1_b,
    const float* __restrict__ w_2, const float* __restrict__ mask)
{
    int b = blockIdx.x, tid = threadIdx.x;
    __shared__ float w1s[100*100];
    __shared__ float nh_s[Dn], seq_s[Dn], red[128];
    __shared__ float w2s[Dn], hb_s[Dn];
    for (int i = tid; i < 100*100; i += 128) w1s[i] = glu1_w[i];
    if (tid < Dn) { w2s[tid] = w_2[tid]; hb_s[tid] = glu1_b[tid] + g_hsg[b*Dn + tid]; }
    __syncthreads();
    float sel = 0.f;
    for (int l = 0; l < Ldim; l++) {
        if (tid < Dn) {
            nh_s[tid]  = g_nh[((size_t)b*Ldim + l)*Dn + tid];
            seq_s[tid] = g_seq[((size_t)b*Ldim + l)*Dn + tid];
        }
        __syncthreads();
        float contrib = 0.f;
        if (tid < Dn) {
            float t = hb_s[tid];
            for (int c = 0; c < Dn; c++) t = fmaf(nh_s[c], w1s[c*100 + tid], t);
            float sg = 1.f / (1.f + __expf(-t));
            contrib = sg * w2s[tid];
        }
        red[tid] = contrib;
        __syncthreads();
        for (int st = 64; st > 0; st >>= 1) {
            if (tid < st) red[tid] += red[tid + st];
            __syncthreads();
        }
        float beta = red[0] * mask[b*Ldim + l];
        if (tid < Dn) sel += beta * seq_s[tid];
        __syncthreads();
    }
    if (tid < Dn) g_select[b*Dn + tid] = sel;
}

// ---------------- K6a: score = select @ emb[1:]^T (float4), row-max atomics --
__global__ __launch_bounds__(256) void k_score(
    const float* __restrict__ emb, float* __restrict__ out)
{
    extern __shared__ float sm[];
    float* sel_s = sm;            // 32 x 104
    float* emb_s = sm + 32*104;   // 128 x 104
    int n0 = blockIdx.x * 128, b0 = blockIdx.y * 32;
    int tid = threadIdx.x;
    for (int idx = tid; idx < 32*25; idx += 256) {
        int r = idx / 25, c4 = idx % 25;
        float4 v = *(const float4*)(g_select + (b0 + r)*Dn + c4*4);
        *(float4*)(sel_s + r*104 + c4*4) = v;
    }
    for (int idx = tid; idx < 128*25; idx += 256) {
        int r = idx / 25, c4 = idx % 25;
        int n = n0 + r;
        float4 v = make_float4(0.f,0.f,0.f,0.f);
        if (n < NOUT) v = *(const float4*)(emb + (size_t)(n + 1)*Dn + c4*4);
        *(float4*)(emb_s + r*104 + c4*4) = v;
    }
    __syncthreads();
    int lane = tid & 31, ty = tid >> 5;
    int rb = ty * 4;
    float acc[4][4] = {};
    #pragma unroll 5
    for (int k = 0; k < 100; k += 4) {
        float4 e0 = *(const float4*)(emb_s + lane*104 + k);
        float4 e1 = *(const float4*)(emb_s + (lane+32)*104 + k);
        float4 e2 = *(const float4*)(emb_s + (lane+64)*104 + k);
        float4 e3 = *(const float4*)(emb_s + (lane+96)*104 + k);
        #pragma unroll
        for (int i = 0; i < 4; i++) {
            float4 s = *(const float4*)(sel_s + (rb+i)*104 + k);
            acc[i][0] = fmaf(s.x, e0.x, acc[i][0]);
            acc[i][1] = fmaf(s.x, e1.x, acc[i][1]);
            acc[i][2] = fmaf(s.x, e2.x, acc[i][2]);
            acc[i][3] = fmaf(s.x, e3.x, acc[i][3]);
            acc[i][0] = fmaf(s.y, e0.y, acc[i][0]);
            acc[i][1] = fmaf(s.y, e1.y, acc[i][1]);
            acc[i][2] = fmaf(s.y, e2.y, acc[i][2]);
            acc[i][3] = fmaf(s.y, e3.y, acc[i][3]);
            acc[i][0] = fmaf(s.z, e0.z, acc[i][0]);
            acc[i][1] = fmaf(s.z, e1.z, acc[i][1]);
            acc[i][2] = fmaf(s.z, e2.z, acc[i][2]);
            acc[i][3] = fmaf(s.z, e3.z, acc[i][3]);
            acc[i][0] = fmaf(s.w, e0.w, acc[i][0]);
            acc[i][1] = fmaf(s.w, e1.w, acc[i][1]);
            acc[i][2] = fmaf(s.w, e2.w, acc[i][2]);
            acc[i][3] = fmaf(s.w, e3.w, acc[i][3]);
        }
    }
    float rowmax[4] = {-3.0e38f, -3.0e38f, -3.0e38f, -3.0e38f};
    #pragma unroll
    for (int i = 0; i < 4; i++) {
        #pragma unroll
        for (int q = 0; q < 4; q++) {
            int n = n0 + lane + 32*q;
            if (n < NOUT) {
                out[(size_t)(b0 + rb + i)*NOUT + n] = acc[i][q];
                rowmax[i] = fmaxf(rowmax[i], acc[i][q]);
            }
        }
    }
    #pragma unroll
    for (int i = 0; i < 4; i++) {
        float m = rowmax[i];
        #pragma unroll
        for (int o = 16; o > 0; o >>= 1) m = fmaxf(m, __shfl_xor_sync(0xffffffffu, m, o));
        if (lane == 0) atomicMax(&g_rmaxbits[b0 + rb + i], fkey(m));
    }
}

// ---------------- K6b: per-chunk sum of exp ----------------
__global__ __launch_bounds__(256) void k_expsum(const float* __restrict__ out)
{
    int b = blockIdx.y, chunk = blockIdx.x, tid = threadIdx.x;
    int start = chunk * CHUNKSZ;
    int end = start + CHUNKSZ; if (end > NOUT) end = NOUT;
    float m = funkey(g_rmaxbits[b]);
    float s = 0.f;
    for (int n = start + tid; n < end; n += 256)
        s += fexp(out[(size_t)b*NOUT + n] - m);
    __shared__ float red[256];
    red[tid] = s;
    __syncthreads();
    for (int st = 128; st > 0; st >>= 1) {
        if (tid < st) red[tid] += red[tid + st];
        __syncthreads();
    }
    if (tid == 0) g_rpart[b*NCHUNK + chunk] = red[0];
}

// ---------------- K6c: exp + scale ----------------
__global__ __launch_bounds__(256) void k_scale(float* __restrict__ out)
{
    int b = blockIdx.y;
    int n = blockIdx.x * 256 + threadIdx.x;
    if (n < NOUT) {
        float ssum = 0.f;
        #pragma unroll
        for (int j = 0; j < NCHUNK; j++) ssum += g_rpart[b*NCHUNK + j];
        float m = funkey(g_rmaxbits[b]);
        float inv = __fdividef(1.f, ssum);
        size_t idx = (size_t)b*NOUT + n;
        out[idx] = fexp(out[idx] - m) * inv;
    }
}

// ---------------- launch ----------------
extern "C" void kernel_launch(void* const* d_in, const int* in_sizes, int n_in,
                              void* d_out, int out_size)
{
    const int*   alias_inputs = (const int*)  d_in[0];
    const int*   items        = (const int*)  d_in[1];
    const int*   adj          = (const int*)  d_in[2];
    const float* mask_item    = (const float*)d_in[3];
    const int*   seq_features = (const int*)  d_in[4];
    const int*   adj_all      = (const int*)  d_in[5];
    const float* num_w        = (const float*)d_in[6];
    const float* emb          = (const float*)d_in[7];
    const float* pos_emb      = (const float*)d_in[8];
    const float* a0           = (const float*)d_in[9];
    const float* a1           = (const float*)d_in[10];
    const float* a2           = (const float*)d_in[11];
    const float* a3           = (const float*)d_in[12];
    const float* g_w1         = (const float*)d_in[13];
    const float* g_w2         = (const float*)d_in[14];
    const float* g_w3         = (const float*)d_in[15];
    const float* w_1          = (const float*)d_in[16];
    const float* w_2          = (const float*)d_in[17];
    const float* glu1_w       = (const float*)d_in[18];
    const float* glu1_b       = (const float*)d_in[19];
    const float* glu2_w       = (const float*)d_in[20];
    const float* glu2_b       = (const float*)d_in[21];
    float* out = (float*)d_out;

    const int GSMEM = GT_TOT * 4;                  // ~86.3 KB
    const int CSMEM = (20000 + 32*200) * 4;        // ~105.6 KB
    const int SSMEM = (32*104 + 128*104) * 4;      // ~66.6 KB
    cudaFuncSetAttribute(k_global,  cudaFuncAttributeMaxDynamicSharedMemorySize, GSMEM);
    cudaFuncSetAttribute(k_combine, cudaFuncAttributeMaxDynamicSharedMemorySize, CSMEM);
    cudaFuncSetAttribute(k_nh,      cudaFuncAttributeMaxDynamicSharedMemorySize, CSMEM);
    cudaFuncSetAttribute(k_score,   cudaFuncAttributeMaxDynamicSharedMemorySize, SSMEM);

    k_init   <<<1, 256>>>();
    k_local  <<<Bn, 256>>>(items, adj, emb, a0, a1, a2, a3);
    k_sess   <<<Bn, 128>>>(seq_features, mask_item, emb);
    k_global <<<Bn*8, 192, GSMEM>>>(items, adj_all, num_w, emb, g_w1, g_w2);
    k_combine<<<(Bn*Ldim)/32, 256, CSMEM>>>(g_w3);
    k_seqhs  <<<Bn, 128>>>(alias_inputs, mask_item, glu2_w, glu2_b);
    k_nh     <<<(Bn*Ldim)/32, 256, CSMEM>>>(pos_emb, w_1);
    k_select <<<Bn, 128>>>(glu1_w, glu1_b, w_2, mask_item);
    dim3 gs((NOUT + 127)/128, Bn/32);
    k_score  <<<gs, 256, SSMEM>>>(emb, out);
    dim3 ge(NCHUNK, Bn);
    k_expsum <<<ge, 256>>>(out);
    dim3 gn((NOUT + 255)/256, Bn);
    k_scale  <<<gn, 256>>>(out);
}

// round 6
// speedup vs baseline: 1.5100x; 1.0856x over previous
#include <cuda_runtime.h>
#include <math.h>
#include <stdint.h>

#define Bn 256
#define Ldim 64
#define Sn 12
#define Dn 100
#define NUM_NODE 43098
#define NOUT 43097
#define NEGV -9000000000000000.0f
#define NCHUNK 8
#define CHUNKSZ 5388   // ceil(43097/8)

// ---------------- scratch (device globals; no allocation) ----------------
__device__ float g_h[Bn*Ldim*Dn];
__device__ float g_hlocal[Bn*Ldim*Dn];
__device__ float g_sess[Bn*Dn];
__device__ float g_nb[Bn*Ldim*Dn];
__device__ float g_hcomb[Bn*Ldim*Dn];
__device__ float g_seq[Bn*Ldim*Dn];
__device__ float g_nh[Bn*Ldim*Dn];
__device__ float g_hsg[Bn*Dn];
__device__ float g_select[Bn*Dn];
__device__ unsigned g_rmaxbits[Bn];
__device__ float g_rpart[Bn*NCHUNK];

__device__ __forceinline__ unsigned fkey(float f) {
    unsigned u = __float_as_uint(f);
    return (u & 0x80000000u) ? ~u : (u | 0x80000000u);
}
__device__ __forceinline__ float funkey(unsigned k) {
    return (k & 0x80000000u) ? __uint_as_float(k ^ 0x80000000u)
                             : __uint_as_float(~k);
}

__device__ __forceinline__ float fexp(float x) {
    float y = x * 1.44269504088896340736f;
    y = fmaxf(y, -126.0f);
    float t = y + 12582912.0f;
    float i = t - 12582912.0f;
    float f = y - i;
    int ii = (int)i;
    float p = 1.54035303933816e-4f;
    p = fmaf(p, f, 1.33335581464284e-3f);
    p = fmaf(p, f, 9.61812910762848e-3f);
    p = fmaf(p, f, 5.55041086648216e-2f);
    p = fmaf(p, f, 2.40226506959101e-1f);
    p = fmaf(p, f, 6.93147180559945e-1f);
    p = fmaf(p, f, 1.0f);
    return p * __int_as_float((ii + 127) << 23);
}

__device__ __forceinline__ float to_tf32(float x) {
    uint32_t r;
    asm("cvt.rna.tf32.f32 %0, %1;" : "=r"(r) : "f"(x));
    return __uint_as_float(r);
}

// ---------------- K0 ----------------
__global__ void k_init() {
    int t = threadIdx.x;
    if (t < Bn) g_rmaxbits[t] = 0u;
}

// ---------------- K1: local graph attention ----------------
__global__ __launch_bounds__(256) void k_local(
    const int* __restrict__ items, const int* __restrict__ adj,
    const float* __restrict__ emb,
    const float* __restrict__ a0, const float* __restrict__ a1,
    const float* __restrict__ a2, const float* __restrict__ a3)
{
    int b = blockIdx.x;
    __shared__ float hs[Ldim][101];
    __shared__ float alpha[Ldim][Ldim+1];
    __shared__ float As[Dn][4];
    int tid = threadIdx.x;

    for (int i = tid; i < Dn; i += 256) {
        As[i][0] = a0[i]; As[i][1] = a1[i]; As[i][2] = a2[i]; As[i][3] = a3[i];
    }
    for (int idx = tid; idx < Ldim*Dn; idx += 256) {
        int l = idx / Dn, d = idx % Dn;
        float v = emb[(size_t)items[b*Ldim + l]*Dn + d];
        hs[l][d] = v;
        g_h[((size_t)b*Ldim + l)*Dn + d] = v;
    }
    __syncthreads();

    for (int p = tid; p < Ldim*Ldim; p += 256) {
        int i = p / Ldim, j = p % Ldim;
        int a = adj[((size_t)b*Ldim + i)*Ldim + j];
        float val = NEGV;
        if (a >= 1 && a <= 4) {
            float acc = 0.f;
            int k = a - 1;
            for (int d = 0; d < Dn; d++)
                acc += hs[i][d] * hs[j][d] * As[d][k];
            val = acc > 0.f ? acc : 0.2f * acc;
        }
        alpha[i][j] = val;
    }
    __syncthreads();

    int warp = tid >> 5, lane = tid & 31;
    for (int i = warp; i < Ldim; i += 8) {
        float x0 = alpha[i][lane], x1 = alpha[i][lane+32];
        float m = fmaxf(x0, x1);
        #pragma unroll
        for (int o = 16; o > 0; o >>= 1) m = fmaxf(m, __shfl_xor_sync(0xffffffffu, m, o));
        float e0 = __expf(fmaxf(x0 - m, -87.f));
        float e1 = __expf(fmaxf(x1 - m, -87.f));
        float s = e0 + e1;
        #pragma unroll
        for (int o = 16; o > 0; o >>= 1) s += __shfl_xor_sync(0xffffffffu, s, o);
        float inv = 1.f / s;
        alpha[i][lane] = e0 * inv;
        alpha[i][lane+32] = e1 * inv;
    }
    __syncthreads();

    for (int idx = tid; idx < Ldim*Dn; idx += 256) {
        int i = idx / Dn, d = idx % Dn;
        float acc = 0.f;
        for (int j = 0; j < Ldim; j++) acc += alpha[i][j] * hs[j][d];
        g_hlocal[((size_t)b*Ldim + i)*Dn + d] = acc;
    }
}

// ---------------- K2: sess mean ----------------
__global__ __launch_bounds__(128) void k_sess(
    const int* __restrict__ seq_features, const float* __restrict__ mask,
    const float* __restrict__ emb)
{
    int b = blockIdx.x, tid = threadIdx.x;
    if (tid >= Dn) return;
    float acc = 0.f, msum = 0.f;
    for (int l = 0; l < Ldim; l++) {
        float mk = mask[b*Ldim + l];
        acc += emb[(size_t)seq_features[b*Ldim + l]*Dn + tid] * mk;
        msum += mk;
    }
    g_sess[b*Dn + tid] = acc / msum;
}

// ---------------- K3: global neighbor aggregation (tf32 mma, amortized) ----
#define GT_W1   0        // 104*104 = 10816
#define GT_FEAT 10816    // 96*108  = 10368
#define GT_W2   21184    // 104
#define GT_SESS 21288    // 100
#define GT_ALSC 21388    // 96
#define GT_NBR  21484    // 96 ints
#define GT_TOT  21580
__global__ __launch_bounds__(192) void k_global(
    const int* __restrict__ items, const int* __restrict__ adj_all,
    const float* __restrict__ num_w, const float* __restrict__ emb,
    const float* __restrict__ g_w1, const float* __restrict__ g_w2)
{
    extern __shared__ float sm[];
    float* w1s   = sm + GT_W1;
    float* feat  = sm + GT_FEAT;
    float* w2s   = sm + GT_W2;
    float* sesss = sm + GT_SESS;
    float* alsc  = sm + GT_ALSC;
    int*   nbrs  = (int*)(sm + GT_NBR);

    int blk = blockIdx.x;
    int b = blk >> 1;
    int l0 = (blk & 1) * 32;
    int tid = threadIdx.x;
    int lane = tid & 31, warp = tid >> 5;

    // one-time setup: B (tf32 w1), w2, sess
    for (int i = tid; i < 104*104; i += 192) w1s[i] = 0.f;
    if (tid < 104) w2s[tid] = (tid < Dn) ? g_w2[tid] : 0.f;
    if (tid < Dn) sesss[tid] = g_sess[b*Dn + tid];
    __syncthreads();
    for (int i = tid; i < 101*100; i += 192) {
        int k = i / 100, n = i % 100;
        w1s[k*104 + n] = to_tf32(g_w1[i]);
    }
    __syncthreads();

    int g = lane >> 2, tg = lane & 3;

    for (int it = 0; it < 4; it++) {
        int lbase = l0 + it*8;
        if (tid < 96) {
            int l = tid / 12, s = tid % 12;
            int node = items[b*Ldim + lbase + l];
            nbrs[tid] = adj_all[(size_t)node*Sn + s];
            feat[tid*108 + 100] = to_tf32(num_w[(size_t)node*Sn + s]);
            feat[tid*108 + 101] = 0.f;
            feat[tid*108 + 102] = 0.f;
            feat[tid*108 + 103] = 0.f;
        }
        __syncthreads();
        for (int idx = tid; idx < 96*25; idx += 192) {
            int r = idx / 25, c4 = (idx % 25) * 4;
            float4 e = *(const float4*)(emb + (size_t)nbrs[r]*Dn + c4);
            float* dst = feat + r*108 + c4;
            dst[0] = to_tf32(e.x * sesss[c4+0]);
            dst[1] = to_tf32(e.y * sesss[c4+1]);
            dst[2] = to_tf32(e.z * sesss[c4+2]);
            dst[3] = to_tf32(e.w * sesss[c4+3]);
        }
        __syncthreads();

        const float* Ab = feat + warp*16*108;
        float score_a = 0.f, score_b = 0.f;
        #pragma unroll 1
        for (int nt = 0; nt < 13; nt++) {
            float c0 = 0.f, c1 = 0.f, c2 = 0.f, c3 = 0.f;
            #pragma unroll
            for (int kt = 0; kt < 13; kt++) {
                int ak = kt*8;
                uint32_t a0 = __float_as_uint(Ab[ g     *108 + ak + tg    ]);
                uint32_t a1 = __float_as_uint(Ab[(g+8)  *108 + ak + tg    ]);
                uint32_t a2 = __float_as_uint(Ab[ g     *108 + ak + tg + 4]);
                uint32_t a3 = __float_as_uint(Ab[(g+8)  *108 + ak + tg + 4]);
                uint32_t b0 = __float_as_uint(w1s[(ak + tg    )*104 + nt*8 + g]);
                uint32_t b1 = __float_as_uint(w1s[(ak + tg + 4)*104 + nt*8 + g]);
                asm volatile(
                    "mma.sync.aligned.m16n8k8.row.col.f32.tf32.tf32.f32 "
                    "{%0,%1,%2,%3}, {%4,%5,%6,%7}, {%8,%9}, {%0,%1,%2,%3};"
                    : "+f"(c0), "+f"(c1), "+f"(c2), "+f"(c3)
                    : "r"(a0), "r"(a1), "r"(a2), "r"(a3), "r"(b0), "r"(b1));
            }
            int j0 = nt*8 + tg*2;
            float w20 = w2s[j0], w21 = w2s[j0+1];
            float v0 = c0 > 0.f ? c0 : 0.2f*c0;
            float v1 = c1 > 0.f ? c1 : 0.2f*c1;
            float v2 = c2 > 0.f ? c2 : 0.2f*c2;
            float v3 = c3 > 0.f ? c3 : 0.2f*c3;
            score_a = fmaf(v0, w20, fmaf(v1, w21, score_a));
            score_b = fmaf(v2, w20, fmaf(v3, w21, score_b));
        }
        score_a += __shfl_xor_sync(0xffffffffu, score_a, 1);
        score_a += __shfl_xor_sync(0xffffffffu, score_a, 2);
        score_b += __shfl_xor_sync(0xffffffffu, score_b, 1);
        score_b += __shfl_xor_sync(0xffffffffu, score_b, 2);
        if (tg == 0) {
            alsc[warp*16 + g]     = score_a;
            alsc[warp*16 + g + 8] = score_b;
        }
        __syncthreads();

        if (tid < 8) {
            float* a = alsc + tid*12;
            float m = a[0];
            #pragma unroll
            for (int s = 1; s < Sn; s++) m = fmaxf(m, a[s]);
            float ssum = 0.f;
            float e[Sn];
            #pragma unroll
            for (int s = 0; s < Sn; s++) { e[s] = __expf(a[s] - m); ssum += e[s]; }
            float inv = 1.f / ssum;
            #pragma unroll
            for (int s = 0; s < Sn; s++) a[s] = e[s] * inv;
        }
        __syncthreads();

        for (int idx = tid; idx < 800; idx += 192) {
            int l = idx / 100, c = idx % 100;
            float acc = 0.f;
            #pragma unroll
            for (int s = 0; s < Sn; s++)
                acc = fmaf(alsc[l*12 + s], emb[(size_t)nbrs[l*12 + s]*Dn + c], acc);
            g_nb[((size_t)b*Ldim + lbase + l)*Dn + c] = acc;
        }
        __syncthreads();
    }
}

// ---------------- K4: h_combine = relu([h,nb]@g_w3) + h_local ----------------
__global__ __launch_bounds__(256) void k_combine(const float* __restrict__ g_w3)
{
    extern __shared__ float sm[];
    float* w_s = sm;            // 20000
    float* ins = sm + 20000;    // 32 x 200
    int tid = threadIdx.x;
    int row0 = blockIdx.x * 32;
    for (int i = tid; i < 200*100; i += 256) w_s[i] = g_w3[i];
    for (int idx = tid; idx < 32*200; idx += 256) {
        int r = idx / 200, k = idx % 200;
        size_t row = row0 + r;
        ins[r*200 + k] = (k < 100) ? g_h[row*Dn + k] : g_nb[row*Dn + (k-100)];
    }
    __syncthreads();
    int lane = tid & 31, ty = tid >> 5;
    int r0 = ty * 4;
    float acc[4][4] = {};
    for (int k = 0; k < 200; k++) {
        float w0 = w_s[k*100 + lane];
        float w1 = w_s[k*100 + lane + 32];
        float w2 = w_s[k*100 + lane + 64];
        float w3 = (lane < 4) ? w_s[k*100 + lane + 96] : 0.f;
        #pragma unroll
        for (int i = 0; i < 4; i++) {
            float a = ins[(r0+i)*200 + k];
            acc[i][0] = fmaf(a, w0, acc[i][0]);
            acc[i][1] = fmaf(a, w1, acc[i][1]);
            acc[i][2] = fmaf(a, w2, acc[i][2]);
            acc[i][3] = fmaf(a, w3, acc[i][3]);
        }
    }
    #pragma unroll
    for (int i = 0; i < 4; i++) {
        size_t row = row0 + r0 + i;
        #pragma unroll
        for (int q = 0; q < 4; q++) {
            int c = lane + 32*q;
            if (c < 100)
                g_hcomb[row*Dn + c] = g_hlocal[row*Dn + c] + fmaxf(acc[i][q], 0.f);
        }
    }
}

// ---------------- K5a: seq gather, hs, hsg ----------------
__global__ __launch_bounds__(128) void k_seqhs(
    const int* __restrict__ alias, const float* __restrict__ mask,
    const float* __restrict__ glu2_w, const float* __restrict__ glu2_b)
{
    int b = blockIdx.x, tid = threadIdx.x;
    __shared__ float hs_s[Dn];
    __shared__ int alias_s[Ldim];
    __shared__ float mk_s[Ldim];
    if (tid < Ldim) { alias_s[tid] = alias[b*Ldim + tid]; mk_s[tid] = mask[b*Ldim + tid]; }
    __syncthreads();
    if (tid < Dn) {
        float acc = 0.f, msum = 0.f;
        for (int l = 0; l < Ldim; l++) {
            float v = g_hcomb[((size_t)b*Ldim + alias_s[l])*Dn + tid];
            g_seq[((size_t)b*Ldim + l)*Dn + tid] = v;
            acc += v * mk_s[l];
            msum += mk_s[l];
        }
        hs_s[tid] = acc / msum;
    }
    __syncthreads();
    if (tid < Dn) {
        float t = glu2_b[tid];
        for (int c = 0; c < Dn; c++) t = fmaf(hs_s[c], __ldg(&glu2_w[c*Dn + tid]), t);
        g_hsg[b*Dn + tid] = t;
    }
}

// ---------------- K5b: nh = tanh([pe, seq]@w_1) ----------------
__global__ __launch_bounds__(256) void k_nh(
    const float* __restrict__ pos_emb, const float* __restrict__ w_1)
{
    extern __shared__ float sm[];
    float* w_s = sm;            // 20000
    float* ins = sm + 20000;    // 32 x 200
    int tid = threadIdx.x;
    int row0 = blockIdx.x * 32;
    for (int i = tid; i < 200*100; i += 256) w_s[i] = w_1[i];
    for (int idx = tid; idx < 32*200; idx += 256) {
        int r = idx / 200, k = idx % 200;
        size_t row = row0 + r;
        int l = (int)(row % Ldim);
        ins[r*200 + k] = (k < 100) ? pos_emb[l*Dn + k] : g_seq[row*Dn + (k-100)];
    }
    __syncthreads();
    int lane = tid & 31, ty = tid >> 5;
    int r0 = ty * 4;
    float acc[4][4] = {};
    for (int k = 0; k < 200; k++) {
        float w0 = w_s[k*100 + lane];
        float w1 = w_s[k*100 + lane + 32];
        float w2 = w_s[k*100 + lane + 64];
        float w3 = (lane < 4) ? w_s[k*100 + lane + 96] : 0.f;
        #pragma unroll
        for (int i = 0; i < 4; i++) {
            float a = ins[(r0+i)*200 + k];
            acc[i][0] = fmaf(a, w0, acc[i][0]);
            acc[i][1] = fmaf(a, w1, acc[i][1]);
            acc[i][2] = fmaf(a, w2, acc[i][2]);
            acc[i][3] = fmaf(a, w3, acc[i][3]);
        }
    }
    #pragma unroll
    for (int i = 0; i < 4; i++) {
        size_t row = row0 + r0 + i;
        #pragma unroll
        for (int q = 0; q < 4; q++) {
            int c = lane + 32*q;
            if (c < 100) g_nh[row*Dn + c] = tanhf(acc[i][q]);
        }
    }
}

// ---------------- K5c: GLU sigmoid, beta, select ----------------
__global__ __launch_bounds__(128) void k_select(
    const float* __restrict__ glu1_w, const float* __restrict__ glu1_b,
    const float* __restrict__ w_2, const float* __restrict__ mask)
{
    int b = blockIdx.x, tid = threadIdx.x;
    __shared__ float w1s[100*100];
    __shared__ float nh_s[Dn], seq_s[Dn], red[128];
    __shared__ float w2s[Dn], hb_s[Dn];
    for (int i = tid; i < 100*100; i += 128) w1s[i] = glu1_w[i];
    if (tid < Dn) { w2s[tid] = w_2[tid]; hb_s[tid] = glu1_b[tid] + g_hsg[b*Dn + tid]; }
    __syncthreads();
    float sel = 0.f;
    for (int l = 0; l < Ldim; l++) {
        if (tid < Dn) {
            nh_s[tid]  = g_nh[((size_t)b*Ldim + l)*Dn + tid];
            seq_s[tid] = g_seq[((size_t)b*Ldim + l)*Dn + tid];
        }
        __syncthreads();
        float contrib = 0.f;
        if (tid < Dn) {
            float t = hb_s[tid];
            for (int c = 0; c < Dn; c++) t = fmaf(nh_s[c], w1s[c*100 + tid], t);
            float sg = 1.f / (1.f + __expf(-t));
            contrib = sg * w2s[tid];
        }
        red[tid] = contrib;
        __syncthreads();
        for (int st = 64; st > 0; st >>= 1) {
            if (tid < st) red[tid] += red[tid + st];
            __syncthreads();
        }
        float beta = red[0] * mask[b*Ldim + l];
        if (tid < Dn) sel += beta * seq_s[tid];
        __syncthreads();
    }
    if (tid < Dn) g_select[b*Dn + tid] = sel;
}

// ---------------- K6a: score = select @ emb[1:]^T (tf32 mma) ----------------
// smem: sel_s [32][104] tf32 row-major; embT [104][137] tf32 = B[k][n]
#define SC_EMBT 3328          // after sel_s 32*104
#define SC_TOT  (3328 + 104*137)   // 17576 floats
__global__ __launch_bounds__(256) void k_score(
    const float* __restrict__ emb, float* __restrict__ out)
{
    extern __shared__ float sm[];
    float* sel_s = sm;
    float* embT  = sm + SC_EMBT;
    int n0 = blockIdx.x * 128, b0 = blockIdx.y * 32;
    int tid = threadIdx.x;
    int lane = tid & 31, warp = tid >> 5;

    for (int idx = tid; idx < 32*25; idx += 256) {
        int r = idx / 25, c4 = (idx % 25) * 4;
        float4 v = *(const float4*)(g_select + (b0 + r)*Dn + c4);
        float* d = sel_s + r*104 + c4;
        d[0] = to_tf32(v.x); d[1] = to_tf32(v.y);
        d[2] = to_tf32(v.z); d[3] = to_tf32(v.w);
    }
    if (tid < 32) {
        float* d = sel_s + tid*104 + 100;
        d[0] = 0.f; d[1] = 0.f; d[2] = 0.f; d[3] = 0.f;
    }
    for (int idx = tid; idx < 128*25; idx += 256) {
        int r = idx / 25, c4 = (idx % 25) * 4;
        int n = n0 + r;
        float4 v = make_float4(0.f,0.f,0.f,0.f);
        if (n < NOUT) v = *(const float4*)(emb + (size_t)(n + 1)*Dn + c4);
        embT[(c4+0)*137 + r] = to_tf32(v.x);
        embT[(c4+1)*137 + r] = to_tf32(v.y);
        embT[(c4+2)*137 + r] = to_tf32(v.z);
        embT[(c4+3)*137 + r] = to_tf32(v.w);
    }
    for (int idx = tid; idx < 4*128; idx += 256) {
        int k = 100 + idx / 128, n = idx % 128;
        embT[k*137 + n] = 0.f;
    }
    __syncthreads();

    int g = lane >> 2, tg = lane & 3;
    int mt = warp & 1;           // m-tile (b rows 0-15 / 16-31)
    int nb = warp >> 1;          // 4 n-tiles each
    const float* Arow = sel_s + mt*16*104;

    float acc[4][4];
    #pragma unroll
    for (int j = 0; j < 4; j++)
        #pragma unroll
        for (int q = 0; q < 4; q++) acc[j][q] = 0.f;

    #pragma unroll 1
    for (int kt = 0; kt < 13; kt++) {
        int ak = kt*8;
        uint32_t a0 = __float_as_uint(Arow[ g   *104 + ak + tg    ]);
        uint32_t a1 = __float_as_uint(Arow[(g+8)*104 + ak + tg    ]);
        uint32_t a2 = __float_as_uint(Arow[ g   *104 + ak + tg + 4]);
        uint32_t a3 = __float_as_uint(Arow[(g+8)*104 + ak + tg + 4]);
        #pragma unroll
        for (int j = 0; j < 4; j++) {
            int nt = nb*4 + j;
            uint32_t bb0 = __float_as_uint(embT[(ak + tg    )*137 + nt*8 + g]);
            uint32_t bb1 = __float_as_uint(embT[(ak + tg + 4)*137 + nt*8 + g]);
            asm volatile(
                "mma.sync.aligned.m16n8k8.row.col.f32.tf32.tf32.f32 "
                "{%0,%1,%2,%3}, {%4,%5,%6,%7}, {%8,%9}, {%0,%1,%2,%3};"
                : "+f"(acc[j][0]), "+f"(acc[j][1]), "+f"(acc[j][2]), "+f"(acc[j][3])
                : "r"(a0), "r"(a1), "r"(a2), "r"(a3), "r"(bb0), "r"(bb1));
        }
    }

    int row_lo = b0 + mt*16 + g;
    int row_hi = row_lo + 8;
    float rmax_lo = -3.0e38f, rmax_hi = -3.0e38f;
    #pragma unroll
    for (int j = 0; j < 4; j++) {
        int nt = nb*4 + j;
        int ncol = n0 + nt*8 + tg*2;
        if (ncol < NOUT) {
            out[(size_t)row_lo*NOUT + ncol] = acc[j][0];
            out[(size_t)row_hi*NOUT + ncol] = acc[j][2];
            rmax_lo = fmaxf(rmax_lo, acc[j][0]);
            rmax_hi = fmaxf(rmax_hi, acc[j][2]);
        }
        if (ncol + 1 < NOUT) {
            out[(size_t)row_lo*NOUT + ncol + 1] = acc[j][1];
            out[(size_t)row_hi*NOUT + ncol + 1] = acc[j][3];
            rmax_lo = fmaxf(rmax_lo, acc[j][1]);
            rmax_hi = fmaxf(rmax_hi, acc[j][3]);
        }
    }
    rmax_lo = fmaxf(rmax_lo, __shfl_xor_sync(0xffffffffu, rmax_lo, 1));
    rmax_lo = fmaxf(rmax_lo, __shfl_xor_sync(0xffffffffu, rmax_lo, 2));
    rmax_hi = fmaxf(rmax_hi, __shfl_xor_sync(0xffffffffu, rmax_hi, 1));
    rmax_hi = fmaxf(rmax_hi, __shfl_xor_sync(0xffffffffu, rmax_hi, 2));
    if (tg == 0) {
        atomicMax(&g_rmaxbits[row_lo], fkey(rmax_lo));
        atomicMax(&g_rmaxbits[row_hi], fkey(rmax_hi));
    }
}

// ---------------- K6b: per-chunk sum of exp ----------------
__global__ __launch_bounds__(256) void k_expsum(const float* __restrict__ out)
{
    int b = blockIdx.y, chunk = blockIdx.x, tid = threadIdx.x;
    int start = chunk * CHUNKSZ;
    int end = start + CHUNKSZ; if (end > NOUT) end = NOUT;
    float m = funkey(g_rmaxbits[b]);
    float s = 0.f;
    for (int n = start + tid; n < end; n += 256)
        s += fexp(out[(size_t)b*NOUT + n] - m);
    __shared__ float red[256];
    red[tid] = s;
    __syncthreads();
    for (int st = 128; st > 0; st >>= 1) {
        if (tid < st) red[tid] += red[tid + st];
        __syncthreads();
    }
    if (tid == 0) g_rpart[b*NCHUNK + chunk] = red[0];
}

// ---------------- K6c: exp + scale ----------------
__global__ __launch_bounds__(256) void k_scale(float* __restrict__ out)
{
    int b = blockIdx.y;
    int n = blockIdx.x * 256 + threadIdx.x;
    if (n < NOUT) {
        float ssum = 0.f;
        #pragma unroll
        for (int j = 0; j < NCHUNK; j++) ssum += g_rpart[b*NCHUNK + j];
        float m = funkey(g_rmaxbits[b]);
        float inv = __fdividef(1.f, ssum);
        size_t idx = (size_t)b*NOUT + n;
        out[idx] = fexp(out[idx] - m) * inv;
    }
}

// ---------------- launch ----------------
extern "C" void kernel_launch(void* const* d_in, const int* in_sizes, int n_in,
                              void* d_out, int out_size)
{
    const int*   alias_inputs = (const int*)  d_in[0];
    const int*   items        = (const int*)  d_in[1];
    const int*   adj          = (const int*)  d_in[2];
    const float* mask_item    = (const float*)d_in[3];
    const int*   seq_features = (const int*)  d_in[4];
    const int*   adj_all      = (const int*)  d_in[5];
    const float* num_w        = (const float*)d_in[6];
    const float* emb          = (const float*)d_in[7];
    const float* pos_emb      = (const float*)d_in[8];
    const float* a0           = (const float*)d_in[9];
    const float* a1           = (const float*)d_in[10];
    const float* a2           = (const float*)d_in[11];
    const float* a3           = (const float*)d_in[12];
    const float* g_w1         = (const float*)d_in[13];
    const float* g_w2         = (const float*)d_in[14];
    const float* g_w3         = (const float*)d_in[15];
    const float* w_1          = (const float*)d_in[16];
    const float* w_2          = (const float*)d_in[17];
    const float* glu1_w       = (const float*)d_in[18];
    const float* glu1_b       = (const float*)d_in[19];
    const float* glu2_w       = (const float*)d_in[20];
    const float* glu2_b       = (const float*)d_in[21];
    float* out = (float*)d_out;

    const int GSMEM = GT_TOT * 4;                  // ~86.3 KB
    const int CSMEM = (20000 + 32*200) * 4;        // ~105.6 KB
    const int SSMEM = SC_TOT * 4;                  // ~70.3 KB
    cudaFuncSetAttribute(k_global,  cudaFuncAttributeMaxDynamicSharedMemorySize, GSMEM);
    cudaFuncSetAttribute(k_combine, cudaFuncAttributeMaxDynamicSharedMemorySize, CSMEM);
    cudaFuncSetAttribute(k_nh,      cudaFuncAttributeMaxDynamicSharedMemorySize, CSMEM);
    cudaFuncSetAttribute(k_score,   cudaFuncAttributeMaxDynamicSharedMemorySize, SSMEM);

    k_init   <<<1, 256>>>();
    k_local  <<<Bn, 256>>>(items, adj, emb, a0, a1, a2, a3);
    k_sess   <<<Bn, 128>>>(seq_features, mask_item, emb);
    k_global <<<Bn*2, 192, GSMEM>>>(items, adj_all, num_w, emb, g_w1, g_w2);
    k_combine<<<(Bn*Ldim)/32, 256, CSMEM>>>(g_w3);
    k_seqhs  <<<Bn, 128>>>(alias_inputs, mask_item, glu2_w, glu2_b);
    k_nh     <<<(Bn*Ldim)/32, 256, CSMEM>>>(pos_emb, w_1);
    k_select <<<Bn, 128>>>(glu1_w, glu1_b, w_2, mask_item);
    dim3 gs((NOUT + 127)/128, Bn/32);
    k_score  <<<gs, 256, SSMEM>>>(emb, out);
    dim3 ge(NCHUNK, Bn);
    k_expsum <<<ge, 256>>>(out);
    dim3 gn((NOUT + 255)/256, Bn);
    k_scale  <<<gn, 256>>>(out);
}

// round 8
// speedup vs baseline: 1.7554x; 1.1625x over previous
#include <cuda_runtime.h>
#include <math.h>
#include <stdint.h>

#define Bn 256
#define Ldim 64
#define Sn 12
#define Dn 100
#define NUM_NODE 43098
#define NOUT 43097
#define NEGV -9000000000000000.0f
#define NCHUNK 8
#define CHUNKSZ 5388   // ceil(43097/8)

// ---------------- scratch (device globals; no allocation) ----------------
__device__ float g_h[Bn*Ldim*Dn];
__device__ float g_hlocal[Bn*Ldim*Dn];
__device__ float g_sess[Bn*Dn];
__device__ float g_nb[Bn*Ldim*Dn];
__device__ float g_hcomb[Bn*Ldim*Dn];
__device__ float g_seq[Bn*Ldim*Dn];
__device__ float g_hsg[Bn*Dn];
__device__ float g_selpart[2*Bn*Dn];
__device__ unsigned g_rmaxbits[Bn];
__device__ float g_rpart[Bn*NCHUNK];

__device__ __forceinline__ unsigned fkey(float f) {
    unsigned u = __float_as_uint(f);
    return (u & 0x80000000u) ? ~u : (u | 0x80000000u);
}
__device__ __forceinline__ float funkey(unsigned k) {
    return (k & 0x80000000u) ? __uint_as_float(k ^ 0x80000000u)
                             : __uint_as_float(~k);
}

__device__ __forceinline__ float fexp(float x) {
    float y = x * 1.44269504088896340736f;
    y = fmaxf(y, -126.0f);
    float t = y + 12582912.0f;
    float i = t - 12582912.0f;
    float f = y - i;
    int ii = (int)i;
    float p = 1.54035303933816e-4f;
    p = fmaf(p, f, 1.33335581464284e-3f);
    p = fmaf(p, f, 9.61812910762848e-3f);
    p = fmaf(p, f, 5.55041086648216e-2f);
    p = fmaf(p, f, 2.40226506959101e-1f);
    p = fmaf(p, f, 6.93147180559945e-1f);
    p = fmaf(p, f, 1.0f);
    return p * __int_as_float((ii + 127) << 23);
}

__device__ __forceinline__ float to_tf32(float x) {
    uint32_t r;
    asm("cvt.rna.tf32.f32 %0, %1;" : "=r"(r) : "f"(x));
    return __uint_as_float(r);
}

// ---------------- K0 ----------------
__global__ void k_init() {
    int t = threadIdx.x;
    if (t < Bn) g_rmaxbits[t] = 0u;
}

// ---------------- K1: local graph attention ----------------
__global__ __launch_bounds__(256) void k_local(
    const int* __restrict__ items, const int* __restrict__ adj,
    const float* __restrict__ emb,
    const float* __restrict__ a0, const float* __restrict__ a1,
    const float* __restrict__ a2, const float* __restrict__ a3)
{
    int b = blockIdx.x;
    __shared__ float hs[Ldim][101];
    __shared__ float alpha[Ldim][Ldim+1];
    __shared__ float As[Dn][4];
    int tid = threadIdx.x;

    for (int i = tid; i < Dn; i += 256) {
        As[i][0] = a0[i]; As[i][1] = a1[i]; As[i][2] = a2[i]; As[i][3] = a3[i];
    }
    for (int idx = tid; idx < Ldim*Dn; idx += 256) {
        int l = idx / Dn, d = idx % Dn;
        float v = emb[(size_t)items[b*Ldim + l]*Dn + d];
        hs[l][d] = v;
        g_h[((size_t)b*Ldim + l)*Dn + d] = v;
    }
    __syncthreads();

    for (int p = tid; p < Ldim*Ldim; p += 256) {
        int i = p / Ldim, j = p % Ldim;
        int a = adj[((size_t)b*Ldim + i)*Ldim + j];
        float val = NEGV;
        if (a >= 1 && a <= 4) {
            float acc = 0.f;
            int k = a - 1;
            for (int d = 0; d < Dn; d++)
                acc += hs[i][d] * hs[j][d] * As[d][k];
            val = acc > 0.f ? acc : 0.2f * acc;
        }
        alpha[i][j] = val;
    }
    __syncthreads();

    int warp = tid >> 5, lane = tid & 31;
    for (int i = warp; i < Ldim; i += 8) {
        float x0 = alpha[i][lane], x1 = alpha[i][lane+32];
        float m = fmaxf(x0, x1);
        #pragma unroll
        for (int o = 16; o > 0; o >>= 1) m = fmaxf(m, __shfl_xor_sync(0xffffffffu, m, o));
        float e0 = __expf(fmaxf(x0 - m, -87.f));
        float e1 = __expf(fmaxf(x1 - m, -87.f));
        float s = e0 + e1;
        #pragma unroll
        for (int o = 16; o > 0; o >>= 1) s += __shfl_xor_sync(0xffffffffu, s, o);
        float inv = 1.f / s;
        alpha[i][lane] = e0 * inv;
        alpha[i][lane+32] = e1 * inv;
    }
    __syncthreads();

    for (int idx = tid; idx < Ldim*Dn; idx += 256) {
        int i = idx / Dn, d = idx % Dn;
        float acc = 0.f;
        for (int j = 0; j < Ldim; j++) acc += alpha[i][j] * hs[j][d];
        g_hlocal[((size_t)b*Ldim + i)*Dn + d] = acc;
    }
}

// ---------------- K2: sess mean ----------------
__global__ __launch_bounds__(128) void k_sess(
    const int* __restrict__ seq_features, const float* __restrict__ mask,
    const float* __restrict__ emb)
{
    int b = blockIdx.x, tid = threadIdx.x;
    if (tid >= Dn) return;
    float acc = 0.f, msum = 0.f;
    for (int l = 0; l < Ldim; l++) {
        float mk = mask[b*Ldim + l];
        acc += emb[(size_t)seq_features[b*Ldim + l]*Dn + tid] * mk;
        msum += mk;
    }
    g_sess[b*Dn + tid] = acc / msum;
}

// ---------------- K3: global neighbor aggregation (tf32 mma, 8 warps) ------
#define GT_W1   0        // 104*104 = 10816
#define GT_FEAT 10816    // 96*108  = 10368
#define GT_W2   21184    // 104
#define GT_SESS 21288    // 100
#define GT_ALSC 21388    // 96
#define GT_NBR  21484    // 96 ints
#define GT_TOT  21580
__global__ __launch_bounds__(256) void k_global(
    const int* __restrict__ items, const int* __restrict__ adj_all,
    const float* __restrict__ num_w, const float* __restrict__ emb,
    const float* __restrict__ g_w1, const float* __restrict__ g_w2)
{
    extern __shared__ float sm[];
    float* w1s   = sm + GT_W1;
    float* feat  = sm + GT_FEAT;
    float* w2s   = sm + GT_W2;
    float* sesss = sm + GT_SESS;
    float* alsc  = sm + GT_ALSC;
    int*   nbrs  = (int*)(sm + GT_NBR);

    int blk = blockIdx.x;
    int b = blk >> 1;
    int l0 = (blk & 1) * 32;
    int tid = threadIdx.x;
    int lane = tid & 31, warp = tid >> 5;

    for (int i = tid; i < 104*104; i += 256) w1s[i] = 0.f;
    if (tid < 104) w2s[tid] = (tid < Dn) ? g_w2[tid] : 0.f;
    if (tid < Dn) sesss[tid] = g_sess[b*Dn + tid];
    __syncthreads();
    for (int i = tid; i < 101*100; i += 256) {
        int k = i / 100, n = i % 100;
        w1s[k*104 + n] = to_tf32(g_w1[i]);
    }
    __syncthreads();

    int g = lane >> 2, tg = lane & 3;

    for (int it = 0; it < 4; it++) {
        int lbase = l0 + it*8;
        if (tid < 96) {
            int l = tid / 12, s = tid % 12;
            int node = items[b*Ldim + lbase + l];
            nbrs[tid] = adj_all[(size_t)node*Sn + s];
            feat[tid*108 + 100] = to_tf32(num_w[(size_t)node*Sn + s]);
            feat[tid*108 + 101] = 0.f;
            feat[tid*108 + 102] = 0.f;
            feat[tid*108 + 103] = 0.f;
        }
        __syncthreads();
        for (int idx = tid; idx < 96*25; idx += 256) {
            int r = idx / 25, c4 = (idx % 25) * 4;
            float4 e = *(const float4*)(emb + (size_t)nbrs[r]*Dn + c4);
            float* dst = feat + r*108 + c4;
            dst[0] = to_tf32(e.x * sesss[c4+0]);
            dst[1] = to_tf32(e.y * sesss[c4+1]);
            dst[2] = to_tf32(e.z * sesss[c4+2]);
            dst[3] = to_tf32(e.w * sesss[c4+3]);
        }
        __syncthreads();

        if (warp < 6) {
            const float* Ab = feat + warp*16*108;
            float score_a = 0.f, score_b = 0.f;
            #pragma unroll 1
            for (int nt = 0; nt < 13; nt++) {
                float c0 = 0.f, c1 = 0.f, c2 = 0.f, c3 = 0.f;
                #pragma unroll
                for (int kt = 0; kt < 13; kt++) {
                    int ak = kt*8;
                    uint32_t a0 = __float_as_uint(Ab[ g   *108 + ak + tg    ]);
                    uint32_t a1 = __float_as_uint(Ab[(g+8)*108 + ak + tg    ]);
                    uint32_t a2 = __float_as_uint(Ab[ g   *108 + ak + tg + 4]);
                    uint32_t a3 = __float_as_uint(Ab[(g+8)*108 + ak + tg + 4]);
                    uint32_t b0 = __float_as_uint(w1s[(ak + tg    )*104 + nt*8 + g]);
                    uint32_t b1 = __float_as_uint(w1s[(ak + tg + 4)*104 + nt*8 + g]);
                    asm volatile(
                        "mma.sync.aligned.m16n8k8.row.col.f32.tf32.tf32.f32 "
                        "{%0,%1,%2,%3}, {%4,%5,%6,%7}, {%8,%9}, {%0,%1,%2,%3};"
                        : "+f"(c0), "+f"(c1), "+f"(c2), "+f"(c3)
                        : "r"(a0), "r"(a1), "r"(a2), "r"(a3), "r"(b0), "r"(b1));
                }
                int j0 = nt*8 + tg*2;
                float w20 = w2s[j0], w21 = w2s[j0+1];
                float v0 = c0 > 0.f ? c0 : 0.2f*c0;
                float v1 = c1 > 0.f ? c1 : 0.2f*c1;
                float v2 = c2 > 0.f ? c2 : 0.2f*c2;
                float v3 = c3 > 0.f ? c3 : 0.2f*c3;
                score_a = fmaf(v0, w20, fmaf(v1, w21, score_a));
                score_b = fmaf(v2, w20, fmaf(v3, w21, score_b));
            }
            score_a += __shfl_xor_sync(0xffffffffu, score_a, 1);
            score_a += __shfl_xor_sync(0xffffffffu, score_a, 2);
            score_b += __shfl_xor_sync(0xffffffffu, score_b, 1);
            score_b += __shfl_xor_sync(0xffffffffu, score_b, 2);
            if (tg == 0) {
                alsc[warp*16 + g]     = score_a;
                alsc[warp*16 + g + 8] = score_b;
            }
        }
        __syncthreads();

        if (tid < 8) {
            float* a = alsc + tid*12;
            float m = a[0];
            #pragma unroll
            for (int s = 1; s < Sn; s++) m = fmaxf(m, a[s]);
            float ssum = 0.f;
            float e[Sn];
            #pragma unroll
            for (int s = 0; s < Sn; s++) { e[s] = __expf(a[s] - m); ssum += e[s]; }
            float inv = 1.f / ssum;
            #pragma unroll
            for (int s = 0; s < Sn; s++) a[s] = e[s] * inv;
        }
        __syncthreads();

        for (int idx = tid; idx < 800; idx += 256) {
            int l = idx / 100, c = idx % 100;
            float acc = 0.f;
            #pragma unroll
            for (int s = 0; s < Sn; s++)
                acc = fmaf(alsc[l*12 + s], emb[(size_t)nbrs[l*12 + s]*Dn + c], acc);
            g_nb[((size_t)b*Ldim + lbase + l)*Dn + c] = acc;
        }
        __syncthreads();
    }
}

// ---------------- K4: h_combine = relu([h,nb]@g_w3) + h_local ----------------
__global__ __launch_bounds__(256) void k_combine(const float* __restrict__ g_w3)
{
    extern __shared__ float sm[];
    float* w_s = sm;            // 20000
    float* ins = sm + 20000;    // 32 x 200
    int tid = threadIdx.x;
    int row0 = blockIdx.x * 32;
    for (int i = tid; i < 200*100; i += 256) w_s[i] = g_w3[i];
    for (int idx = tid; idx < 32*200; idx += 256) {
        int r = idx / 200, k = idx % 200;
        size_t row = row0 + r;
        ins[r*200 + k] = (k < 100) ? g_h[row*Dn + k] : g_nb[row*Dn + (k-100)];
    }
    __syncthreads();
    int lane = tid & 31, ty = tid >> 5;
    int r0 = ty * 4;
    float acc[4][4] = {};
    for (int k = 0; k < 200; k++) {
        float w0 = w_s[k*100 + lane];
        float w1 = w_s[k*100 + lane + 32];
        float w2 = w_s[k*100 + lane + 64];
        float w3 = (lane < 4) ? w_s[k*100 + lane + 96] : 0.f;
        #pragma unroll
        for (int i = 0; i < 4; i++) {
            float a = ins[(r0+i)*200 + k];
            acc[i][0] = fmaf(a, w0, acc[i][0]);
            acc[i][1] = fmaf(a, w1, acc[i][1]);
            acc[i][2] = fmaf(a, w2, acc[i][2]);
            acc[i][3] = fmaf(a, w3, acc[i][3]);
        }
    }
    #pragma unroll
    for (int i = 0; i < 4; i++) {
        size_t row = row0 + r0 + i;
        #pragma unroll
        for (int q = 0; q < 4; q++) {
            int c = lane + 32*q;
            if (c < 100)
                g_hcomb[row*Dn + c] = g_hlocal[row*Dn + c] + fmaxf(acc[i][q], 0.f);
        }
    }
}

// ---------------- K5a: seq gather, hs, hsg ----------------
__global__ __launch_bounds__(128) void k_seqhs(
    const int* __restrict__ alias, const float* __restrict__ mask,
    const float* __restrict__ glu2_w, const float* __restrict__ glu2_b)
{
    int b = blockIdx.x, tid = threadIdx.x;
    __shared__ float hs_s[Dn];
    __shared__ int alias_s[Ldim];
    __shared__ float mk_s[Ldim];
    if (tid < Ldim) { alias_s[tid] = alias[b*Ldim + tid]; mk_s[tid] = mask[b*Ldim + tid]; }
    __syncthreads();
    if (tid < Dn) {
        float acc = 0.f, msum = 0.f;
        for (int l = 0; l < Ldim; l++) {
            float v = g_hcomb[((size_t)b*Ldim + alias_s[l])*Dn + tid];
            g_seq[((size_t)b*Ldim + l)*Dn + tid] = v;
            acc += v * mk_s[l];
            msum += mk_s[l];
        }
        hs_s[tid] = acc / msum;
    }
    __syncthreads();
    if (tid < Dn) {
        float t = glu2_b[tid];
        for (int c = 0; c < Dn; c++) t = fmaf(hs_s[c], __ldg(&glu2_w[c*Dn + tid]), t);
        g_hsg[b*Dn + tid] = t;
    }
}

// ---------------- K5b: fused nh + GLU + select partial ----------------
// smem: w_s[20000] (w_1 then glu1_w), ins[32*200], hb[100], w2[100], beta[32]
#define NH_TOT (20000 + 6400 + 100 + 100 + 32)
__global__ __launch_bounds__(256) void k_nhsel(
    const float* __restrict__ pos_emb, const float* __restrict__ w_1,
    const float* __restrict__ glu1_w, const float* __restrict__ glu1_b,
    const float* __restrict__ w_2, const float* __restrict__ mask)
{
    extern __shared__ float sm[];
    float* w_s   = sm;             // 20000
    float* ins   = sm + 20000;     // 32 x 200
    float* hb_s  = sm + 26400;     // 100
    float* w2s   = sm + 26500;     // 100
    float* beta_s= sm + 26600;     // 32
    int tid = threadIdx.x;
    int row0 = blockIdx.x * 32;
    int b = row0 >> 6;
    int lbase = row0 & 63;

    for (int i = tid; i < 20000; i += 256) w_s[i] = w_1[i];
    for (int idx = tid; idx < 32*200; idx += 256) {
        int r = idx / 200, k = idx % 200;
        size_t row = row0 + r;
        int l = (int)(row % Ldim);
        ins[r*200 + k] = (k < 100) ? pos_emb[l*Dn + k] : g_seq[row*Dn + (k-100)];
    }
    if (tid < Dn) { hb_s[tid] = glu1_b[tid] + g_hsg[b*Dn + tid]; w2s[tid] = w_2[tid]; }
    __syncthreads();

    int lane = tid & 31, ty = tid >> 5;
    int r0 = ty * 4;

    // GEMM1: nh = tanh([pe,seq] @ w_1)
    {
        float acc[4][4] = {};
        for (int k = 0; k < 200; k++) {
            float w0 = w_s[k*100 + lane];
            float w1 = w_s[k*100 + lane + 32];
            float w2 = w_s[k*100 + lane + 64];
            float w3 = (lane < 4) ? w_s[k*100 + lane + 96] : 0.f;
            #pragma unroll
            for (int i = 0; i < 4; i++) {
                float a = ins[(r0+i)*200 + k];
                acc[i][0] = fmaf(a, w0, acc[i][0]);
                acc[i][1] = fmaf(a, w1, acc[i][1]);
                acc[i][2] = fmaf(a, w2, acc[i][2]);
                acc[i][3] = fmaf(a, w3, acc[i][3]);
            }
        }
        // write tanh(nh) into own rows' cols 0..99 of ins (per-warp private rows)
        #pragma unroll
        for (int i = 0; i < 4; i++) {
            #pragma unroll
            for (int q = 0; q < 4; q++) {
                int c = lane + 32*q;
                if (c < 100) ins[(r0+i)*200 + c] = tanhf(acc[i][q]);
            }
        }
    }
    __syncthreads();
    // reload w_s with glu1_w (all warps done reading w_1)
    for (int i = tid; i < 10000; i += 256) w_s[i] = glu1_w[i];
    __syncthreads();

    // GEMM2: t = nh @ glu1_w + hb ; sig = sigmoid(t); beta_row = sum_c sig*w2
    {
        float t[4][4];
        #pragma unroll
        for (int i = 0; i < 4; i++) {
            #pragma unroll
            for (int q = 0; q < 4; q++) {
                int c = lane + 32*q;
                t[i][q] = (c < 100) ? hb_s[c] : 0.f;
            }
        }
        for (int k = 0; k < 100; k++) {
            float w0 = w_s[k*100 + lane];
            float w1 = w_s[k*100 + lane + 32];
            float w2 = w_s[k*100 + lane + 64];
            float w3 = (lane < 4) ? w_s[k*100 + lane + 96] : 0.f;
            #pragma unroll
            for (int i = 0; i < 4; i++) {
                float a = ins[(r0+i)*200 + k];   // nh
                t[i][0] = fmaf(a, w0, t[i][0]);
                t[i][1] = fmaf(a, w1, t[i][1]);
                t[i][2] = fmaf(a, w2, t[i][2]);
                t[i][3] = fmaf(a, w3, t[i][3]);
            }
        }
        #pragma unroll
        for (int i = 0; i < 4; i++) {
            float s = 0.f;
            #pragma unroll
            for (int q = 0; q < 4; q++) {
                int c = lane + 32*q;
                if (c < 100) {
                    float sg = 1.f / (1.f + __expf(-t[i][q]));
                    s = fmaf(sg, w2s[c], s);
                }
            }
            #pragma unroll
            for (int o = 16; o > 0; o >>= 1) s += __shfl_xor_sync(0xffffffffu, s, o);
            if (lane == 0)
                beta_s[r0 + i] = s * mask[b*Ldim + lbase + r0 + i];
        }
    }
    __syncthreads();

    // select partial: sum over this CTA's 32 l of beta * seq
    if (tid < Dn) {
        float sel = 0.f;
        #pragma unroll 8
        for (int r = 0; r < 32; r++)
            sel = fmaf(beta_s[r], ins[r*200 + 100 + tid], sel);
        g_selpart[blockIdx.x*Dn + tid] = sel;
    }
}

// ---------------- K6a: score = (selpart0+selpart1) @ emb[1:]^T (tf32 mma) ---
#define SC_EMBT 3328          // after sel_s 32*104
#define SC_TOT  (3328 + 104*137)
__global__ __launch_bounds__(256) void k_score(
    const float* __restrict__ emb, float* __restrict__ out)
{
    extern __shared__ float sm[];
    float* sel_s = sm;
    float* embT  = sm + SC_EMBT;
    int n0 = blockIdx.x * 128, b0 = blockIdx.y * 32;
    int tid = threadIdx.x;
    int lane = tid & 31, warp = tid >> 5;

    for (int idx = tid; idx < 32*25; idx += 256) {
        int r = idx / 25, c4 = (idx % 25) * 4;
        int bb = b0 + r;
        float4 v0 = *(const float4*)(g_selpart + (2*bb)*Dn + c4);
        float4 v1 = *(const float4*)(g_selpart + (2*bb+1)*Dn + c4);
        float* d = sel_s + r*104 + c4;
        d[0] = to_tf32(v0.x + v1.x); d[1] = to_tf32(v0.y + v1.y);
        d[2] = to_tf32(v0.z + v1.z); d[3] = to_tf32(v0.w + v1.w);
    }
    if (tid < 32) {
        float* d = sel_s + tid*104 + 100;
        d[0] = 0.f; d[1] = 0.f; d[2] = 0.f; d[3] = 0.f;
    }
    for (int idx = tid; idx < 128*25; idx += 256) {
        int r = idx / 25, c4 = (idx % 25) * 4;
        int n = n0 + r;
        float4 v = make_float4(0.f,0.f,0.f,0.f);
        if (n < NOUT) v = *(const float4*)(emb + (size_t)(n + 1)*Dn + c4);
        embT[(c4+0)*137 + r] = to_tf32(v.x);
        embT[(c4+1)*137 + r] = to_tf32(v.y);
        embT[(c4+2)*137 + r] = to_tf32(v.z);
        embT[(c4+3)*137 + r] = to_tf32(v.w);
    }
    for (int idx = tid; idx < 4*128; idx += 256) {
        int k = 100 + idx / 128, n = idx % 128;
        embT[k*137 + n] = 0.f;
    }
    __syncthreads();

    int g = lane >> 2, tg = lane & 3;
    int mt = warp & 1;
    int nb = warp >> 1;
    const float* Arow = sel_s + mt*16*104;

    float acc[4][4];
    #pragma unroll
    for (int j = 0; j < 4; j++)
        #pragma unroll
        for (int q = 0; q < 4; q++) acc[j][q] = 0.f;

    #pragma unroll 1
    for (int kt = 0; kt < 13; kt++) {
        int ak = kt*8;
        uint32_t a0 = __float_as_uint(Arow[ g   *104 + ak + tg    ]);
        uint32_t a1 = __float_as_uint(Arow[(g+8)*104 + ak + tg    ]);
        uint32_t a2 = __float_as_uint(Arow[ g   *104 + ak + tg + 4]);
        uint32_t a3 = __float_as_uint(Arow[(g+8)*104 + ak + tg + 4]);
        #pragma unroll
        for (int j = 0; j < 4; j++) {
            int nt = nb*4 + j;
            uint32_t bb0 = __float_as_uint(embT[(ak + tg    )*137 + nt*8 + g]);
            uint32_t bb1 = __float_as_uint(embT[(ak + tg + 4)*137 + nt*8 + g]);
            asm volatile(
                "mma.sync.aligned.m16n8k8.row.col.f32.tf32.tf32.f32 "
                "{%0,%1,%2,%3}, {%4,%5,%6,%7}, {%8,%9}, {%0,%1,%2,%3};"
                : "+f"(acc[j][0]), "+f"(acc[j][1]), "+f"(acc[j][2]), "+f"(acc[j][3])
                : "r"(a0), "r"(a1), "r"(a2), "r"(a3), "r"(bb0), "r"(bb1));
        }
    }

    int row_lo = b0 + mt*16 + g;
    int row_hi = row_lo + 8;
    float rmax_lo = -3.0e38f, rmax_hi = -3.0e38f;
    #pragma unroll
    for (int j = 0; j < 4; j++) {
        int nt = nb*4 + j;
        int ncol = n0 + nt*8 + tg*2;
        if (ncol < NOUT) {
            out[(size_t)row_lo*NOUT + ncol] = acc[j][0];
            out[(size_t)row_hi*NOUT + ncol] = acc[j][2];
            rmax_lo = fmaxf(rmax_lo, acc[j][0]);
            rmax_hi = fmaxf(rmax_hi, acc[j][2]);
        }
        if (ncol + 1 < NOUT) {
            out[(size_t)row_lo*NOUT + ncol + 1] = acc[j][1];
            out[(size_t)row_hi*NOUT + ncol + 1] = acc[j][3];
            rmax_lo = fmaxf(rmax_lo, acc[j][1]);
            rmax_hi = fmaxf(rmax_hi, acc[j][3]);
        }
    }
    rmax_lo = fmaxf(rmax_lo, __shfl_xor_sync(0xffffffffu, rmax_lo, 1));
    rmax_lo = fmaxf(rmax_lo, __shfl_xor_sync(0xffffffffu, rmax_lo, 2));
    rmax_hi = fmaxf(rmax_hi, __shfl_xor_sync(0xffffffffu, rmax_hi, 1));
    rmax_hi = fmaxf(rmax_hi, __shfl_xor_sync(0xffffffffu, rmax_hi, 2));
    if (tg == 0) {
        atomicMax(&g_rmaxbits[row_lo], fkey(rmax_lo));
        atomicMax(&g_rmaxbits[row_hi], fkey(rmax_hi));
    }
}

// ---------------- K6b: per-chunk sum of exp ----------------
__global__ __launch_bounds__(256) void k_expsum(const float* __restrict__ out)
{
    int b = blockIdx.y, chunk = blockIdx.x, tid = threadIdx.x;
    int start = chunk * CHUNKSZ;
    int end = start + CHUNKSZ; if (end > NOUT) end = NOUT;
    float m = funkey(g_rmaxbits[b]);
    float s = 0.f;
    for (int n = start + tid; n < end; n += 256)
        s += fexp(out[(size_t)b*NOUT + n] - m);
    __shared__ float red[256];
    red[tid] = s;
    __syncthreads();
    for (int st = 128; st > 0; st >>= 1) {
        if (tid < st) red[tid] += red[tid + st];
        __syncthreads();
    }
    if (tid == 0) g_rpart[b*NCHUNK + chunk] = red[0];
}

// ---------------- K6c: exp + scale ----------------
__global__ __launch_bounds__(256) void k_scale(float* __restrict__ out)
{
    int b = blockIdx.y;
    int n = blockIdx.x * 256 + threadIdx.x;
    if (n < NOUT) {
        float ssum = 0.f;
        #pragma unroll
        for (int j = 0; j < NCHUNK; j++) ssum += g_rpart[b*NCHUNK + j];
        float m = funkey(g_rmaxbits[b]);
        float inv = __fdividef(1.f, ssum);
        size_t idx = (size_t)b*NOUT + n;
        out[idx] = fexp(out[idx] - m) * inv;
    }
}

// ---------------- launch ----------------
extern "C" void kernel_launch(void* const* d_in, const int* in_sizes, int n_in,
                              void* d_out, int out_size)
{
    const int*   alias_inputs = (const int*)  d_in[0];
    const int*   items        = (const int*)  d_in[1];
    const int*   adj          = (const int*)  d_in[2];
    const float* mask_item    = (const float*)d_in[3];
    const int*   seq_features = (const int*)  d_in[4];
    const int*   adj_all      = (const int*)  d_in[5];
    const float* num_w        = (const float*)d_in[6];
    const float* emb          = (const float*)d_in[7];
    const float* pos_emb      = (const float*)d_in[8];
    const float* a0           = (const float*)d_in[9];
    const float* a1           = (const float*)d_in[10];
    const float* a2           = (const float*)d_in[11];
    const float* a3           = (const float*)d_in[12];
    const float* g_w1         = (const float*)d_in[13];
    const float* g_w2         = (const float*)d_in[14];
    const float* g_w3         = (const float*)d_in[15];
    const float* w_1          = (const float*)d_in[16];
    const float* w_2          = (const float*)d_in[17];
    const float* glu1_w       = (const float*)d_in[18];
    const float* glu1_b       = (const float*)d_in[19];
    const float* glu2_w       = (const float*)d_in[20];
    const float* glu2_b       = (const float*)d_in[21];
    float* out = (float*)d_out;

    const int GSMEM = GT_TOT * 4;                  // ~86.3 KB
    const int CSMEM = (20000 + 32*200) * 4;        // ~105.6 KB
    const int NSMEM = NH_TOT * 4;                  // ~106.5 KB
    const int SSMEM = SC_TOT * 4;                  // ~70.3 KB
    cudaFuncSetAttribute(k_global,  cudaFuncAttributeMaxDynamicSharedMemorySize, GSMEM);
    cudaFuncSetAttribute(k_combine, cudaFuncAttributeMaxDynamicSharedMemorySize, CSMEM);
    cudaFuncSetAttribute(k_nhsel,   cudaFuncAttributeMaxDynamicSharedMemorySize, NSMEM);
    cudaFuncSetAttribute(k_score,   cudaFuncAttributeMaxDynamicSharedMemorySize, SSMEM);

    k_init   <<<1, 256>>>();
    k_local  <<<Bn, 256>>>(items, adj, emb, a0, a1, a2, a3);
    k_sess   <<<Bn, 128>>>(seq_features, mask_item, emb);
    k_global <<<Bn*2, 256, GSMEM>>>(items, adj_all, num_w, emb, g_w1, g_w2);
    k_combine<<<(Bn*Ldim)/32, 256, CSMEM>>>(g_w3);
    k_seqhs  <<<Bn, 128>>>(alias_inputs, mask_item, glu2_w, glu2_b);
    k_nhsel  <<<(Bn*Ldim)/32, 256, NSMEM>>>(pos_emb, w_1, glu1_w, glu1_b, w_2, mask_item);
    dim3 gs((NOUT + 127)/128, Bn/32);
    k_score  <<<gs, 256, SSMEM>>>(emb, out);
    dim3 ge(NCHUNK, Bn);
    k_expsum <<<ge, 256>>>(out);
    dim3 gn((NOUT + 255)/256, Bn);
    k_scale  <<<gn, 256>>>(out);
}

// round 9
// speedup vs baseline: 1.9610x; 1.1172x over previous
#include <cuda_runtime.h>
#include <math.h>
#include <stdint.h>

#define Bn 256
#define Ldim 64
#define Sn 12
#define Dn 100
#define NUM_NODE 43098
#define NOUT 43097
#define NEGV -9000000000000000.0f
#define NCHUNK 8
#define CHUNKSZ 5388   // ceil(43097/8)

// ---------------- scratch (device globals; no allocation) ----------------
__device__ float g_h[Bn*Ldim*Dn];
__device__ float g_hlocal[Bn*Ldim*Dn];
__device__ float g_sess[Bn*Dn];
__device__ float g_nb[Bn*Ldim*Dn];
__device__ float g_hcomb[Bn*Ldim*Dn];
__device__ float g_seq[Bn*Ldim*Dn];
__device__ float g_hsg[Bn*Dn];
__device__ float g_selpart[2*Bn*Dn];
__device__ unsigned g_rmaxbits[Bn];
__device__ float g_rpart[Bn*NCHUNK];

__device__ __forceinline__ unsigned fkey(float f) {
    unsigned u = __float_as_uint(f);
    return (u & 0x80000000u) ? ~u : (u | 0x80000000u);
}
__device__ __forceinline__ float funkey(unsigned k) {
    return (k & 0x80000000u) ? __uint_as_float(k ^ 0x80000000u)
                             : __uint_as_float(~k);
}

__device__ __forceinline__ float fexp(float x) {
    float y = x * 1.44269504088896340736f;
    y = fmaxf(y, -126.0f);
    float t = y + 12582912.0f;
    float i = t - 12582912.0f;
    float f = y - i;
    int ii = (int)i;
    float p = 1.54035303933816e-4f;
    p = fmaf(p, f, 1.33335581464284e-3f);
    p = fmaf(p, f, 9.61812910762848e-3f);
    p = fmaf(p, f, 5.55041086648216e-2f);
    p = fmaf(p, f, 2.40226506959101e-1f);
    p = fmaf(p, f, 6.93147180559945e-1f);
    p = fmaf(p, f, 1.0f);
    return p * __int_as_float((ii + 127) << 23);
}

__device__ __forceinline__ float to_tf32(float x) {
    uint32_t r;
    asm("cvt.rna.tf32.f32 %0, %1;" : "=r"(r) : "f"(x));
    return __uint_as_float(r);
}

// ---------------- K0 ----------------
__global__ void k_init() {
    int t = threadIdx.x;
    if (t < Bn) g_rmaxbits[t] = 0u;
}

// ---------------- K1: local graph attention ----------------
__global__ __launch_bounds__(256) void k_local(
    const int* __restrict__ items, const int* __restrict__ adj,
    const float* __restrict__ emb,
    const float* __restrict__ a0, const float* __restrict__ a1,
    const float* __restrict__ a2, const float* __restrict__ a3)
{
    int b = blockIdx.x;
    __shared__ float hs[Ldim][101];
    __shared__ float alpha[Ldim][Ldim+1];
    __shared__ float As[Dn][4];
    int tid = threadIdx.x;

    for (int i = tid; i < Dn; i += 256) {
        As[i][0] = a0[i]; As[i][1] = a1[i]; As[i][2] = a2[i]; As[i][3] = a3[i];
    }
    for (int idx = tid; idx < Ldim*Dn; idx += 256) {
        int l = idx / Dn, d = idx % Dn;
        float v = emb[(size_t)items[b*Ldim + l]*Dn + d];
        hs[l][d] = v;
        g_h[((size_t)b*Ldim + l)*Dn + d] = v;
    }
    __syncthreads();

    for (int p = tid; p < Ldim*Ldim; p += 256) {
        int i = p / Ldim, j = p % Ldim;
        int a = adj[((size_t)b*Ldim + i)*Ldim + j];
        float val = NEGV;
        if (a >= 1 && a <= 4) {
            float acc = 0.f;
            int k = a - 1;
            for (int d = 0; d < Dn; d++)
                acc += hs[i][d] * hs[j][d] * As[d][k];
            val = acc > 0.f ? acc : 0.2f * acc;
        }
        alpha[i][j] = val;
    }
    __syncthreads();

    int warp = tid >> 5, lane = tid & 31;
    for (int i = warp; i < Ldim; i += 8) {
        float x0 = alpha[i][lane], x1 = alpha[i][lane+32];
        float m = fmaxf(x0, x1);
        #pragma unroll
        for (int o = 16; o > 0; o >>= 1) m = fmaxf(m, __shfl_xor_sync(0xffffffffu, m, o));
        float e0 = __expf(fmaxf(x0 - m, -87.f));
        float e1 = __expf(fmaxf(x1 - m, -87.f));
        float s = e0 + e1;
        #pragma unroll
        for (int o = 16; o > 0; o >>= 1) s += __shfl_xor_sync(0xffffffffu, s, o);
        float inv = 1.f / s;
        alpha[i][lane] = e0 * inv;
        alpha[i][lane+32] = e1 * inv;
    }
    __syncthreads();

    for (int idx = tid; idx < Ldim*Dn; idx += 256) {
        int i = idx / Dn, d = idx % Dn;
        float acc = 0.f;
        for (int j = 0; j < Ldim; j++) acc += alpha[i][j] * hs[j][d];
        g_hlocal[((size_t)b*Ldim + i)*Dn + d] = acc;
    }
}

// ---------------- K2: sess mean ----------------
__global__ __launch_bounds__(128) void k_sess(
    const int* __restrict__ seq_features, const float* __restrict__ mask,
    const float* __restrict__ emb)
{
    int b = blockIdx.x, tid = threadIdx.x;
    if (tid >= Dn) return;
    float acc = 0.f, msum = 0.f;
    for (int l = 0; l < Ldim; l++) {
        float mk = mask[b*Ldim + l];
        acc += emb[(size_t)seq_features[b*Ldim + l]*Dn + tid] * mk;
        msum += mk;
    }
    g_sess[b*Dn + tid] = acc / msum;
}

// ---------------- K3: global neighbor aggregation (tf32 mma; sess folded) --
// w1s rows pre-scaled by sess  =>  feat = raw tf32 emb  =>  nb epilogue from smem
#define GT_W1   0        // 104*104 = 10816
#define GT_FEAT 10816    // 96*108  = 10368
#define GT_W2   21184    // 104
#define GT_SESS 21288    // 100
#define GT_ALSC 21388    // 96
#define GT_NBR  21484    // 96 ints
#define GT_TOT  21580
__global__ __launch_bounds__(256) void k_global(
    const int* __restrict__ items, const int* __restrict__ adj_all,
    const float* __restrict__ num_w, const float* __restrict__ emb,
    const float* __restrict__ g_w1, const float* __restrict__ g_w2)
{
    extern __shared__ float sm[];
    float* w1s   = sm + GT_W1;
    float* feat  = sm + GT_FEAT;
    float* w2s   = sm + GT_W2;
    float* sesss = sm + GT_SESS;
    float* alsc  = sm + GT_ALSC;
    int*   nbrs  = (int*)(sm + GT_NBR);

    int blk = blockIdx.x;
    int b = blk >> 1;
    int l0 = (blk & 1) * 32;
    int tid = threadIdx.x;
    int lane = tid & 31, warp = tid >> 5;

    for (int i = tid; i < 104*104; i += 256) w1s[i] = 0.f;
    if (tid < 104) w2s[tid] = (tid < Dn) ? g_w2[tid] : 0.f;
    if (tid < Dn) sesss[tid] = g_sess[b*Dn + tid];
    __syncthreads();
    for (int i = tid; i < 101*100; i += 256) {
        int k = i / 100, n = i % 100;
        float scale = (k < 100) ? sesss[k] : 1.f;
        w1s[k*104 + n] = to_tf32(g_w1[i] * scale);
    }
    __syncthreads();

    int g = lane >> 2, tg = lane & 3;

    for (int it = 0; it < 4; it++) {
        int lbase = l0 + it*8;
        if (tid < 96) {
            int l = tid / 12, s = tid % 12;
            int node = items[b*Ldim + lbase + l];
            nbrs[tid] = adj_all[(size_t)node*Sn + s];
            feat[tid*108 + 100] = to_tf32(num_w[(size_t)node*Sn + s]);
            feat[tid*108 + 101] = 0.f;
            feat[tid*108 + 102] = 0.f;
            feat[tid*108 + 103] = 0.f;
        }
        __syncthreads();
        for (int idx = tid; idx < 96*25; idx += 256) {
            int r = idx / 25, c4 = (idx % 25) * 4;
            float4 e = *(const float4*)(emb + (size_t)nbrs[r]*Dn + c4);
            float* dst = feat + r*108 + c4;
            dst[0] = to_tf32(e.x);
            dst[1] = to_tf32(e.y);
            dst[2] = to_tf32(e.z);
            dst[3] = to_tf32(e.w);
        }
        __syncthreads();

        if (warp < 6) {
            const float* Ab = feat + warp*16*108;
            float score_a = 0.f, score_b = 0.f;
            #pragma unroll 1
            for (int nt = 0; nt < 13; nt++) {
                float c0 = 0.f, c1 = 0.f, c2 = 0.f, c3 = 0.f;
                #pragma unroll
                for (int kt = 0; kt < 13; kt++) {
                    int ak = kt*8;
                    uint32_t a0 = __float_as_uint(Ab[ g   *108 + ak + tg    ]);
                    uint32_t a1 = __float_as_uint(Ab[(g+8)*108 + ak + tg    ]);
                    uint32_t a2 = __float_as_uint(Ab[ g   *108 + ak + tg + 4]);
                    uint32_t a3 = __float_as_uint(Ab[(g+8)*108 + ak + tg + 4]);
                    uint32_t b0 = __float_as_uint(w1s[(ak + tg    )*104 + nt*8 + g]);
                    uint32_t b1 = __float_as_uint(w1s[(ak + tg + 4)*104 + nt*8 + g]);
                    asm volatile(
                        "mma.sync.aligned.m16n8k8.row.col.f32.tf32.tf32.f32 "
                        "{%0,%1,%2,%3}, {%4,%5,%6,%7}, {%8,%9}, {%0,%1,%2,%3};"
                        : "+f"(c0), "+f"(c1), "+f"(c2), "+f"(c3)
                        : "r"(a0), "r"(a1), "r"(a2), "r"(a3), "r"(b0), "r"(b1));
                }
                int j0 = nt*8 + tg*2;
                float w20 = w2s[j0], w21 = w2s[j0+1];
                float v0 = c0 > 0.f ? c0 : 0.2f*c0;
                float v1 = c1 > 0.f ? c1 : 0.2f*c1;
                float v2 = c2 > 0.f ? c2 : 0.2f*c2;
                float v3 = c3 > 0.f ? c3 : 0.2f*c3;
                score_a = fmaf(v0, w20, fmaf(v1, w21, score_a));
                score_b = fmaf(v2, w20, fmaf(v3, w21, score_b));
            }
            score_a += __shfl_xor_sync(0xffffffffu, score_a, 1);
            score_a += __shfl_xor_sync(0xffffffffu, score_a, 2);
            score_b += __shfl_xor_sync(0xffffffffu, score_b, 1);
            score_b += __shfl_xor_sync(0xffffffffu, score_b, 2);
            if (tg == 0) {
                alsc[warp*16 + g]     = score_a;
                alsc[warp*16 + g + 8] = score_b;
            }
        }
        __syncthreads();

        if (tid < 8) {
            float* a = alsc + tid*12;
            float m = a[0];
            #pragma unroll
            for (int s = 1; s < Sn; s++) m = fmaxf(m, a[s]);
            float ssum = 0.f;
            float e[Sn];
            #pragma unroll
            for (int s = 0; s < Sn; s++) { e[s] = __expf(a[s] - m); ssum += e[s]; }
            float inv = 1.f / ssum;
            #pragma unroll
            for (int s = 0; s < Sn; s++) a[s] = e[s] * inv;
        }
        __syncthreads();

        // nb from smem feat (tf32-rounded emb)
        for (int idx = tid; idx < 800; idx += 256) {
            int l = idx / 100, c = idx % 100;
            const float* fr = feat + (l*12)*108 + c;
            const float* al = alsc + l*12;
            float acc = 0.f;
            #pragma unroll
            for (int s = 0; s < Sn; s++)
                acc = fmaf(al[s], fr[s*108], acc);
            g_nb[((size_t)b*Ldim + lbase + l)*Dn + c] = acc;
        }
        __syncthreads();
    }
}

// ---------------- K4: h_combine = relu([h,nb]@g_w3) + h_local (tf32 mma) ----
// smem: w3s [200(k)][104(n)] tf32 ; ins [32 rows][204] tf32
#define CB_W3  0             // 200*104 = 20800
#define CB_INS 20800         // 32*204  = 6528
#define CB_TOT 27328
__global__ __launch_bounds__(256) void k_combine(const float* __restrict__ g_w3)
{
    extern __shared__ float sm[];
    float* w3s = sm + CB_W3;
    float* ins = sm + CB_INS;
    int tid = threadIdx.x;
    int lane = tid & 31, warp = tid >> 5;

    for (int i = tid; i < 200*104; i += 256) w3s[i] = 0.f;
    __syncthreads();
    for (int i = tid; i < 200*100; i += 256) {
        int k = i / 100, n = i % 100;
        w3s[k*104 + n] = to_tf32(g_w3[i]);
    }
    __syncthreads();

    int g = lane >> 2, tg = lane & 3;
    int mt = warp & 1;          // m-tile: rows 0-15 / 16-31
    int ng = warp >> 1;         // n-group: tiles ng*4 .. ng*4+3 (skip >=13)

    for (int it = 0; it < 2; it++) {
        int row0 = blockIdx.x * 64 + it * 32;
        // fill ins: cols 0..99 = h, 100..199 = nb, 200..203 = 0
        for (int idx = tid; idx < 32*25; idx += 256) {
            int r = idx / 25, c4 = (idx % 25) * 4;
            size_t row = row0 + r;
            float4 vh = *(const float4*)(g_h  + row*Dn + c4);
            float4 vn = *(const float4*)(g_nb + row*Dn + c4);
            float* d = ins + r*204;
            d[c4+0]   = to_tf32(vh.x); d[c4+1]   = to_tf32(vh.y);
            d[c4+2]   = to_tf32(vh.z); d[c4+3]   = to_tf32(vh.w);
            d[100+c4+0] = to_tf32(vn.x); d[100+c4+1] = to_tf32(vn.y);
            d[100+c4+2] = to_tf32(vn.z); d[100+c4+3] = to_tf32(vn.w);
        }
        if (tid < 32) {
            float* d = ins + tid*204 + 200;
            d[0] = 0.f; d[1] = 0.f; d[2] = 0.f; d[3] = 0.f;
        }
        __syncthreads();

        float acc[4][4];
        #pragma unroll
        for (int j = 0; j < 4; j++)
            #pragma unroll
            for (int q = 0; q < 4; q++) acc[j][q] = 0.f;

        const float* Arow = ins + mt*16*204;
        #pragma unroll 1
        for (int kt = 0; kt < 25; kt++) {
            int ak = kt*8;
            uint32_t a0 = __float_as_uint(Arow[ g   *204 + ak + tg    ]);
            uint32_t a1 = __float_as_uint(Arow[(g+8)*204 + ak + tg    ]);
            uint32_t a2 = __float_as_uint(Arow[ g   *204 + ak + tg + 4]);
            uint32_t a3 = __float_as_uint(Arow[(g+8)*204 + ak + tg + 4]);
            #pragma unroll
            for (int j = 0; j < 4; j++) {
                int nt = ng*4 + j;
                if (nt < 13) {
                    uint32_t b0 = __float_as_uint(w3s[(ak + tg    )*104 + nt*8 + g]);
                    uint32_t b1 = __float_as_uint(w3s[(ak + tg + 4)*104 + nt*8 + g]);
                    asm volatile(
                        "mma.sync.aligned.m16n8k8.row.col.f32.tf32.tf32.f32 "
                        "{%0,%1,%2,%3}, {%4,%5,%6,%7}, {%8,%9}, {%0,%1,%2,%3};"
                        : "+f"(acc[j][0]), "+f"(acc[j][1]), "+f"(acc[j][2]), "+f"(acc[j][3])
                        : "r"(a0), "r"(a1), "r"(a2), "r"(a3), "r"(b0), "r"(b1));
                }
            }
        }

        size_t row_lo = row0 + mt*16 + g;
        size_t row_hi = row_lo + 8;
        #pragma unroll
        for (int j = 0; j < 4; j++) {
            int nt = ng*4 + j;
            if (nt < 13) {
                int c = nt*8 + tg*2;
                if (c < 100) {
                    g_hcomb[row_lo*Dn + c] = g_hlocal[row_lo*Dn + c] + fmaxf(acc[j][0], 0.f);
                    g_hcomb[row_hi*Dn + c] = g_hlocal[row_hi*Dn + c] + fmaxf(acc[j][2], 0.f);
                }
                if (c + 1 < 100) {
                    g_hcomb[row_lo*Dn + c + 1] = g_hlocal[row_lo*Dn + c + 1] + fmaxf(acc[j][1], 0.f);
                    g_hcomb[row_hi*Dn + c + 1] = g_hlocal[row_hi*Dn + c + 1] + fmaxf(acc[j][3], 0.f);
                }
            }
        }
        __syncthreads();
    }
}

// ---------------- K5a: seq gather, hs, hsg ----------------
__global__ __launch_bounds__(128) void k_seqhs(
    const int* __restrict__ alias, const float* __restrict__ mask,
    const float* __restrict__ glu2_w, const float* __restrict__ glu2_b)
{
    int b = blockIdx.x, tid = threadIdx.x;
    __shared__ float hs_s[Dn];
    __shared__ int alias_s[Ldim];
    __shared__ float mk_s[Ldim];
    if (tid < Ldim) { alias_s[tid] = alias[b*Ldim + tid]; mk_s[tid] = mask[b*Ldim + tid]; }
    __syncthreads();
    if (tid < Dn) {
        float acc = 0.f, msum = 0.f;
        for (int l = 0; l < Ldim; l++) {
            float v = g_hcomb[((size_t)b*Ldim + alias_s[l])*Dn + tid];
            g_seq[((size_t)b*Ldim + l)*Dn + tid] = v;
            acc += v * mk_s[l];
            msum += mk_s[l];
        }
        hs_s[tid] = acc / msum;
    }
    __syncthreads();
    if (tid < Dn) {
        float t = glu2_b[tid];
        for (int c = 0; c < Dn; c++) t = fmaf(hs_s[c], __ldg(&glu2_w[c*Dn + tid]), t);
        g_hsg[b*Dn + tid] = t;
    }
}

// ---------------- K5b: fused nh + GLU + select partial ----------------
#define NH_TOT (20000 + 6400 + 100 + 100 + 32)
__global__ __launch_bounds__(256) void k_nhsel(
    const float* __restrict__ pos_emb, const float* __restrict__ w_1,
    const float* __restrict__ glu1_w, const float* __restrict__ glu1_b,
    const float* __restrict__ w_2, const float* __restrict__ mask)
{
    extern __shared__ float sm[];
    float* w_s   = sm;             // 20000
    float* ins   = sm + 20000;     // 32 x 200
    float* hb_s  = sm + 26400;     // 100
    float* w2s   = sm + 26500;     // 100
    float* beta_s= sm + 26600;     // 32
    int tid = threadIdx.x;
    int row0 = blockIdx.x * 32;
    int b = row0 >> 6;
    int lbase = row0 & 63;

    for (int i = tid; i < 20000; i += 256) w_s[i] = w_1[i];
    for (int idx = tid; idx < 32*200; idx += 256) {
        int r = idx / 200, k = idx % 200;
        size_t row = row0 + r;
        int l = (int)(row % Ldim);
        ins[r*200 + k] = (k < 100) ? pos_emb[l*Dn + k] : g_seq[row*Dn + (k-100)];
    }
    if (tid < Dn) { hb_s[tid] = glu1_b[tid] + g_hsg[b*Dn + tid]; w2s[tid] = w_2[tid]; }
    __syncthreads();

    int lane = tid & 31, ty = tid >> 5;
    int r0 = ty * 4;

    // GEMM1: nh = tanh([pe,seq] @ w_1)
    {
        float acc[4][4] = {};
        for (int k = 0; k < 200; k++) {
            float w0 = w_s[k*100 + lane];
            float w1 = w_s[k*100 + lane + 32];
            float w2 = w_s[k*100 + lane + 64];
            float w3 = (lane < 4) ? w_s[k*100 + lane + 96] : 0.f;
            #pragma unroll
            for (int i = 0; i < 4; i++) {
                float a = ins[(r0+i)*200 + k];
                acc[i][0] = fmaf(a, w0, acc[i][0]);
                acc[i][1] = fmaf(a, w1, acc[i][1]);
                acc[i][2] = fmaf(a, w2, acc[i][2]);
                acc[i][3] = fmaf(a, w3, acc[i][3]);
            }
        }
        #pragma unroll
        for (int i = 0; i < 4; i++) {
            #pragma unroll
            for (int q = 0; q < 4; q++) {
                int c = lane + 32*q;
                if (c < 100) ins[(r0+i)*200 + c] = tanhf(acc[i][q]);
            }
        }
    }
    __syncthreads();
    for (int i = tid; i < 10000; i += 256) w_s[i] = glu1_w[i];
    __syncthreads();

    // GEMM2: t = nh @ glu1_w + hb ; sig = sigmoid(t); beta_row = sum_c sig*w2
    {
        float t[4][4];
        #pragma unroll
        for (int i = 0; i < 4; i++) {
            #pragma unroll
            for (int q = 0; q < 4; q++) {
                int c = lane + 32*q;
                t[i][q] = (c < 100) ? hb_s[c] : 0.f;
            }
        }
        for (int k = 0; k < 100; k++) {
            float w0 = w_s[k*100 + lane];
            float w1 = w_s[k*100 + lane + 32];
            float w2 = w_s[k*100 + lane + 64];
            float w3 = (lane < 4) ? w_s[k*100 + lane + 96] : 0.f;
            #pragma unroll
            for (int i = 0; i < 4; i++) {
                float a = ins[(r0+i)*200 + k];   // nh
                t[i][0] = fmaf(a, w0, t[i][0]);
                t[i][1] = fmaf(a, w1, t[i][1]);
                t[i][2] = fmaf(a, w2, t[i][2]);
                t[i][3] = fmaf(a, w3, t[i][3]);
            }
        }
        #pragma unroll
        for (int i = 0; i < 4; i++) {
            float s = 0.f;
            #pragma unroll
            for (int q = 0; q < 4; q++) {
                int c = lane + 32*q;
                if (c < 100) {
                    float sg = 1.f / (1.f + __expf(-t[i][q]));
                    s = fmaf(sg, w2s[c], s);
                }
            }
            #pragma unroll
            for (int o = 16; o > 0; o >>= 1) s += __shfl_xor_sync(0xffffffffu, s, o);
            if (lane == 0)
                beta_s[r0 + i] = s * mask[b*Ldim + lbase + r0 + i];
        }
    }
    __syncthreads();

    if (tid < Dn) {
        float sel = 0.f;
        #pragma unroll 8
        for (int r = 0; r < 32; r++)
            sel = fmaf(beta_s[r], ins[r*200 + 100 + tid], sel);
        g_selpart[blockIdx.x*Dn + tid] = sel;
    }
}

// ---------------- K6a: score = (selpart0+selpart1) @ emb[1:]^T (tf32 mma) ---
#define SC_EMBT 3328
#define SC_TOT  (3328 + 104*137)
__global__ __launch_bounds__(256) void k_score(
    const float* __restrict__ emb, float* __restrict__ out)
{
    extern __shared__ float sm[];
    float* sel_s = sm;
    float* embT  = sm + SC_EMBT;
    int n0 = blockIdx.x * 128, b0 = blockIdx.y * 32;
    int tid = threadIdx.x;
    int lane = tid & 31, warp = tid >> 5;

    for (int idx = tid; idx < 32*25; idx += 256) {
        int r = idx / 25, c4 = (idx % 25) * 4;
        int bb = b0 + r;
        float4 v0 = *(const float4*)(g_selpart + (2*bb)*Dn + c4);
        float4 v1 = *(const float4*)(g_selpart + (2*bb+1)*Dn + c4);
        float* d = sel_s + r*104 + c4;
        d[0] = to_tf32(v0.x + v1.x); d[1] = to_tf32(v0.y + v1.y);
        d[2] = to_tf32(v0.z + v1.z); d[3] = to_tf32(v0.w + v1.w);
    }
    if (tid < 32) {
        float* d = sel_s + tid*104 + 100;
        d[0] = 0.f; d[1] = 0.f; d[2] = 0.f; d[3] = 0.f;
    }
    for (int idx = tid; idx < 128*25; idx += 256) {
        int r = idx / 25, c4 = (idx % 25) * 4;
        int n = n0 + r;
        float4 v = make_float4(0.f,0.f,0.f,0.f);
        if (n < NOUT) v = *(const float4*)(emb + (size_t)(n + 1)*Dn + c4);
        embT[(c4+0)*137 + r] = to_tf32(v.x);
        embT[(c4+1)*137 + r] = to_tf32(v.y);
        embT[(c4+2)*137 + r] = to_tf32(v.z);
        embT[(c4+3)*137 + r] = to_tf32(v.w);
    }
    for (int idx = tid; idx < 4*128; idx += 256) {
        int k = 100 + idx / 128, n = idx % 128;
        embT[k*137 + n] = 0.f;
    }
    __syncthreads();

    int g = lane >> 2, tg = lane & 3;
    int mt = warp & 1;
    int nb = warp >> 1;
    const float* Arow = sel_s + mt*16*104;

    float acc[4][4];
    #pragma unroll
    for (int j = 0; j < 4; j++)
        #pragma unroll
        for (int q = 0; q < 4; q++) acc[j][q] = 0.f;

    #pragma unroll 1
    for (int kt = 0; kt < 13; kt++) {
        int ak = kt*8;
        uint32_t a0 = __float_as_uint(Arow[ g   *104 + ak + tg    ]);
        uint32_t a1 = __float_as_uint(Arow[(g+8)*104 + ak + tg    ]);
        uint32_t a2 = __float_as_uint(Arow[ g   *104 + ak + tg + 4]);
        uint32_t a3 = __float_as_uint(Arow[(g+8)*104 + ak + tg + 4]);
        #pragma unroll
        for (int j = 0; j < 4; j++) {
            int nt = nb*4 + j;
            uint32_t bb0 = __float_as_uint(embT[(ak + tg    )*137 + nt*8 + g]);
            uint32_t bb1 = __float_as_uint(embT[(ak + tg + 4)*137 + nt*8 + g]);
            asm volatile(
                "mma.sync.aligned.m16n8k8.row.col.f32.tf32.tf32.f32 "
                "{%0,%1,%2,%3}, {%4,%5,%6,%7}, {%8,%9}, {%0,%1,%2,%3};"
                : "+f"(acc[j][0]), "+f"(acc[j][1]), "+f"(acc[j][2]), "+f"(acc[j][3])
                : "r"(a0), "r"(a1), "r"(a2), "r"(a3), "r"(bb0), "r"(bb1));
        }
    }

    int row_lo = b0 + mt*16 + g;
    int row_hi = row_lo + 8;
    float rmax_lo = -3.0e38f, rmax_hi = -3.0e38f;
    #pragma unroll
    for (int j = 0; j < 4; j++) {
        int nt = nb*4 + j;
        int ncol = n0 + nt*8 + tg*2;
        if (ncol < NOUT) {
            out[(size_t)row_lo*NOUT + ncol] = acc[j][0];
            out[(size_t)row_hi*NOUT + ncol] = acc[j][2];
            rmax_lo = fmaxf(rmax_lo, acc[j][0]);
            rmax_hi = fmaxf(rmax_hi, acc[j][2]);
        }
        if (ncol + 1 < NOUT) {
            out[(size_t)row_lo*NOUT + ncol + 1] = acc[j][1];
            out[(size_t)row_hi*NOUT + ncol + 1] = acc[j][3];
            rmax_lo = fmaxf(rmax_lo, acc[j][1]);
            rmax_hi = fmaxf(rmax_hi, acc[j][3]);
        }
    }
    rmax_lo = fmaxf(rmax_lo, __shfl_xor_sync(0xffffffffu, rmax_lo, 1));
    rmax_lo = fmaxf(rmax_lo, __shfl_xor_sync(0xffffffffu, rmax_lo, 2));
    rmax_hi = fmaxf(rmax_hi, __shfl_xor_sync(0xffffffffu, rmax_hi, 1));
    rmax_hi = fmaxf(rmax_hi, __shfl_xor_sync(0xffffffffu, rmax_hi, 2));
    if (tg == 0) {
        atomicMax(&g_rmaxbits[row_lo], fkey(rmax_lo));
        atomicMax(&g_rmaxbits[row_hi], fkey(rmax_hi));
    }
}

// ---------------- K6b: per-chunk sum of exp ----------------
__global__ __launch_bounds__(256) void k_expsum(const float* __restrict__ out)
{
    int b = blockIdx.y, chunk = blockIdx.x, tid = threadIdx.x;
    int start = chunk * CHUNKSZ;
    int end = start + CHUNKSZ; if (end > NOUT) end = NOUT;
    float m = funkey(g_rmaxbits[b]);
    float s = 0.f;
    for (int n = start + tid; n < end; n += 256)
        s += fexp(out[(size_t)b*NOUT + n] - m);
    __shared__ float red[256];
    red[tid] = s;
    __syncthreads();
    for (int st = 128; st > 0; st >>= 1) {
        if (tid < st) red[tid] += red[tid + st];
        __syncthreads();
    }
    if (tid == 0) g_rpart[b*NCHUNK + chunk] = red[0];
}

// ---------------- K6c: exp + scale ----------------
__global__ __launch_bounds__(256) void k_scale(float* __restrict__ out)
{
    int b = blockIdx.y;
    int n = blockIdx.x * 256 + threadIdx.x;
    if (n < NOUT) {
        float ssum = 0.f;
        #pragma unroll
        for (int j = 0; j < NCHUNK; j++) ssum += g_rpart[b*NCHUNK + j];
        float m = funkey(g_rmaxbits[b]);
        float inv = __fdividef(1.f, ssum);
        size_t idx = (size_t)b*NOUT + n;
        out[idx] = fexp(out[idx] - m) * inv;
    }
}

// ---------------- launch ----------------
extern "C" void kernel_launch(void* const* d_in, const int* in_sizes, int n_in,
                              void* d_out, int out_size)
{
    const int*   alias_inputs = (const int*)  d_in[0];
    const int*   items        = (const int*)  d_in[1];
    const int*   adj          = (const int*)  d_in[2];
    const float* mask_item    = (const float*)d_in[3];
    const int*   seq_features = (const int*)  d_in[4];
    const int*   adj_all      = (const int*)  d_in[5];
    const float* num_w        = (const float*)d_in[6];
    const float* emb          = (const float*)d_in[7];
    const float* pos_emb      = (const float*)d_in[8];
    const float* a0           = (const float*)d_in[9];
    const float* a1           = (const float*)d_in[10];
    const float* a2           = (const float*)d_in[11];
    const float* a3           = (const float*)d_in[12];
    const float* g_w1         = (const float*)d_in[13];
    const float* g_w2         = (const float*)d_in[14];
    const float* g_w3         = (const float*)d_in[15];
    const float* w_1          = (const float*)d_in[16];
    const float* w_2          = (const float*)d_in[17];
    const float* glu1_w       = (const float*)d_in[18];
    const float* glu1_b       = (const float*)d_in[19];
    const float* glu2_w       = (const float*)d_in[20];
    const float* glu2_b       = (const float*)d_in[21];
    float* out = (float*)d_out;

    const int GSMEM = GT_TOT * 4;                  // ~86.3 KB
    const int CSMEM = CB_TOT * 4;                  // ~109.3 KB
    const int NSMEM = NH_TOT * 4;                  // ~106.5 KB
    const int SSMEM = SC_TOT * 4;                  // ~70.3 KB
    cudaFuncSetAttribute(k_global,  cudaFuncAttributeMaxDynamicSharedMemorySize, GSMEM);
    cudaFuncSetAttribute(k_combine, cudaFuncAttributeMaxDynamicSharedMemorySize, CSMEM);
    cudaFuncSetAttribute(k_nhsel,   cudaFuncAttributeMaxDynamicSharedMemorySize, NSMEM);
    cudaFuncSetAttribute(k_score,   cudaFuncAttributeMaxDynamicSharedMemorySize, SSMEM);

    k_init   <<<1, 256>>>();
    k_local  <<<Bn, 256>>>(items, adj, emb, a0, a1, a2, a3);
    k_sess   <<<Bn, 128>>>(seq_features, mask_item, emb);
    k_global <<<Bn*2, 256, GSMEM>>>(items, adj_all, num_w, emb, g_w1, g_w2);
    k_combine<<<(Bn*Ldim)/64, 256, CSMEM>>>(g_w3);
    k_seqhs  <<<Bn, 128>>>(alias_inputs, mask_item, glu2_w, glu2_b);
    k_nhsel  <<<(Bn*Ldim)/32, 256, NSMEM>>>(pos_emb, w_1, glu1_w, glu1_b, w_2, mask_item);
    dim3 gs((NOUT + 127)/128, Bn/32);
    k_score  <<<gs, 256, SSMEM>>>(emb, out);
    dim3 ge(NCHUNK, Bn);
    k_expsum <<<ge, 256>>>(out);
    dim3 gn((NOUT + 255)/256, Bn);
    k_scale  <<<gn, 256>>>(out);
}

// round 10
// speedup vs baseline: 2.0060x; 1.0229x over previous
#include <cuda_runtime.h>
#include <math.h>
#include <stdint.h>

#define Bn 256
#define Ldim 64
#define Sn 12
#define Dn 100
#define NUM_NODE 43098
#define NOUT 43097
#define NEGV -9000000000000000.0f
#define NCHUNK 8
#define CHUNKSZ 5388   // ceil(43097/8)

// ---------------- scratch (device globals; no allocation) ----------------
__device__ float g_h[Bn*Ldim*Dn];
__device__ float g_hlocal[Bn*Ldim*Dn];
__device__ float g_sess[Bn*Dn];
__device__ float g_nb[Bn*Ldim*Dn];
__device__ float g_hcomb[Bn*Ldim*Dn];
__device__ float g_seq[Bn*Ldim*Dn];
__device__ float g_hsg[Bn*Dn];
__device__ float g_selpart[2*Bn*Dn];
__device__ unsigned g_rmaxbits[Bn];
__device__ float g_rpart[Bn*NCHUNK];

__device__ __forceinline__ unsigned fkey(float f) {
    unsigned u = __float_as_uint(f);
    return (u & 0x80000000u) ? ~u : (u | 0x80000000u);
}
__device__ __forceinline__ float funkey(unsigned k) {
    return (k & 0x80000000u) ? __uint_as_float(k ^ 0x80000000u)
                             : __uint_as_float(~k);
}

__device__ __forceinline__ float fexp(float x) {
    float y = x * 1.44269504088896340736f;
    y = fmaxf(y, -126.0f);
    float t = y + 12582912.0f;
    float i = t - 12582912.0f;
    float f = y - i;
    int ii = (int)i;
    float p = 1.54035303933816e-4f;
    p = fmaf(p, f, 1.33335581464284e-3f);
    p = fmaf(p, f, 9.61812910762848e-3f);
    p = fmaf(p, f, 5.55041086648216e-2f);
    p = fmaf(p, f, 2.40226506959101e-1f);
    p = fmaf(p, f, 6.93147180559945e-1f);
    p = fmaf(p, f, 1.0f);
    return p * __int_as_float((ii + 127) << 23);
}

__device__ __forceinline__ float to_tf32(float x) {
    uint32_t r;
    asm("cvt.rna.tf32.f32 %0, %1;" : "=r"(r) : "f"(x));
    return __uint_as_float(r);
}

// ---------------- K0 ----------------
__global__ void k_init() {
    int t = threadIdx.x;
    if (t < Bn) g_rmaxbits[t] = 0u;
}

// ---------------- K1: local graph attention (2 CTAs per batch row) ---------
__global__ __launch_bounds__(256) void k_local(
    const int* __restrict__ items, const int* __restrict__ adj,
    const float* __restrict__ emb,
    const float* __restrict__ a0, const float* __restrict__ a1,
    const float* __restrict__ a2, const float* __restrict__ a3)
{
    int b = blockIdx.x >> 1;
    int half = blockIdx.x & 1;
    int i0 = half * 32;
    __shared__ float hs[Ldim][101];
    __shared__ float alpha[32][Ldim+1];
    __shared__ float As[Dn][4];
    int tid = threadIdx.x;

    for (int i = tid; i < Dn; i += 256) {
        As[i][0] = a0[i]; As[i][1] = a1[i]; As[i][2] = a2[i]; As[i][3] = a3[i];
    }
    // load full hs; write only own half's rows to g_h
    for (int idx = tid; idx < Ldim*Dn; idx += 256) {
        int l = idx / Dn, d = idx % Dn;
        float v = emb[(size_t)items[b*Ldim + l]*Dn + d];
        hs[l][d] = v;
    }
    __syncthreads();
    for (int idx = tid; idx < 32*Dn; idx += 256) {
        int l = i0 + idx / Dn, d = idx % Dn;
        g_h[((size_t)b*Ldim + l)*Dn + d] = hs[l][d];
    }

    for (int p = tid; p < 32*Ldim; p += 256) {
        int il = p / Ldim, j = p % Ldim;
        int i = i0 + il;
        int a = adj[((size_t)b*Ldim + i)*Ldim + j];
        float val = NEGV;
        if (a >= 1 && a <= 4) {
            float acc = 0.f;
            int k = a - 1;
            for (int d = 0; d < Dn; d++)
                acc += hs[i][d] * hs[j][d] * As[d][k];
            val = acc > 0.f ? acc : 0.2f * acc;
        }
        alpha[il][j] = val;
    }
    __syncthreads();

    int warp = tid >> 5, lane = tid & 31;
    for (int il = warp; il < 32; il += 8) {
        float x0 = alpha[il][lane], x1 = alpha[il][lane+32];
        float m = fmaxf(x0, x1);
        #pragma unroll
        for (int o = 16; o > 0; o >>= 1) m = fmaxf(m, __shfl_xor_sync(0xffffffffu, m, o));
        float e0 = __expf(fmaxf(x0 - m, -87.f));
        float e1 = __expf(fmaxf(x1 - m, -87.f));
        float s = e0 + e1;
        #pragma unroll
        for (int o = 16; o > 0; o >>= 1) s += __shfl_xor_sync(0xffffffffu, s, o);
        float inv = 1.f / s;
        alpha[il][lane] = e0 * inv;
        alpha[il][lane+32] = e1 * inv;
    }
    __syncthreads();

    for (int idx = tid; idx < 32*Dn; idx += 256) {
        int il = idx / Dn, d = idx % Dn;
        float acc = 0.f;
        for (int j = 0; j < Ldim; j++) acc += alpha[il][j] * hs[j][d];
        g_hlocal[((size_t)b*Ldim + i0 + il)*Dn + d] = acc;
    }
}

// ---------------- K2: sess mean ----------------
__global__ __launch_bounds__(128) void k_sess(
    const int* __restrict__ seq_features, const float* __restrict__ mask,
    const float* __restrict__ emb)
{
    int b = blockIdx.x, tid = threadIdx.x;
    if (tid >= Dn) return;
    float acc = 0.f, msum = 0.f;
    for (int l = 0; l < Ldim; l++) {
        float mk = mask[b*Ldim + l];
        acc += emb[(size_t)seq_features[b*Ldim + l]*Dn + tid] * mk;
        msum += mk;
    }
    g_sess[b*Dn + tid] = acc / msum;
}

// ---------------- K3: global neighbor aggregation (tf32 mma; kt-outer) -----
#define GT_W1   0        // 104*104 = 10816
#define GT_FEAT 10816    // 96*108  = 10368
#define GT_W2   21184    // 104
#define GT_SESS 21288    // 100
#define GT_ALSC 21388    // 96
#define GT_NBR  21484    // 96 ints
#define GT_TOT  21580
__global__ __launch_bounds__(256, 2) void k_global(
    const int* __restrict__ items, const int* __restrict__ adj_all,
    const float* __restrict__ num_w, const float* __restrict__ emb,
    const float* __restrict__ g_w1, const float* __restrict__ g_w2)
{
    extern __shared__ float sm[];
    float* w1s   = sm + GT_W1;
    float* feat  = sm + GT_FEAT;
    float* w2s   = sm + GT_W2;
    float* sesss = sm + GT_SESS;
    float* alsc  = sm + GT_ALSC;
    int*   nbrs  = (int*)(sm + GT_NBR);

    int blk = blockIdx.x;
    int b = blk >> 1;
    int l0 = (blk & 1) * 32;
    int tid = threadIdx.x;
    int lane = tid & 31, warp = tid >> 5;

    for (int i = tid; i < 104*104; i += 256) w1s[i] = 0.f;
    if (tid < 104) w2s[tid] = (tid < Dn) ? g_w2[tid] : 0.f;
    if (tid < Dn) sesss[tid] = g_sess[b*Dn + tid];
    __syncthreads();
    for (int i = tid; i < 101*100; i += 256) {
        int k = i / 100, n = i % 100;
        float scale = (k < 100) ? sesss[k] : 1.f;
        w1s[k*104 + n] = to_tf32(g_w1[i] * scale);
    }
    __syncthreads();

    int g = lane >> 2, tg = lane & 3;

    for (int it = 0; it < 4; it++) {
        int lbase = l0 + it*8;
        if (tid < 96) {
            int l = tid / 12, s = tid % 12;
            int node = items[b*Ldim + lbase + l];
            nbrs[tid] = adj_all[(size_t)node*Sn + s];
            feat[tid*108 + 100] = to_tf32(num_w[(size_t)node*Sn + s]);
            feat[tid*108 + 101] = 0.f;
            feat[tid*108 + 102] = 0.f;
            feat[tid*108 + 103] = 0.f;
        }
        __syncthreads();
        for (int idx = tid; idx < 96*25; idx += 256) {
            int r = idx / 25, c4 = (idx % 25) * 4;
            float4 e = *(const float4*)(emb + (size_t)nbrs[r]*Dn + c4);
            float* dst = feat + r*108 + c4;
            dst[0] = to_tf32(e.x);
            dst[1] = to_tf32(e.y);
            dst[2] = to_tf32(e.z);
            dst[3] = to_tf32(e.w);
        }
        __syncthreads();

        if (warp < 6) {
            const float* Ab = feat + warp*16*108;
            float acc[13][4];
            #pragma unroll
            for (int nt = 0; nt < 13; nt++)
                #pragma unroll
                for (int q = 0; q < 4; q++) acc[nt][q] = 0.f;

            #pragma unroll 1
            for (int kt = 0; kt < 13; kt++) {
                int ak = kt*8;
                uint32_t a0 = __float_as_uint(Ab[ g   *108 + ak + tg    ]);
                uint32_t a1 = __float_as_uint(Ab[(g+8)*108 + ak + tg    ]);
                uint32_t a2 = __float_as_uint(Ab[ g   *108 + ak + tg + 4]);
                uint32_t a3 = __float_as_uint(Ab[(g+8)*108 + ak + tg + 4]);
                const float* wrow0 = w1s + (ak + tg)*104;
                const float* wrow1 = w1s + (ak + tg + 4)*104;
                #pragma unroll
                for (int nt = 0; nt < 13; nt++) {
                    uint32_t b0 = __float_as_uint(wrow0[nt*8 + g]);
                    uint32_t b1 = __float_as_uint(wrow1[nt*8 + g]);
                    asm volatile(
                        "mma.sync.aligned.m16n8k8.row.col.f32.tf32.tf32.f32 "
                        "{%0,%1,%2,%3}, {%4,%5,%6,%7}, {%8,%9}, {%0,%1,%2,%3};"
                        : "+f"(acc[nt][0]), "+f"(acc[nt][1]), "+f"(acc[nt][2]), "+f"(acc[nt][3])
                        : "r"(a0), "r"(a1), "r"(a2), "r"(a3), "r"(b0), "r"(b1));
                }
            }

            float score_a = 0.f, score_b = 0.f;
            #pragma unroll
            for (int nt = 0; nt < 13; nt++) {
                int j0 = nt*8 + tg*2;
                float w20 = w2s[j0], w21 = w2s[j0+1];
                float v0 = acc[nt][0] > 0.f ? acc[nt][0] : 0.2f*acc[nt][0];
                float v1 = acc[nt][1] > 0.f ? acc[nt][1] : 0.2f*acc[nt][1];
                float v2 = acc[nt][2] > 0.f ? acc[nt][2] : 0.2f*acc[nt][2];
                float v3 = acc[nt][3] > 0.f ? acc[nt][3] : 0.2f*acc[nt][3];
                score_a = fmaf(v0, w20, fmaf(v1, w21, score_a));
                score_b = fmaf(v2, w20, fmaf(v3, w21, score_b));
            }
            score_a += __shfl_xor_sync(0xffffffffu, score_a, 1);
            score_a += __shfl_xor_sync(0xffffffffu, score_a, 2);
            score_b += __shfl_xor_sync(0xffffffffu, score_b, 1);
            score_b += __shfl_xor_sync(0xffffffffu, score_b, 2);
            if (tg == 0) {
                alsc[warp*16 + g]     = score_a;
                alsc[warp*16 + g + 8] = score_b;
            }
        }
        __syncthreads();

        if (tid < 8) {
            float* a = alsc + tid*12;
            float m = a[0];
            #pragma unroll
            for (int s = 1; s < Sn; s++) m = fmaxf(m, a[s]);
            float ssum = 0.f;
            float e[Sn];
            #pragma unroll
            for (int s = 0; s < Sn; s++) { e[s] = __expf(a[s] - m); ssum += e[s]; }
            float inv = 1.f / ssum;
            #pragma unroll
            for (int s = 0; s < Sn; s++) a[s] = e[s] * inv;
        }
        __syncthreads();

        for (int idx = tid; idx < 800; idx += 256) {
            int l = idx / 100, c = idx % 100;
            const float* fr = feat + (l*12)*108 + c;
            const float* al = alsc + l*12;
            float acc2 = 0.f;
            #pragma unroll
            for (int s = 0; s < Sn; s++)
                acc2 = fmaf(al[s], fr[s*108], acc2);
            g_nb[((size_t)b*Ldim + lbase + l)*Dn + c] = acc2;
        }
        __syncthreads();
    }
}

// ---------------- K4: h_combine = relu([h,nb]@g_w3) + h_local (tf32 mma) ----
#define CB_W3  0             // 200*104 = 20800
#define CB_INS 20800         // 32*204  = 6528
#define CB_TOT 27328
__global__ __launch_bounds__(256) void k_combine(const float* __restrict__ g_w3)
{
    extern __shared__ float sm[];
    float* w3s = sm + CB_W3;
    float* ins = sm + CB_INS;
    int tid = threadIdx.x;
    int lane = tid & 31, warp = tid >> 5;

    for (int i = tid; i < 200*104; i += 256) w3s[i] = 0.f;
    __syncthreads();
    for (int i = tid; i < 200*100; i += 256) {
        int k = i / 100, n = i % 100;
        w3s[k*104 + n] = to_tf32(g_w3[i]);
    }
    __syncthreads();

    int g = lane >> 2, tg = lane & 3;
    int mt = warp & 1;
    int ng = warp >> 1;

    for (int it = 0; it < 2; it++) {
        int row0 = blockIdx.x * 64 + it * 32;
        for (int idx = tid; idx < 32*25; idx += 256) {
            int r = idx / 25, c4 = (idx % 25) * 4;
            size_t row = row0 + r;
            float4 vh = *(const float4*)(g_h  + row*Dn + c4);
            float4 vn = *(const float4*)(g_nb + row*Dn + c4);
            float* d = ins + r*204;
            d[c4+0]   = to_tf32(vh.x); d[c4+1]   = to_tf32(vh.y);
            d[c4+2]   = to_tf32(vh.z); d[c4+3]   = to_tf32(vh.w);
            d[100+c4+0] = to_tf32(vn.x); d[100+c4+1] = to_tf32(vn.y);
            d[100+c4+2] = to_tf32(vn.z); d[100+c4+3] = to_tf32(vn.w);
        }
        if (tid < 32) {
            float* d = ins + tid*204 + 200;
            d[0] = 0.f; d[1] = 0.f; d[2] = 0.f; d[3] = 0.f;
        }
        __syncthreads();

        float acc[4][4];
        #pragma unroll
        for (int j = 0; j < 4; j++)
            #pragma unroll
            for (int q = 0; q < 4; q++) acc[j][q] = 0.f;

        const float* Arow = ins + mt*16*204;
        #pragma unroll 1
        for (int kt = 0; kt < 25; kt++) {
            int ak = kt*8;
            uint32_t a0 = __float_as_uint(Arow[ g   *204 + ak + tg    ]);
            uint32_t a1 = __float_as_uint(Arow[(g+8)*204 + ak + tg    ]);
            uint32_t a2 = __float_as_uint(Arow[ g   *204 + ak + tg + 4]);
            uint32_t a3 = __float_as_uint(Arow[(g+8)*204 + ak + tg + 4]);
            #pragma unroll
            for (int j = 0; j < 4; j++) {
                int nt = ng*4 + j;
                if (nt < 13) {
                    uint32_t b0 = __float_as_uint(w3s[(ak + tg    )*104 + nt*8 + g]);
                    uint32_t b1 = __float_as_uint(w3s[(ak + tg + 4)*104 + nt*8 + g]);
                    asm volatile(
                        "mma.sync.aligned.m16n8k8.row.col.f32.tf32.tf32.f32 "
                        "{%0,%1,%2,%3}, {%4,%5,%6,%7}, {%8,%9}, {%0,%1,%2,%3};"
                        : "+f"(acc[j][0]), "+f"(acc[j][1]), "+f"(acc[j][2]), "+f"(acc[j][3])
                        : "r"(a0), "r"(a1), "r"(a2), "r"(a3), "r"(b0), "r"(b1));
                }
            }
        }

        size_t row_lo = row0 + mt*16 + g;
        size_t row_hi = row_lo + 8;
        #pragma unroll
        for (int j = 0; j < 4; j++) {
            int nt = ng*4 + j;
            if (nt < 13) {
                int c = nt*8 + tg*2;
                if (c < 100) {
                    g_hcomb[row_lo*Dn + c] = g_hlocal[row_lo*Dn + c] + fmaxf(acc[j][0], 0.f);
                    g_hcomb[row_hi*Dn + c] = g_hlocal[row_hi*Dn + c] + fmaxf(acc[j][2], 0.f);
                }
                if (c + 1 < 100) {
                    g_hcomb[row_lo*Dn + c + 1] = g_hlocal[row_lo*Dn + c + 1] + fmaxf(acc[j][1], 0.f);
                    g_hcomb[row_hi*Dn + c + 1] = g_hlocal[row_hi*Dn + c + 1] + fmaxf(acc[j][3], 0.f);
                }
            }
        }
        __syncthreads();
    }
}

// ---------------- K5a: seq gather (parallel), hs, hsg ----------------
__global__ __launch_bounds__(256) void k_seqhs(
    const int* __restrict__ alias, const float* __restrict__ mask,
    const float* __restrict__ glu2_w, const float* __restrict__ glu2_b)
{
    int b = blockIdx.x, tid = threadIdx.x;
    __shared__ float seqs[Ldim][Dn];      // 25.6 KB
    __shared__ float hs_s[Dn];
    __shared__ int alias_s[Ldim];
    __shared__ float mk_s[Ldim];
    if (tid < Ldim) { alias_s[tid] = alias[b*Ldim + tid]; mk_s[tid] = mask[b*Ldim + tid]; }
    __syncthreads();
    // parallel gather + write g_seq
    for (int idx = tid; idx < Ldim*Dn; idx += 256) {
        int l = idx / Dn, c = idx % Dn;
        float v = g_hcomb[((size_t)b*Ldim + alias_s[l])*Dn + c];
        seqs[l][c] = v;
        g_seq[((size_t)b*Ldim + l)*Dn + c] = v;
    }
    __syncthreads();
    if (tid < Dn) {
        float acc = 0.f, msum = 0.f;
        for (int l = 0; l < Ldim; l++) {
            acc = fmaf(seqs[l][tid], mk_s[l], acc);
            msum += mk_s[l];
        }
        hs_s[tid] = acc / msum;
    }
    __syncthreads();
    if (tid < Dn) {
        float t = glu2_b[tid];
        for (int c = 0; c < Dn; c++) t = fmaf(hs_s[c], __ldg(&glu2_w[c*Dn + tid]), t);
        g_hsg[b*Dn + tid] = t;
    }
}

// ---------------- K5b: fused nh + GLU + select partial ----------------
#define NH_TOT (20000 + 6400 + 100 + 100 + 32)
__global__ __launch_bounds__(256) void k_nhsel(
    const float* __restrict__ pos_emb, const float* __restrict__ w_1,
    const float* __restrict__ glu1_w, const float* __restrict__ glu1_b,
    const float* __restrict__ w_2, const float* __restrict__ mask)
{
    extern __shared__ float sm[];
    float* w_s   = sm;             // 20000
    float* ins   = sm + 20000;     // 32 x 200
    float* hb_s  = sm + 26400;     // 100
    float* w2s   = sm + 26500;     // 100
    float* beta_s= sm + 26600;     // 32
    int tid = threadIdx.x;
    int row0 = blockIdx.x * 32;
    int b = row0 >> 6;
    int lbase = row0 & 63;

    for (int i = tid; i < 20000; i += 256) w_s[i] = w_1[i];
    for (int idx = tid; idx < 32*200; idx += 256) {
        int r = idx / 200, k = idx % 200;
        size_t row = row0 + r;
        int l = (int)(row % Ldim);
        ins[r*200 + k] = (k < 100) ? pos_emb[l*Dn + k] : g_seq[row*Dn + (k-100)];
    }
    if (tid < Dn) { hb_s[tid] = glu1_b[tid] + g_hsg[b*Dn + tid]; w2s[tid] = w_2[tid]; }
    __syncthreads();

    int lane = tid & 31, ty = tid >> 5;
    int r0 = ty * 4;

    // GEMM1: nh = tanh([pe,seq] @ w_1)
    {
        float acc[4][4] = {};
        for (int k = 0; k < 200; k++) {
            float w0 = w_s[k*100 + lane];
            float w1 = w_s[k*100 + lane + 32];
            float w2 = w_s[k*100 + lane + 64];
            float w3 = (lane < 4) ? w_s[k*100 + lane + 96] : 0.f;
            #pragma unroll
            for (int i = 0; i < 4; i++) {
                float a = ins[(r0+i)*200 + k];
                acc[i][0] = fmaf(a, w0, acc[i][0]);
                acc[i][1] = fmaf(a, w1, acc[i][1]);
                acc[i][2] = fmaf(a, w2, acc[i][2]);
                acc[i][3] = fmaf(a, w3, acc[i][3]);
            }
        }
        #pragma unroll
        for (int i = 0; i < 4; i++) {
            #pragma unroll
            for (int q = 0; q < 4; q++) {
                int c = lane + 32*q;
                if (c < 100) ins[(r0+i)*200 + c] = tanhf(acc[i][q]);
            }
        }
    }
    __syncthreads();
    for (int i = tid; i < 10000; i += 256) w_s[i] = glu1_w[i];
    __syncthreads();

    // GEMM2
    {
        float t[4][4];
        #pragma unroll
        for (int i = 0; i < 4; i++) {
            #pragma unroll
            for (int q = 0; q < 4; q++) {
                int c = lane + 32*q;
                t[i][q] = (c < 100) ? hb_s[c] : 0.f;
            }
        }
        for (int k = 0; k < 100; k++) {
            float w0 = w_s[k*100 + lane];
            float w1 = w_s[k*100 + lane + 32];
            float w2 = w_s[k*100 + lane + 64];
            float w3 = (lane < 4) ? w_s[k*100 + lane + 96] : 0.f;
            #pragma unroll
            for (int i = 0; i < 4; i++) {
                float a = ins[(r0+i)*200 + k];
                t[i][0] = fmaf(a, w0, t[i][0]);
                t[i][1] = fmaf(a, w1, t[i][1]);
                t[i][2] = fmaf(a, w2, t[i][2]);
                t[i][3] = fmaf(a, w3, t[i][3]);
            }
        }
        #pragma unroll
        for (int i = 0; i < 4; i++) {
            float s = 0.f;
            #pragma unroll
            for (int q = 0; q < 4; q++) {
                int c = lane + 32*q;
                if (c < 100) {
                    float sg = 1.f / (1.f + __expf(-t[i][q]));
                    s = fmaf(sg, w2s[c], s);
                }
            }
            #pragma unroll
            for (int o = 16; o > 0; o >>= 1) s += __shfl_xor_sync(0xffffffffu, s, o);
            if (lane == 0)
                beta_s[r0 + i] = s * mask[b*Ldim + lbase + r0 + i];
        }
    }
    __syncthreads();

    if (tid < Dn) {
        float sel = 0.f;
        #pragma unroll 8
        for (int r = 0; r < 32; r++)
            sel = fmaf(beta_s[r], ins[r*200 + 100 + tid], sel);
        g_selpart[blockIdx.x*Dn + tid] = sel;
    }
}

// ---------------- K6a: score = (selpart0+selpart1) @ emb[1:]^T (tf32 mma) ---
#define SC_EMBT 3328
#define SC_TOT  (3328 + 104*137)
__global__ __launch_bounds__(256) void k_score(
    const float* __restrict__ emb, float* __restrict__ out)
{
    extern __shared__ float sm[];
    float* sel_s = sm;
    float* embT  = sm + SC_EMBT;
    int n0 = blockIdx.x * 128, b0 = blockIdx.y * 32;
    int tid = threadIdx.x;
    int lane = tid & 31, warp = tid >> 5;

    for (int idx = tid; idx < 32*25; idx += 256) {
        int r = idx / 25, c4 = (idx % 25) * 4;
        int bb = b0 + r;
        float4 v0 = *(const float4*)(g_selpart + (2*bb)*Dn + c4);
        float4 v1 = *(const float4*)(g_selpart + (2*bb+1)*Dn + c4);
        float* d = sel_s + r*104 + c4;
        d[0] = to_tf32(v0.x + v1.x); d[1] = to_tf32(v0.y + v1.y);
        d[2] = to_tf32(v0.z + v1.z); d[3] = to_tf32(v0.w + v1.w);
    }
    if (tid < 32) {
        float* d = sel_s + tid*104 + 100;
        d[0] = 0.f; d[1] = 0.f; d[2] = 0.f; d[3] = 0.f;
    }
    for (int idx = tid; idx < 128*25; idx += 256) {
        int r = idx / 25, c4 = (idx % 25) * 4;
        int n = n0 + r;
        float4 v = make_float4(0.f,0.f,0.f,0.f);
        if (n < NOUT) v = *(const float4*)(emb + (size_t)(n + 1)*Dn + c4);
        embT[(c4+0)*137 + r] = to_tf32(v.x);
        embT[(c4+1)*137 + r] = to_tf32(v.y);
        embT[(c4+2)*137 + r] = to_tf32(v.z);
        embT[(c4+3)*137 + r] = to_tf32(v.w);
    }
    for (int idx = tid; idx < 4*128; idx += 256) {
        int k = 100 + idx / 128, n = idx % 128;
        embT[k*137 + n] = 0.f;
    }
    __syncthreads();

    int g = lane >> 2, tg = lane & 3;
    int mt = warp & 1;
    int nb = warp >> 1;
    const float* Arow = sel_s + mt*16*104;

    float acc[4][4];
    #pragma unroll
    for (int j = 0; j < 4; j++)
        #pragma unroll
        for (int q = 0; q < 4; q++) acc[j][q] = 0.f;

    #pragma unroll 1
    for (int kt = 0; kt < 13; kt++) {
        int ak = kt*8;
        uint32_t a0 = __float_as_uint(Arow[ g   *104 + ak + tg    ]);
        uint32_t a1 = __float_as_uint(Arow[(g+8)*104 + ak + tg    ]);
        uint32_t a2 = __float_as_uint(Arow[ g   *104 + ak + tg + 4]);
        uint32_t a3 = __float_as_uint(Arow[(g+8)*104 + ak + tg + 4]);
        #pragma unroll
        for (int j = 0; j < 4; j++) {
            int nt = nb*4 + j;
            uint32_t bb0 = __float_as_uint(embT[(ak + tg    )*137 + nt*8 + g]);
            uint32_t bb1 = __float_as_uint(embT[(ak + tg + 4)*137 + nt*8 + g]);
            asm volatile(
                "mma.sync.aligned.m16n8k8.row.col.f32.tf32.tf32.f32 "
                "{%0,%1,%2,%3}, {%4,%5,%6,%7}, {%8,%9}, {%0,%1,%2,%3};"
                : "+f"(acc[j][0]), "+f"(acc[j][1]), "+f"(acc[j][2]), "+f"(acc[j][3])
                : "r"(a0), "r"(a1), "r"(a2), "r"(a3), "r"(bb0), "r"(bb1));
        }
    }

    int row_lo = b0 + mt*16 + g;
    int row_hi = row_lo + 8;
    float rmax_lo = -3.0e38f, rmax_hi = -3.0e38f;
    #pragma unroll
    for (int j = 0; j < 4; j++) {
        int nt = nb*4 + j;
        int ncol = n0 + nt*8 + tg*2;
        if (ncol < NOUT) {
            out[(size_t)row_lo*NOUT + ncol] = acc[j][0];
            out[(size_t)row_hi*NOUT + ncol] = acc[j][2];
            rmax_lo = fmaxf(rmax_lo, acc[j][0]);
            rmax_hi = fmaxf(rmax_hi, acc[j][2]);
        }
        if (ncol + 1 < NOUT) {
            out[(size_t)row_lo*NOUT + ncol + 1] = acc[j][1];
            out[(size_t)row_hi*NOUT + ncol + 1] = acc[j][3];
            rmax_lo = fmaxf(rmax_lo, acc[j][1]);
            rmax_hi = fmaxf(rmax_hi, acc[j][3]);
        }
    }
    rmax_lo = fmaxf(rmax_lo, __shfl_xor_sync(0xffffffffu, rmax_lo, 1));
    rmax_lo = fmaxf(rmax_lo, __shfl_xor_sync(0xffffffffu, rmax_lo, 2));
    rmax_hi = fmaxf(rmax_hi, __shfl_xor_sync(0xffffffffu, rmax_hi, 1));
    rmax_hi = fmaxf(rmax_hi, __shfl_xor_sync(0xffffffffu, rmax_hi, 2));
    if (tg == 0) {
        atomicMax(&g_rmaxbits[row_lo], fkey(rmax_lo));
        atomicMax(&g_rmaxbits[row_hi], fkey(rmax_hi));
    }
}

// ---------------- K6b: per-chunk sum of exp ----------------
__global__ __launch_bounds__(256) void k_expsum(const float* __restrict__ out)
{
    int b = blockIdx.y, chunk = blockIdx.x, tid = threadIdx.x;
    int start = chunk * CHUNKSZ;
    int end = start + CHUNKSZ; if (end > NOUT) end = NOUT;
    float m = funkey(g_rmaxbits[b]);
    float s = 0.f;
    for (int n = start + tid; n < end; n += 256)
        s += fexp(out[(size_t)b*NOUT + n] - m);
    __shared__ float red[256];
    red[tid] = s;
    __syncthreads();
    for (int st = 128; st > 0; st >>= 1) {
        if (tid < st) red[tid] += red[tid + st];
        __syncthreads();
    }
    if (tid == 0) g_rpart[b*NCHUNK + chunk] = red[0];
}

// ---------------- K6c: exp + scale ----------------
__global__ __launch_bounds__(256) void k_scale(float* __restrict__ out)
{
    int b = blockIdx.y;
    int n = blockIdx.x * 256 + threadIdx.x;
    if (n < NOUT) {
        float ssum = 0.f;
        #pragma unroll
        for (int j = 0; j < NCHUNK; j++) ssum += g_rpart[b*NCHUNK + j];
        float m = funkey(g_rmaxbits[b]);
        float inv = __fdividef(1.f, ssum);
        size_t idx = (size_t)b*NOUT + n;
        out[idx] = fexp(out[idx] - m) * inv;
    }
}

// ---------------- launch ----------------
extern "C" void kernel_launch(void* const* d_in, const int* in_sizes, int n_in,
                              void* d_out, int out_size)
{
    const int*   alias_inputs = (const int*)  d_in[0];
    const int*   items        = (const int*)  d_in[1];
    const int*   adj          = (const int*)  d_in[2];
    const float* mask_item    = (const float*)d_in[3];
    const int*   seq_features = (const int*)  d_in[4];
    const int*   adj_all      = (const int*)  d_in[5];
    const float* num_w        = (const float*)d_in[6];
    const float* emb          = (const float*)d_in[7];
    const float* pos_emb      = (const float*)d_in[8];
    const float* a0           = (const float*)d_in[9];
    const float* a1           = (const float*)d_in[10];
    const float* a2           = (const float*)d_in[11];
    const float* a3           = (const float*)d_in[12];
    const float* g_w1         = (const float*)d_in[13];
    const float* g_w2         = (const float*)d_in[14];
    const float* g_w3         = (const float*)d_in[15];
    const float* w_1          = (const float*)d_in[16];
    const float* w_2          = (const float*)d_in[17];
    const float* glu1_w       = (const float*)d_in[18];
    const float* glu1_b       = (const float*)d_in[19];
    const float* glu2_w       = (const float*)d_in[20];
    const float* glu2_b       = (const float*)d_in[21];
    float* out = (float*)d_out;

    const int GSMEM = GT_TOT * 4;                  // ~86.3 KB
    const int CSMEM = CB_TOT * 4;                  // ~109.3 KB
    const int NSMEM = NH_TOT * 4;                  // ~106.5 KB
    const int SSMEM = SC_TOT * 4;                  // ~70.3 KB
    cudaFuncSetAttribute(k_global,  cudaFuncAttributeMaxDynamicSharedMemorySize, GSMEM);
    cudaFuncSetAttribute(k_combine, cudaFuncAttributeMaxDynamicSharedMemorySize, CSMEM);
    cudaFuncSetAttribute(k_nhsel,   cudaFuncAttributeMaxDynamicSharedMemorySize, NSMEM);
    cudaFuncSetAttribute(k_score,   cudaFuncAttributeMaxDynamicSharedMemorySize, SSMEM);

    k_init   <<<1, 256>>>();
    k_local  <<<Bn*2, 256>>>(items, adj, emb, a0, a1, a2, a3);
    k_sess   <<<Bn, 128>>>(seq_features, mask_item, emb);
    k_global <<<Bn*2, 256, GSMEM>>>(items, adj_all, num_w, emb, g_w1, g_w2);
    k_combine<<<(Bn*Ldim)/64, 256, CSMEM>>>(g_w3);
    k_seqhs  <<<Bn, 256>>>(alias_inputs, mask_item, glu2_w, glu2_b);
    k_nhsel  <<<(Bn*Ldim)/32, 256, NSMEM>>>(pos_emb, w_1, glu1_w, glu1_b, w_2, mask_item);
    dim3 gs((NOUT + 127)/128, Bn/32);
    k_score  <<<gs, 256, SSMEM>>>(emb, out);
    dim3 ge(NCHUNK, Bn);
    k_expsum <<<ge, 256>>>(out);
    dim3 gn((NOUT + 255)/256, Bn);
    k_scale  <<<gn, 256>>>(out);
}

// round 11
// speedup vs baseline: 2.0302x; 1.0121x over previous
#include <cuda_runtime.h>
#include <math.h>
#include <stdint.h>

#define Bn 256
#define Ldim 64
#define Sn 12
#define Dn 100
#define NUM_NODE 43098
#define NOUT 43097
#define NEGV -9000000000000000.0f
#define NCHUNK 8
#define CHUNKSZ 5388   // ceil(43097/8)

// ---------------- scratch (device globals; no allocation) ----------------
__device__ float g_h[Bn*Ldim*Dn];
__device__ float g_hlocal[Bn*Ldim*Dn];
__device__ float g_sess[Bn*Dn];
__device__ float g_nb[Bn*Ldim*Dn];
__device__ float g_hcomb[Bn*Ldim*Dn];
__device__ float g_seq[Bn*Ldim*Dn];
__device__ float g_hsg[Bn*Dn];
__device__ float g_selpart[2*Bn*Dn];
__device__ unsigned g_rmaxbits[Bn];
__device__ float g_rpart[Bn*NCHUNK];

__device__ __forceinline__ unsigned fkey(float f) {
    unsigned u = __float_as_uint(f);
    return (u & 0x80000000u) ? ~u : (u | 0x80000000u);
}
__device__ __forceinline__ float funkey(unsigned k) {
    return (k & 0x80000000u) ? __uint_as_float(k ^ 0x80000000u)
                             : __uint_as_float(~k);
}

__device__ __forceinline__ float fexp(float x) {
    float y = x * 1.44269504088896340736f;
    y = fmaxf(y, -126.0f);
    float t = y + 12582912.0f;
    float i = t - 12582912.0f;
    float f = y - i;
    int ii = (int)i;
    float p = 1.54035303933816e-4f;
    p = fmaf(p, f, 1.33335581464284e-3f);
    p = fmaf(p, f, 9.61812910762848e-3f);
    p = fmaf(p, f, 5.55041086648216e-2f);
    p = fmaf(p, f, 2.40226506959101e-1f);
    p = fmaf(p, f, 6.93147180559945e-1f);
    p = fmaf(p, f, 1.0f);
    return p * __int_as_float((ii + 127) << 23);
}

__device__ __forceinline__ float to_tf32(float x) {
    uint32_t r;
    asm("cvt.rna.tf32.f32 %0, %1;" : "=r"(r) : "f"(x));
    return __uint_as_float(r);
}

// ---------------- K0 ----------------
__global__ void k_init() {
    int t = threadIdx.x;
    if (t < Bn) g_rmaxbits[t] = 0u;
}

// ---------------- K1: local graph attention (2 CTAs per batch row) ---------
__global__ __launch_bounds__(256) void k_local(
    const int* __restrict__ items, const int* __restrict__ adj,
    const float* __restrict__ emb,
    const float* __restrict__ a0, const float* __restrict__ a1,
    const float* __restrict__ a2, const float* __restrict__ a3)
{
    int b = blockIdx.x >> 1;
    int half = blockIdx.x & 1;
    int i0 = half * 32;
    __shared__ float hs[Ldim][101];
    __shared__ float alpha[32][Ldim+1];
    __shared__ float As[Dn][4];
    int tid = threadIdx.x;

    for (int i = tid; i < Dn; i += 256) {
        As[i][0] = a0[i]; As[i][1] = a1[i]; As[i][2] = a2[i]; As[i][3] = a3[i];
    }
    for (int idx = tid; idx < Ldim*Dn; idx += 256) {
        int l = idx / Dn, d = idx % Dn;
        float v = emb[(size_t)items[b*Ldim + l]*Dn + d];
        hs[l][d] = v;
    }
    __syncthreads();
    for (int idx = tid; idx < 32*Dn; idx += 256) {
        int l = i0 + idx / Dn, d = idx % Dn;
        g_h[((size_t)b*Ldim + l)*Dn + d] = hs[l][d];
    }

    for (int p = tid; p < 32*Ldim; p += 256) {
        int il = p / Ldim, j = p % Ldim;
        int i = i0 + il;
        int a = adj[((size_t)b*Ldim + i)*Ldim + j];
        float val = NEGV;
        if (a >= 1 && a <= 4) {
            float acc = 0.f;
            int k = a - 1;
            for (int d = 0; d < Dn; d++)
                acc += hs[i][d] * hs[j][d] * As[d][k];
            val = acc > 0.f ? acc : 0.2f * acc;
        }
        alpha[il][j] = val;
    }
    __syncthreads();

    int warp = tid >> 5, lane = tid & 31;
    for (int il = warp; il < 32; il += 8) {
        float x0 = alpha[il][lane], x1 = alpha[il][lane+32];
        float m = fmaxf(x0, x1);
        #pragma unroll
        for (int o = 16; o > 0; o >>= 1) m = fmaxf(m, __shfl_xor_sync(0xffffffffu, m, o));
        float e0 = __expf(fmaxf(x0 - m, -87.f));
        float e1 = __expf(fmaxf(x1 - m, -87.f));
        float s = e0 + e1;
        #pragma unroll
        for (int o = 16; o > 0; o >>= 1) s += __shfl_xor_sync(0xffffffffu, s, o);
        float inv = 1.f / s;
        alpha[il][lane] = e0 * inv;
        alpha[il][lane+32] = e1 * inv;
    }
    __syncthreads();

    for (int idx = tid; idx < 32*Dn; idx += 256) {
        int il = idx / Dn, d = idx % Dn;
        float acc = 0.f;
        for (int j = 0; j < Ldim; j++) acc += alpha[il][j] * hs[j][d];
        g_hlocal[((size_t)b*Ldim + i0 + il)*Dn + d] = acc;
    }
}

// ---------------- K2: sess mean ----------------
__global__ __launch_bounds__(128) void k_sess(
    const int* __restrict__ seq_features, const float* __restrict__ mask,
    const float* __restrict__ emb)
{
    int b = blockIdx.x, tid = threadIdx.x;
    if (tid >= Dn) return;
    float acc = 0.f, msum = 0.f;
    for (int l = 0; l < Ldim; l++) {
        float mk = mask[b*Ldim + l];
        acc += emb[(size_t)seq_features[b*Ldim + l]*Dn + tid] * mk;
        msum += mk;
    }
    g_sess[b*Dn + tid] = acc / msum;
}

// ---------------- K3: global neighbor aggregation (tf32 mma; kt-outer) -----
#define GT_W1   0        // 104*104 = 10816
#define GT_FEAT 10816    // 96*108  = 10368
#define GT_W2   21184    // 104
#define GT_SESS 21288    // 100
#define GT_ALSC 21388    // 96
#define GT_NBR  21484    // 96 ints
#define GT_TOT  21580
__global__ __launch_bounds__(256, 2) void k_global(
    const int* __restrict__ items, const int* __restrict__ adj_all,
    const float* __restrict__ num_w, const float* __restrict__ emb,
    const float* __restrict__ g_w1, const float* __restrict__ g_w2)
{
    extern __shared__ float sm[];
    float* w1s   = sm + GT_W1;
    float* feat  = sm + GT_FEAT;
    float* w2s   = sm + GT_W2;
    float* sesss = sm + GT_SESS;
    float* alsc  = sm + GT_ALSC;
    int*   nbrs  = (int*)(sm + GT_NBR);

    int blk = blockIdx.x;
    int b = blk >> 1;
    int l0 = (blk & 1) * 32;
    int tid = threadIdx.x;
    int lane = tid & 31, warp = tid >> 5;

    for (int i = tid; i < 104*104; i += 256) w1s[i] = 0.f;
    if (tid < 104) w2s[tid] = (tid < Dn) ? g_w2[tid] : 0.f;
    if (tid < Dn) sesss[tid] = g_sess[b*Dn + tid];
    __syncthreads();
    for (int i = tid; i < 101*100; i += 256) {
        int k = i / 100, n = i % 100;
        float scale = (k < 100) ? sesss[k] : 1.f;
        w1s[k*104 + n] = to_tf32(g_w1[i] * scale);
    }
    __syncthreads();

    int g = lane >> 2, tg = lane & 3;

    for (int it = 0; it < 4; it++) {
        int lbase = l0 + it*8;
        // merged gather: nbrs staging + num_w + feat in one phase
        if (tid < 96) {
            int l = tid / 12, s = tid % 12;
            int node = items[b*Ldim + lbase + l];
            nbrs[tid] = adj_all[(size_t)node*Sn + s];
            feat[tid*108 + 100] = to_tf32(num_w[(size_t)node*Sn + s]);
            feat[tid*108 + 101] = 0.f;
            feat[tid*108 + 102] = 0.f;
            feat[tid*108 + 103] = 0.f;
        }
        for (int idx = tid; idx < 96*25; idx += 256) {
            int r = idx / 25, c4 = (idx % 25) * 4;
            int node = items[b*Ldim + lbase + r/12];          // L1 broadcast
            int nbr  = adj_all[(size_t)node*Sn + (r%12)];     // L1 broadcast
            float4 e = *(const float4*)(emb + (size_t)nbr*Dn + c4);
            float* dst = feat + r*108 + c4;
            dst[0] = to_tf32(e.x);
            dst[1] = to_tf32(e.y);
            dst[2] = to_tf32(e.z);
            dst[3] = to_tf32(e.w);
        }
        __syncthreads();

        if (warp < 6) {
            const float* Ab = feat + warp*16*108;
            float acc[13][4];
            #pragma unroll
            for (int nt = 0; nt < 13; nt++)
                #pragma unroll
                for (int q = 0; q < 4; q++) acc[nt][q] = 0.f;

            #pragma unroll 1
            for (int kt = 0; kt < 13; kt++) {
                int ak = kt*8;
                uint32_t a0 = __float_as_uint(Ab[ g   *108 + ak + tg    ]);
                uint32_t a1 = __float_as_uint(Ab[(g+8)*108 + ak + tg    ]);
                uint32_t a2 = __float_as_uint(Ab[ g   *108 + ak + tg + 4]);
                uint32_t a3 = __float_as_uint(Ab[(g+8)*108 + ak + tg + 4]);
                const float* wrow0 = w1s + (ak + tg)*104;
                const float* wrow1 = w1s + (ak + tg + 4)*104;
                #pragma unroll
                for (int nt = 0; nt < 13; nt++) {
                    uint32_t b0 = __float_as_uint(wrow0[nt*8 + g]);
                    uint32_t b1 = __float_as_uint(wrow1[nt*8 + g]);
                    asm volatile(
                        "mma.sync.aligned.m16n8k8.row.col.f32.tf32.tf32.f32 "
                        "{%0,%1,%2,%3}, {%4,%5,%6,%7}, {%8,%9}, {%0,%1,%2,%3};"
                        : "+f"(acc[nt][0]), "+f"(acc[nt][1]), "+f"(acc[nt][2]), "+f"(acc[nt][3])
                        : "r"(a0), "r"(a1), "r"(a2), "r"(a3), "r"(b0), "r"(b1));
                }
            }

            float score_a = 0.f, score_b = 0.f;
            #pragma unroll
            for (int nt = 0; nt < 13; nt++) {
                int j0 = nt*8 + tg*2;
                float w20 = w2s[j0], w21 = w2s[j0+1];
                float v0 = acc[nt][0] > 0.f ? acc[nt][0] : 0.2f*acc[nt][0];
                float v1 = acc[nt][1] > 0.f ? acc[nt][1] : 0.2f*acc[nt][1];
                float v2 = acc[nt][2] > 0.f ? acc[nt][2] : 0.2f*acc[nt][2];
                float v3 = acc[nt][3] > 0.f ? acc[nt][3] : 0.2f*acc[nt][3];
                score_a = fmaf(v0, w20, fmaf(v1, w21, score_a));
                score_b = fmaf(v2, w20, fmaf(v3, w21, score_b));
            }
            score_a += __shfl_xor_sync(0xffffffffu, score_a, 1);
            score_a += __shfl_xor_sync(0xffffffffu, score_a, 2);
            score_b += __shfl_xor_sync(0xffffffffu, score_b, 1);
            score_b += __shfl_xor_sync(0xffffffffu, score_b, 2);
            if (tg == 0) {
                alsc[warp*16 + g]     = score_a;
                alsc[warp*16 + g + 8] = score_b;
            }
        }
        __syncthreads();

        if (tid < 8) {
            float* a = alsc + tid*12;
            float m = a[0];
            #pragma unroll
            for (int s = 1; s < Sn; s++) m = fmaxf(m, a[s]);
            float ssum = 0.f;
            float e[Sn];
            #pragma unroll
            for (int s = 0; s < Sn; s++) { e[s] = __expf(a[s] - m); ssum += e[s]; }
            float inv = 1.f / ssum;
            #pragma unroll
            for (int s = 0; s < Sn; s++) a[s] = e[s] * inv;
        }
        __syncthreads();

        for (int idx = tid; idx < 800; idx += 256) {
            int l = idx / 100, c = idx % 100;
            const float* fr = feat + (l*12)*108 + c;
            const float* al = alsc + l*12;
            float acc2 = 0.f;
            #pragma unroll
            for (int s = 0; s < Sn; s++)
                acc2 = fmaf(al[s], fr[s*108], acc2);
            g_nb[((size_t)b*Ldim + lbase + l)*Dn + c] = acc2;
        }
        __syncthreads();
    }
}

// ---------------- K4: h_combine = relu([h,nb]@g_w3) + h_local (tf32 mma) ----
#define CB_W3  0             // 200*104 = 20800
#define CB_INS 20800         // 32*204  = 6528
#define CB_TOT 27328
__global__ __launch_bounds__(256) void k_combine(const float* __restrict__ g_w3)
{
    extern __shared__ float sm[];
    float* w3s = sm + CB_W3;
    float* ins = sm + CB_INS;
    int tid = threadIdx.x;
    int lane = tid & 31, warp = tid >> 5;

    for (int i = tid; i < 200*104; i += 256) w3s[i] = 0.f;
    __syncthreads();
    for (int i = tid; i < 200*100; i += 256) {
        int k = i / 100, n = i % 100;
        w3s[k*104 + n] = to_tf32(g_w3[i]);
    }
    __syncthreads();

    int g = lane >> 2, tg = lane & 3;
    int mt = warp & 1;
    int ng = warp >> 1;

    for (int it = 0; it < 2; it++) {
        int row0 = blockIdx.x * 64 + it * 32;
        for (int idx = tid; idx < 32*25; idx += 256) {
            int r = idx / 25, c4 = (idx % 25) * 4;
            size_t row = row0 + r;
            float4 vh = *(const float4*)(g_h  + row*Dn + c4);
            float4 vn = *(const float4*)(g_nb + row*Dn + c4);
            float* d = ins + r*204;
            d[c4+0]   = to_tf32(vh.x); d[c4+1]   = to_tf32(vh.y);
            d[c4+2]   = to_tf32(vh.z); d[c4+3]   = to_tf32(vh.w);
            d[100+c4+0] = to_tf32(vn.x); d[100+c4+1] = to_tf32(vn.y);
            d[100+c4+2] = to_tf32(vn.z); d[100+c4+3] = to_tf32(vn.w);
        }
        if (tid < 32) {
            float* d = ins + tid*204 + 200;
            d[0] = 0.f; d[1] = 0.f; d[2] = 0.f; d[3] = 0.f;
        }
        __syncthreads();

        float acc[4][4];
        #pragma unroll
        for (int j = 0; j < 4; j++)
            #pragma unroll
            for (int q = 0; q < 4; q++) acc[j][q] = 0.f;

        const float* Arow = ins + mt*16*204;
        #pragma unroll 1
        for (int kt = 0; kt < 25; kt++) {
            int ak = kt*8;
            uint32_t a0 = __float_as_uint(Arow[ g   *204 + ak + tg    ]);
            uint32_t a1 = __float_as_uint(Arow[(g+8)*204 + ak + tg    ]);
            uint32_t a2 = __float_as_uint(Arow[ g   *204 + ak + tg + 4]);
            uint32_t a3 = __float_as_uint(Arow[(g+8)*204 + ak + tg + 4]);
            #pragma unroll
            for (int j = 0; j < 4; j++) {
                int nt = ng*4 + j;
                if (nt < 13) {
                    uint32_t b0 = __float_as_uint(w3s[(ak + tg    )*104 + nt*8 + g]);
                    uint32_t b1 = __float_as_uint(w3s[(ak + tg + 4)*104 + nt*8 + g]);
                    asm volatile(
                        "mma.sync.aligned.m16n8k8.row.col.f32.tf32.tf32.f32 "
                        "{%0,%1,%2,%3}, {%4,%5,%6,%7}, {%8,%9}, {%0,%1,%2,%3};"
                        : "+f"(acc[j][0]), "+f"(acc[j][1]), "+f"(acc[j][2]), "+f"(acc[j][3])
                        : "r"(a0), "r"(a1), "r"(a2), "r"(a3), "r"(b0), "r"(b1));
                }
            }
        }

        size_t row_lo = row0 + mt*16 + g;
        size_t row_hi = row_lo + 8;
        #pragma unroll
        for (int j = 0; j < 4; j++) {
            int nt = ng*4 + j;
            if (nt < 13) {
                int c = nt*8 + tg*2;
                if (c < 100) {
                    g_hcomb[row_lo*Dn + c] = g_hlocal[row_lo*Dn + c] + fmaxf(acc[j][0], 0.f);
                    g_hcomb[row_hi*Dn + c] = g_hlocal[row_hi*Dn + c] + fmaxf(acc[j][2], 0.f);
                }
                if (c + 1 < 100) {
                    g_hcomb[row_lo*Dn + c + 1] = g_hlocal[row_lo*Dn + c + 1] + fmaxf(acc[j][1], 0.f);
                    g_hcomb[row_hi*Dn + c + 1] = g_hlocal[row_hi*Dn + c + 1] + fmaxf(acc[j][3], 0.f);
                }
            }
        }
        __syncthreads();
    }
}

// ---------------- K5a: seq gather (parallel), hs, hsg ----------------
__global__ __launch_bounds__(256) void k_seqhs(
    const int* __restrict__ alias, const float* __restrict__ mask,
    const float* __restrict__ glu2_w, const float* __restrict__ glu2_b)
{
    int b = blockIdx.x, tid = threadIdx.x;
    __shared__ float seqs[Ldim][Dn];
    __shared__ float hs_s[Dn];
    __shared__ int alias_s[Ldim];
    __shared__ float mk_s[Ldim];
    if (tid < Ldim) { alias_s[tid] = alias[b*Ldim + tid]; mk_s[tid] = mask[b*Ldim + tid]; }
    __syncthreads();
    for (int idx = tid; idx < Ldim*Dn; idx += 256) {
        int l = idx / Dn, c = idx % Dn;
        float v = g_hcomb[((size_t)b*Ldim + alias_s[l])*Dn + c];
        seqs[l][c] = v;
        g_seq[((size_t)b*Ldim + l)*Dn + c] = v;
    }
    __syncthreads();
    if (tid < Dn) {
        float acc = 0.f, msum = 0.f;
        for (int l = 0; l < Ldim; l++) {
            acc = fmaf(seqs[l][tid], mk_s[l], acc);
            msum += mk_s[l];
        }
        hs_s[tid] = acc / msum;
    }
    __syncthreads();
    if (tid < Dn) {
        float t = glu2_b[tid];
        for (int c = 0; c < Dn; c++) t = fmaf(hs_s[c], __ldg(&glu2_w[c*Dn + tid]), t);
        g_hsg[b*Dn + tid] = t;
    }
}

// ---------------- K5b: fused nh + GLU + select partial ----------------
#define NH_TOT (20000 + 6400 + 100 + 100 + 32)
__global__ __launch_bounds__(256) void k_nhsel(
    const float* __restrict__ pos_emb, const float* __restrict__ w_1,
    const float* __restrict__ glu1_w, const float* __restrict__ glu1_b,
    const float* __restrict__ w_2, const float* __restrict__ mask)
{
    extern __shared__ float sm[];
    float* w_s   = sm;             // 20000
    float* ins   = sm + 20000;     // 32 x 200
    float* hb_s  = sm + 26400;     // 100
    float* w2s   = sm + 26500;     // 100
    float* beta_s= sm + 26600;     // 32
    int tid = threadIdx.x;
    int row0 = blockIdx.x * 32;
    int b = row0 >> 6;
    int lbase = row0 & 63;

    for (int i = tid; i < 20000; i += 256) w_s[i] = w_1[i];
    for (int idx = tid; idx < 32*200; idx += 256) {
        int r = idx / 200, k = idx % 200;
        size_t row = row0 + r;
        int l = (int)(row % Ldim);
        ins[r*200 + k] = (k < 100) ? pos_emb[l*Dn + k] : g_seq[row*Dn + (k-100)];
    }
    if (tid < Dn) { hb_s[tid] = glu1_b[tid] + g_hsg[b*Dn + tid]; w2s[tid] = w_2[tid]; }
    __syncthreads();

    int lane = tid & 31, ty = tid >> 5;
    int r0 = ty * 4;

    {
        float acc[4][4] = {};
        for (int k = 0; k < 200; k++) {
            float w0 = w_s[k*100 + lane];
            float w1 = w_s[k*100 + lane + 32];
            float w2 = w_s[k*100 + lane + 64];
            float w3 = (lane < 4) ? w_s[k*100 + lane + 96] : 0.f;
            #pragma unroll
            for (int i = 0; i < 4; i++) {
                float a = ins[(r0+i)*200 + k];
                acc[i][0] = fmaf(a, w0, acc[i][0]);
                acc[i][1] = fmaf(a, w1, acc[i][1]);
                acc[i][2] = fmaf(a, w2, acc[i][2]);
                acc[i][3] = fmaf(a, w3, acc[i][3]);
            }
        }
        #pragma unroll
        for (int i = 0; i < 4; i++) {
            #pragma unroll
            for (int q = 0; q < 4; q++) {
                int c = lane + 32*q;
                if (c < 100) ins[(r0+i)*200 + c] = tanhf(acc[i][q]);
            }
        }
    }
    __syncthreads();
    for (int i = tid; i < 10000; i += 256) w_s[i] = glu1_w[i];
    __syncthreads();

    {
        float t[4][4];
        #pragma unroll
        for (int i = 0; i < 4; i++) {
            #pragma unroll
            for (int q = 0; q < 4; q++) {
                int c = lane + 32*q;
                t[i][q] = (c < 100) ? hb_s[c] : 0.f;
            }
        }
        for (int k = 0; k < 100; k++) {
            float w0 = w_s[k*100 + lane];
            float w1 = w_s[k*100 + lane + 32];
            float w2 = w_s[k*100 + lane + 64];
            float w3 = (lane < 4) ? w_s[k*100 + lane + 96] : 0.f;
            #pragma unroll
            for (int i = 0; i < 4; i++) {
                float a = ins[(r0+i)*200 + k];
                t[i][0] = fmaf(a, w0, t[i][0]);
                t[i][1] = fmaf(a, w1, t[i][1]);
                t[i][2] = fmaf(a, w2, t[i][2]);
                t[i][3] = fmaf(a, w3, t[i][3]);
            }
        }
        #pragma unroll
        for (int i = 0; i < 4; i++) {
            float s = 0.f;
            #pragma unroll
            for (int q = 0; q < 4; q++) {
                int c = lane + 32*q;
                if (c < 100) {
                    float sg = 1.f / (1.f + __expf(-t[i][q]));
                    s = fmaf(sg, w2s[c], s);
                }
            }
            #pragma unroll
            for (int o = 16; o > 0; o >>= 1) s += __shfl_xor_sync(0xffffffffu, s, o);
            if (lane == 0)
                beta_s[r0 + i] = s * mask[b*Ldim + lbase + r0 + i];
        }
    }
    __syncthreads();

    if (tid < Dn) {
        float sel = 0.f;
        #pragma unroll 8
        for (int r = 0; r < 32; r++)
            sel = fmaf(beta_s[r], ins[r*200 + 100 + tid], sel);
        g_selpart[blockIdx.x*Dn + tid] = sel;
    }
}

// ---------------- K6a: score (tf32 mma, row-major B direct loads) -----------
// smem: sel_s [32][104]; emb_s [128][104] row-major (no transpose)
#define SC_EMB  3328          // after sel_s 32*104
#define SC_TOT  (3328 + 128*104)   // 16640 floats
__global__ __launch_bounds__(256) void k_score(
    const float* __restrict__ emb, float* __restrict__ out)
{
    extern __shared__ float sm[];
    float* sel_s = sm;
    float* emb_s = sm + SC_EMB;
    int n0 = blockIdx.x * 128, b0 = blockIdx.y * 32;
    int tid = threadIdx.x;
    int lane = tid & 31, warp = tid >> 5;

    for (int idx = tid; idx < 32*25; idx += 256) {
        int r = idx / 25, c4 = (idx % 25) * 4;
        int bb = b0 + r;
        float4 v0 = *(const float4*)(g_selpart + (2*bb)*Dn + c4);
        float4 v1 = *(const float4*)(g_selpart + (2*bb+1)*Dn + c4);
        float* d = sel_s + r*104 + c4;
        d[0] = to_tf32(v0.x + v1.x); d[1] = to_tf32(v0.y + v1.y);
        d[2] = to_tf32(v0.z + v1.z); d[3] = to_tf32(v0.w + v1.w);
    }
    if (tid < 32) {
        float* d = sel_s + tid*104 + 100;
        d[0] = 0.f; d[1] = 0.f; d[2] = 0.f; d[3] = 0.f;
    }
    for (int idx = tid; idx < 128*25; idx += 256) {
        int r = idx / 25, c4 = (idx % 25) * 4;
        int n = n0 + r;
        float4 v = make_float4(0.f,0.f,0.f,0.f);
        if (n < NOUT) v = *(const float4*)(emb + (size_t)(n + 1)*Dn + c4);
        float* d = emb_s + r*104 + c4;
        d[0] = to_tf32(v.x); d[1] = to_tf32(v.y);
        d[2] = to_tf32(v.z); d[3] = to_tf32(v.w);
    }
    if (tid < 128) {
        float* d = emb_s + tid*104 + 100;
        d[0] = 0.f; d[1] = 0.f; d[2] = 0.f; d[3] = 0.f;
    }
    __syncthreads();

    int g = lane >> 2, tg = lane & 3;
    int mt = warp & 1;
    int nb = warp >> 1;
    const float* Arow = sel_s + mt*16*104;

    float acc[4][4];
    #pragma unroll
    for (int j = 0; j < 4; j++)
        #pragma unroll
        for (int q = 0; q < 4; q++) acc[j][q] = 0.f;

    #pragma unroll 1
    for (int kt = 0; kt < 13; kt++) {
        int ak = kt*8;
        uint32_t a0 = __float_as_uint(Arow[ g   *104 + ak + tg    ]);
        uint32_t a1 = __float_as_uint(Arow[(g+8)*104 + ak + tg    ]);
        uint32_t a2 = __float_as_uint(Arow[ g   *104 + ak + tg + 4]);
        uint32_t a3 = __float_as_uint(Arow[(g+8)*104 + ak + tg + 4]);
        #pragma unroll
        for (int j = 0; j < 4; j++) {
            int nt = nb*4 + j;
            // B[k][n] = emb_s[n*104 + k]  (direct row-major access, 2-way conflict)
            uint32_t bb0 = __float_as_uint(emb_s[(nt*8 + g)*104 + ak + tg    ]);
            uint32_t bb1 = __float_as_uint(emb_s[(nt*8 + g)*104 + ak + tg + 4]);
            asm volatile(
                "mma.sync.aligned.m16n8k8.row.col.f32.tf32.tf32.f32 "
                "{%0,%1,%2,%3}, {%4,%5,%6,%7}, {%8,%9}, {%0,%1,%2,%3};"
                : "+f"(acc[j][0]), "+f"(acc[j][1]), "+f"(acc[j][2]), "+f"(acc[j][3])
                : "r"(a0), "r"(a1), "r"(a2), "r"(a3), "r"(bb0), "r"(bb1));
        }
    }

    int row_lo = b0 + mt*16 + g;
    int row_hi = row_lo + 8;
    float rmax_lo = -3.0e38f, rmax_hi = -3.0e38f;
    #pragma unroll
    for (int j = 0; j < 4; j++) {
        int nt = nb*4 + j;
        int ncol = n0 + nt*8 + tg*2;
        if (ncol < NOUT) {
            out[(size_t)row_lo*NOUT + ncol] = acc[j][0];
            out[(size_t)row_hi*NOUT + ncol] = acc[j][2];
            rmax_lo = fmaxf(rmax_lo, acc[j][0]);
            rmax_hi = fmaxf(rmax_hi, acc[j][2]);
        }
        if (ncol + 1 < NOUT) {
            out[(size_t)row_lo*NOUT + ncol + 1] = acc[j][1];
            out[(size_t)row_hi*NOUT + ncol + 1] = acc[j][3];
            rmax_lo = fmaxf(rmax_lo, acc[j][1]);
            rmax_hi = fmaxf(rmax_hi, acc[j][3]);
        }
    }
    rmax_lo = fmaxf(rmax_lo, __shfl_xor_sync(0xffffffffu, rmax_lo, 1));
    rmax_lo = fmaxf(rmax_lo, __shfl_xor_sync(0xffffffffu, rmax_lo, 2));
    rmax_hi = fmaxf(rmax_hi, __shfl_xor_sync(0xffffffffu, rmax_hi, 1));
    rmax_hi = fmaxf(rmax_hi, __shfl_xor_sync(0xffffffffu, rmax_hi, 2));
    if (tg == 0) {
        atomicMax(&g_rmaxbits[row_lo], fkey(rmax_lo));
        atomicMax(&g_rmaxbits[row_hi], fkey(rmax_hi));
    }
}

// ---------------- K6b: per-chunk sum of exp ----------------
__global__ __launch_bounds__(256) void k_expsum(const float* __restrict__ out)
{
    int b = blockIdx.y, chunk = blockIdx.x, tid = threadIdx.x;
    int start = chunk * CHUNKSZ;
    int end = start + CHUNKSZ; if (end > NOUT) end = NOUT;
    float m = funkey(g_rmaxbits[b]);
    float s = 0.f;
    for (int n = start + tid; n < end; n += 256)
        s += fexp(out[(size_t)b*NOUT + n] - m);
    __shared__ float red[256];
    red[tid] = s;
    __syncthreads();
    for (int st = 128; st > 0; st >>= 1) {
        if (tid < st) red[tid] += red[tid + st];
        __syncthreads();
    }
    if (tid == 0) g_rpart[b*NCHUNK + chunk] = red[0];
}

// ---------------- K6c: exp + scale ----------------
__global__ __launch_bounds__(256) void k_scale(float* __restrict__ out)
{
    int b = blockIdx.y;
    int n = blockIdx.x * 256 + threadIdx.x;
    if (n < NOUT) {
        float ssum = 0.f;
        #pragma unroll
        for (int j = 0; j < NCHUNK; j++) ssum += g_rpart[b*NCHUNK + j];
        float m = funkey(g_rmaxbits[b]);
        float inv = __fdividef(1.f, ssum);
        size_t idx = (size_t)b*NOUT + n;
        out[idx] = fexp(out[idx] - m) * inv;
    }
}

// ---------------- launch ----------------
extern "C" void kernel_launch(void* const* d_in, const int* in_sizes, int n_in,
                              void* d_out, int out_size)
{
    const int*   alias_inputs = (const int*)  d_in[0];
    const int*   items        = (const int*)  d_in[1];
    const int*   adj          = (const int*)  d_in[2];
    const float* mask_item    = (const float*)d_in[3];
    const int*   seq_features = (const int*)  d_in[4];
    const int*   adj_all      = (const int*)  d_in[5];
    const float* num_w        = (const float*)d_in[6];
    const float* emb          = (const float*)d_in[7];
    const float* pos_emb      = (const float*)d_in[8];
    const float* a0           = (const float*)d_in[9];
    const float* a1           = (const float*)d_in[10];
    const float* a2           = (const float*)d_in[11];
    const float* a3           = (const float*)d_in[12];
    const float* g_w1         = (const float*)d_in[13];
    const float* g_w2         = (const float*)d_in[14];
    const float* g_w3         = (const float*)d_in[15];
    const float* w_1          = (const float*)d_in[16];
    const float* w_2          = (const float*)d_in[17];
    const float* glu1_w       = (const float*)d_in[18];
    const float* glu1_b       = (const float*)d_in[19];
    const float* glu2_w       = (const float*)d_in[20];
    const float* glu2_b       = (const float*)d_in[21];
    float* out = (float*)d_out;

    const int GSMEM = GT_TOT * 4;                  // ~86.3 KB
    const int CSMEM = CB_TOT * 4;                  // ~109.3 KB
    const int NSMEM = NH_TOT * 4;                  // ~106.5 KB
    const int SSMEM = SC_TOT * 4;                  // ~66.6 KB
    cudaFuncSetAttribute(k_global,  cudaFuncAttributeMaxDynamicSharedMemorySize, GSMEM);
    cudaFuncSetAttribute(k_combine, cudaFuncAttributeMaxDynamicSharedMemorySize, CSMEM);
    cudaFuncSetAttribute(k_nhsel,   cudaFuncAttributeMaxDynamicSharedMemorySize, NSMEM);
    cudaFuncSetAttribute(k_score,   cudaFuncAttributeMaxDynamicSharedMemorySize, SSMEM);

    k_init   <<<1, 256>>>();
    k_local  <<<Bn*2, 256>>>(items, adj, emb, a0, a1, a2, a3);
    k_sess   <<<Bn, 128>>>(seq_features, mask_item, emb);
    k_global <<<Bn*2, 256, GSMEM>>>(items, adj_all, num_w, emb, g_w1, g_w2);
    k_combine<<<(Bn*Ldim)/64, 256, CSMEM>>>(g_w3);
    k_seqhs  <<<Bn, 256>>>(alias_inputs, mask_item, glu2_w, glu2_b);
    k_nhsel  <<<(Bn*Ldim)/32, 256, NSMEM>>>(pos_emb, w_1, glu1_w, glu1_b, w_2, mask_item);
    dim3 gs((NOUT + 127)/128, Bn/32);
    k_score  <<<gs, 256, SSMEM>>>(emb, out);
    dim3 ge(NCHUNK, Bn);
    k_expsum <<<ge, 256>>>(out);
    dim3 gn((NOUT + 255)/256, Bn);
    k_scale  <<<gn, 256>>>(out);
}

// round 12
// speedup vs baseline: 2.1966x; 1.0820x over previous
#include <cuda_runtime.h>
#include <math.h>
#include <stdint.h>

#define Bn 256
#define Ldim 64
#define Sn 12
#define Dn 100
#define NUM_NODE 43098
#define NOUT 43097
#define NEGV -9000000000000000.0f
#define NCHUNK 8
#define CHUNKSZ 5388   // ceil(43097/8)

// ---------------- scratch (device globals; no allocation) ----------------
__device__ float g_h[Bn*Ldim*Dn];
__device__ float g_hlocal[Bn*Ldim*Dn];
__device__ float g_sess[Bn*Dn];
__device__ float g_nb[Bn*Ldim*Dn];
__device__ float g_hcomb[Bn*Ldim*Dn];
__device__ float g_seq[Bn*Ldim*Dn];
__device__ float g_hsg[Bn*Dn];
__device__ float g_selpart[2*Bn*Dn];
__device__ unsigned g_rmaxbits[Bn];
__device__ float g_rpart[Bn*NCHUNK];

__device__ __forceinline__ unsigned fkey(float f) {
    unsigned u = __float_as_uint(f);
    return (u & 0x80000000u) ? ~u : (u | 0x80000000u);
}
__device__ __forceinline__ float funkey(unsigned k) {
    return (k & 0x80000000u) ? __uint_as_float(k ^ 0x80000000u)
                             : __uint_as_float(~k);
}

__device__ __forceinline__ float fexp(float x) {
    float y = x * 1.44269504088896340736f;
    y = fmaxf(y, -126.0f);
    float t = y + 12582912.0f;
    float i = t - 12582912.0f;
    float f = y - i;
    int ii = (int)i;
    float p = 1.54035303933816e-4f;
    p = fmaf(p, f, 1.33335581464284e-3f);
    p = fmaf(p, f, 9.61812910762848e-3f);
    p = fmaf(p, f, 5.55041086648216e-2f);
    p = fmaf(p, f, 2.40226506959101e-1f);
    p = fmaf(p, f, 6.93147180559945e-1f);
    p = fmaf(p, f, 1.0f);
    return p * __int_as_float((ii + 127) << 23);
}

__device__ __forceinline__ float to_tf32(float x) {
    uint32_t r;
    asm("cvt.rna.tf32.f32 %0, %1;" : "=r"(r) : "f"(x));
    return __uint_as_float(r);
}

// ---------------- K0 ----------------
__global__ void k_init() {
    int t = threadIdx.x;
    if (t < Bn) g_rmaxbits[t] = 0u;
}

// ---------------- K1: local graph attention (float4, 2 CTAs/row) -----------
__global__ __launch_bounds__(256) void k_local(
    const int* __restrict__ items, const int* __restrict__ adj,
    const float* __restrict__ emb,
    const float* __restrict__ a0, const float* __restrict__ a1,
    const float* __restrict__ a2, const float* __restrict__ a3)
{
    int b = blockIdx.x >> 1;
    int half = blockIdx.x & 1;
    int i0 = half * 32;
    __shared__ float hs[Ldim][108];
    __shared__ float alpha[32][Ldim+1];
    __shared__ float At[4][108];
    int tid = threadIdx.x;

    for (int i = tid; i < Dn; i += 256) {
        At[0][i] = a0[i]; At[1][i] = a1[i]; At[2][i] = a2[i]; At[3][i] = a3[i];
    }
    for (int idx = tid; idx < Ldim*25; idx += 256) {
        int l = idx / 25, c4 = (idx % 25) * 4;
        float4 v = *(const float4*)(emb + (size_t)items[b*Ldim + l]*Dn + c4);
        *(float4*)(&hs[l][c4]) = v;
    }
    __syncthreads();
    for (int idx = tid; idx < 32*25; idx += 256) {
        int l = i0 + idx / 25, c4 = (idx % 25) * 4;
        *(float4*)(g_h + ((size_t)b*Ldim + l)*Dn + c4) = *(const float4*)(&hs[l][c4]);
    }

    for (int p = tid; p < 32*Ldim; p += 256) {
        int il = p >> 6, j = p & 63;
        int i = i0 + il;
        int a = adj[((size_t)b*Ldim + i)*Ldim + j];
        float val = NEGV;
        if (a >= 1 && a <= 4) {
            int k = a - 1;
            const float4* hi = (const float4*)hs[i];
            const float4* hj = (const float4*)hs[j];
            const float4* at = (const float4*)At[k];
            float acc = 0.f;
            #pragma unroll 5
            for (int d4 = 0; d4 < 25; d4++) {
                float4 x = hi[d4], y = hj[d4], w = at[d4];
                acc = fmaf(x.x*y.x, w.x, acc);
                acc = fmaf(x.y*y.y, w.y, acc);
                acc = fmaf(x.z*y.z, w.z, acc);
                acc = fmaf(x.w*y.w, w.w, acc);
            }
            val = acc > 0.f ? acc : 0.2f * acc;
        }
        alpha[il][j] = val;
    }
    __syncthreads();

    int warp = tid >> 5, lane = tid & 31;
    for (int il = warp; il < 32; il += 8) {
        float x0 = alpha[il][lane], x1 = alpha[il][lane+32];
        float m = fmaxf(x0, x1);
        #pragma unroll
        for (int o = 16; o > 0; o >>= 1) m = fmaxf(m, __shfl_xor_sync(0xffffffffu, m, o));
        float e0 = __expf(fmaxf(x0 - m, -87.f));
        float e1 = __expf(fmaxf(x1 - m, -87.f));
        float s = e0 + e1;
        #pragma unroll
        for (int o = 16; o > 0; o >>= 1) s += __shfl_xor_sync(0xffffffffu, s, o);
        float inv = 1.f / s;
        alpha[il][lane] = e0 * inv;
        alpha[il][lane+32] = e1 * inv;
    }
    __syncthreads();

    for (int idx = tid; idx < 32*25; idx += 256) {
        int il = idx / 25, c4 = (idx % 25) * 4;
        float ax = 0.f, ay = 0.f, az = 0.f, aw = 0.f;
        for (int j = 0; j < Ldim; j++) {
            float al = alpha[il][j];
            float4 v = *(const float4*)(&hs[j][c4]);
            ax = fmaf(al, v.x, ax);
            ay = fmaf(al, v.y, ay);
            az = fmaf(al, v.z, az);
            aw = fmaf(al, v.w, aw);
        }
        *(float4*)(g_hlocal + ((size_t)b*Ldim + i0 + il)*Dn + c4)
            = make_float4(ax, ay, az, aw);
    }
}

// ---------------- K2: sess mean ----------------
__global__ __launch_bounds__(128) void k_sess(
    const int* __restrict__ seq_features, const float* __restrict__ mask,
    const float* __restrict__ emb)
{
    int b = blockIdx.x, tid = threadIdx.x;
    if (tid >= Dn) return;
    float acc = 0.f, msum = 0.f;
    for (int l = 0; l < Ldim; l++) {
        float mk = mask[b*Ldim + l];
        acc += emb[(size_t)seq_features[b*Ldim + l]*Dn + tid] * mk;
        msum += mk;
    }
    g_sess[b*Dn + tid] = acc / msum;
}

// ---------------- K3: global neighbor aggregation (tf32 mma; kt-outer) -----
#define GT_W1   0        // 104*104 = 10816
#define GT_FEAT 10816    // 96*108  = 10368
#define GT_W2   21184    // 104
#define GT_SESS 21288    // 100
#define GT_ALSC 21388    // 96
#define GT_NBR  21484    // 96 ints
#define GT_TOT  21580
__global__ __launch_bounds__(256, 2) void k_global(
    const int* __restrict__ items, const int* __restrict__ adj_all,
    const float* __restrict__ num_w, const float* __restrict__ emb,
    const float* __restrict__ g_w1, const float* __restrict__ g_w2)
{
    extern __shared__ float sm[];
    float* w1s   = sm + GT_W1;
    float* feat  = sm + GT_FEAT;
    float* w2s   = sm + GT_W2;
    float* sesss = sm + GT_SESS;
    float* alsc  = sm + GT_ALSC;
    int*   nbrs  = (int*)(sm + GT_NBR);

    int blk = blockIdx.x;
    int b = blk >> 1;
    int l0 = (blk & 1) * 32;
    int tid = threadIdx.x;
    int lane = tid & 31, warp = tid >> 5;

    for (int i = tid; i < 104*104; i += 256) w1s[i] = 0.f;
    if (tid < 104) w2s[tid] = (tid < Dn) ? g_w2[tid] : 0.f;
    if (tid < Dn) sesss[tid] = g_sess[b*Dn + tid];
    __syncthreads();
    for (int i = tid; i < 101*100; i += 256) {
        int k = i / 100, n = i % 100;
        float scale = (k < 100) ? sesss[k] : 1.f;
        w1s[k*104 + n] = to_tf32(g_w1[i] * scale);
    }
    __syncthreads();

    int g = lane >> 2, tg = lane & 3;

    for (int it = 0; it < 4; it++) {
        int lbase = l0 + it*8;
        if (tid < 96) {
            int l = tid / 12, s = tid % 12;
            int node = items[b*Ldim + lbase + l];
            nbrs[tid] = adj_all[(size_t)node*Sn + s];
            feat[tid*108 + 100] = to_tf32(num_w[(size_t)node*Sn + s]);
            feat[tid*108 + 101] = 0.f;
            feat[tid*108 + 102] = 0.f;
            feat[tid*108 + 103] = 0.f;
        }
        for (int idx = tid; idx < 96*25; idx += 256) {
            int r = idx / 25, c4 = (idx % 25) * 4;
            int node = items[b*Ldim + lbase + r/12];
            int nbr  = adj_all[(size_t)node*Sn + (r%12)];
            float4 e = *(const float4*)(emb + (size_t)nbr*Dn + c4);
            float* dst = feat + r*108 + c4;
            dst[0] = to_tf32(e.x);
            dst[1] = to_tf32(e.y);
            dst[2] = to_tf32(e.z);
            dst[3] = to_tf32(e.w);
        }
        __syncthreads();

        if (warp < 6) {
            const float* Ab = feat + warp*16*108;
            float acc[13][4];
            #pragma unroll
            for (int nt = 0; nt < 13; nt++)
                #pragma unroll
                for (int q = 0; q < 4; q++) acc[nt][q] = 0.f;

            #pragma unroll 1
            for (int kt = 0; kt < 13; kt++) {
                int ak = kt*8;
                uint32_t a0 = __float_as_uint(Ab[ g   *108 + ak + tg    ]);
                uint32_t a1 = __float_as_uint(Ab[(g+8)*108 + ak + tg    ]);
                uint32_t a2 = __float_as_uint(Ab[ g   *108 + ak + tg + 4]);
                uint32_t a3 = __float_as_uint(Ab[(g+8)*108 + ak + tg + 4]);
                const float* wrow0 = w1s + (ak + tg)*104;
                const float* wrow1 = w1s + (ak + tg + 4)*104;
                #pragma unroll
                for (int nt = 0; nt < 13; nt++) {
                    uint32_t b0 = __float_as_uint(wrow0[nt*8 + g]);
                    uint32_t b1 = __float_as_uint(wrow1[nt*8 + g]);
                    asm volatile(
                        "mma.sync.aligned.m16n8k8.row.col.f32.tf32.tf32.f32 "
                        "{%0,%1,%2,%3}, {%4,%5,%6,%7}, {%8,%9}, {%0,%1,%2,%3};"
                        : "+f"(acc[nt][0]), "+f"(acc[nt][1]), "+f"(acc[nt][2]), "+f"(acc[nt][3])
                        : "r"(a0), "r"(a1), "r"(a2), "r"(a3), "r"(b0), "r"(b1));
                }
            }

            float score_a = 0.f, score_b = 0.f;
            #pragma unroll
            for (int nt = 0; nt < 13; nt++) {
                int j0 = nt*8 + tg*2;
                float w20 = w2s[j0], w21 = w2s[j0+1];
                float v0 = acc[nt][0] > 0.f ? acc[nt][0] : 0.2f*acc[nt][0];
                float v1 = acc[nt][1] > 0.f ? acc[nt][1] : 0.2f*acc[nt][1];
                float v2 = acc[nt][2] > 0.f ? acc[nt][2] : 0.2f*acc[nt][2];
                float v3 = acc[nt][3] > 0.f ? acc[nt][3] : 0.2f*acc[nt][3];
                score_a = fmaf(v0, w20, fmaf(v1, w21, score_a));
                score_b = fmaf(v2, w20, fmaf(v3, w21, score_b));
            }
            score_a += __shfl_xor_sync(0xffffffffu, score_a, 1);
            score_a += __shfl_xor_sync(0xffffffffu, score_a, 2);
            score_b += __shfl_xor_sync(0xffffffffu, score_b, 1);
            score_b += __shfl_xor_sync(0xffffffffu, score_b, 2);
            if (tg == 0) {
                alsc[warp*16 + g]     = score_a;
                alsc[warp*16 + g + 8] = score_b;
            }
        }
        __syncthreads();

        if (tid < 8) {
            float* a = alsc + tid*12;
            float m = a[0];
            #pragma unroll
            for (int s = 1; s < Sn; s++) m = fmaxf(m, a[s]);
            float ssum = 0.f;
            float e[Sn];
            #pragma unroll
            for (int s = 0; s < Sn; s++) { e[s] = __expf(a[s] - m); ssum += e[s]; }
            float inv = 1.f / ssum;
            #pragma unroll
            for (int s = 0; s < Sn; s++) a[s] = e[s] * inv;
        }
        __syncthreads();

        for (int idx = tid; idx < 800; idx += 256) {
            int l = idx / 100, c = idx % 100;
            const float* fr = feat + (l*12)*108 + c;
            const float* al = alsc + l*12;
            float acc2 = 0.f;
            #pragma unroll
            for (int s = 0; s < Sn; s++)
                acc2 = fmaf(al[s], fr[s*108], acc2);
            g_nb[((size_t)b*Ldim + lbase + l)*Dn + c] = acc2;
        }
        __syncthreads();
    }
}

// ---------------- K4: h_combine = relu([h,nb]@g_w3) + h_local (tf32 mma) ----
#define CB_W3  0             // 200*104 = 20800
#define CB_INS 20800         // 32*204  = 6528
#define CB_TOT 27328
__global__ __launch_bounds__(256) void k_combine(const float* __restrict__ g_w3)
{
    extern __shared__ float sm[];
    float* w3s = sm + CB_W3;
    float* ins = sm + CB_INS;
    int tid = threadIdx.x;
    int lane = tid & 31, warp = tid >> 5;

    for (int i = tid; i < 200*104; i += 256) w3s[i] = 0.f;
    __syncthreads();
    for (int i = tid; i < 200*100; i += 256) {
        int k = i / 100, n = i % 100;
        w3s[k*104 + n] = to_tf32(g_w3[i]);
    }
    __syncthreads();

    int g = lane >> 2, tg = lane & 3;
    int mt = warp & 1;
    int ng = warp >> 1;

    for (int it = 0; it < 2; it++) {
        int row0 = blockIdx.x * 64 + it * 32;
        for (int idx = tid; idx < 32*25; idx += 256) {
            int r = idx / 25, c4 = (idx % 25) * 4;
            size_t row = row0 + r;
            float4 vh = *(const float4*)(g_h  + row*Dn + c4);
            float4 vn = *(const float4*)(g_nb + row*Dn + c4);
            float* d = ins + r*204;
            d[c4+0]   = to_tf32(vh.x); d[c4+1]   = to_tf32(vh.y);
            d[c4+2]   = to_tf32(vh.z); d[c4+3]   = to_tf32(vh.w);
            d[100+c4+0] = to_tf32(vn.x); d[100+c4+1] = to_tf32(vn.y);
            d[100+c4+2] = to_tf32(vn.z); d[100+c4+3] = to_tf32(vn.w);
        }
        if (tid < 32) {
            float* d = ins + tid*204 + 200;
            d[0] = 0.f; d[1] = 0.f; d[2] = 0.f; d[3] = 0.f;
        }
        __syncthreads();

        float acc[4][4];
        #pragma unroll
        for (int j = 0; j < 4; j++)
            #pragma unroll
            for (int q = 0; q < 4; q++) acc[j][q] = 0.f;

        const float* Arow = ins + mt*16*204;
        #pragma unroll 1
        for (int kt = 0; kt < 25; kt++) {
            int ak = kt*8;
            uint32_t a0 = __float_as_uint(Arow[ g   *204 + ak + tg    ]);
            uint32_t a1 = __float_as_uint(Arow[(g+8)*204 + ak + tg    ]);
            uint32_t a2 = __float_as_uint(Arow[ g   *204 + ak + tg + 4]);
            uint32_t a3 = __float_as_uint(Arow[(g+8)*204 + ak + tg + 4]);
            #pragma unroll
            for (int j = 0; j < 4; j++) {
                int nt = ng*4 + j;
                if (nt < 13) {
                    uint32_t b0 = __float_as_uint(w3s[(ak + tg    )*104 + nt*8 + g]);
                    uint32_t b1 = __float_as_uint(w3s[(ak + tg + 4)*104 + nt*8 + g]);
                    asm volatile(
                        "mma.sync.aligned.m16n8k8.row.col.f32.tf32.tf32.f32 "
                        "{%0,%1,%2,%3}, {%4,%5,%6,%7}, {%8,%9}, {%0,%1,%2,%3};"
                        : "+f"(acc[j][0]), "+f"(acc[j][1]), "+f"(acc[j][2]), "+f"(acc[j][3])
                        : "r"(a0), "r"(a1), "r"(a2), "r"(a3), "r"(b0), "r"(b1));
                }
            }
        }

        size_t row_lo = row0 + mt*16 + g;
        size_t row_hi = row_lo + 8;
        #pragma unroll
        for (int j = 0; j < 4; j++) {
            int nt = ng*4 + j;
            if (nt < 13) {
                int c = nt*8 + tg*2;
                if (c < 100) {
                    g_hcomb[row_lo*Dn + c] = g_hlocal[row_lo*Dn + c] + fmaxf(acc[j][0], 0.f);
                    g_hcomb[row_hi*Dn + c] = g_hlocal[row_hi*Dn + c] + fmaxf(acc[j][2], 0.f);
                }
                if (c + 1 < 100) {
                    g_hcomb[row_lo*Dn + c + 1] = g_hlocal[row_lo*Dn + c + 1] + fmaxf(acc[j][1], 0.f);
                    g_hcomb[row_hi*Dn + c + 1] = g_hlocal[row_hi*Dn + c + 1] + fmaxf(acc[j][3], 0.f);
                }
            }
        }
        __syncthreads();
    }
}

// ---------------- K5a: seq gather (parallel), hs, hsg ----------------
__global__ __launch_bounds__(256) void k_seqhs(
    const int* __restrict__ alias, const float* __restrict__ mask,
    const float* __restrict__ glu2_w, const float* __restrict__ glu2_b)
{
    int b = blockIdx.x, tid = threadIdx.x;
    __shared__ float seqs[Ldim][Dn];
    __shared__ float hs_s[Dn];
    __shared__ int alias_s[Ldim];
    __shared__ float mk_s[Ldim];
    if (tid < Ldim) { alias_s[tid] = alias[b*Ldim + tid]; mk_s[tid] = mask[b*Ldim + tid]; }
    __syncthreads();
    for (int idx = tid; idx < Ldim*Dn; idx += 256) {
        int l = idx / Dn, c = idx % Dn;
        float v = g_hcomb[((size_t)b*Ldim + alias_s[l])*Dn + c];
        seqs[l][c] = v;
        g_seq[((size_t)b*Ldim + l)*Dn + c] = v;
    }
    __syncthreads();
    if (tid < Dn) {
        float acc = 0.f, msum = 0.f;
        for (int l = 0; l < Ldim; l++) {
            acc = fmaf(seqs[l][tid], mk_s[l], acc);
            msum += mk_s[l];
        }
        hs_s[tid] = acc / msum;
    }
    __syncthreads();
    if (tid < Dn) {
        float t = glu2_b[tid];
        for (int c = 0; c < Dn; c++) t = fmaf(hs_s[c], __ldg(&glu2_w[c*Dn + tid]), t);
        g_hsg[b*Dn + tid] = t;
    }
}

// ---------------- K5b: fused nh + GLU + select (tf32 mma x2) ----------------
#define NS_WA   0        // 200*104 = 20800
#define NS_INS  20800    // 32*204  = 6528  -> 27328
#define NS_NH   27328    // 32*108  = 3456  -> 30784
#define NS_HB   30784    // 104
#define NS_W2   30888    // 104
#define NS_RED  30992    // 32*4 = 128
#define NS_BETA 31120    // 32
#define NS_TOT  31152
__global__ __launch_bounds__(256) void k_nhsel(
    const float* __restrict__ pos_emb, const float* __restrict__ w_1,
    const float* __restrict__ glu1_w, const float* __restrict__ glu1_b,
    const float* __restrict__ w_2, const float* __restrict__ mask)
{
    extern __shared__ float sm[];
    float* wA    = sm + NS_WA;
    float* ins   = sm + NS_INS;
    float* nh    = sm + NS_NH;
    float* hb_s  = sm + NS_HB;
    float* w2s   = sm + NS_W2;
    float* red   = sm + NS_RED;
    float* beta_s= sm + NS_BETA;
    int tid = threadIdx.x;
    int lane = tid & 31, warp = tid >> 5;
    int row0 = blockIdx.x * 32;
    int b = row0 >> 6;
    int lbase = row0 & 63;

    for (int i = tid; i < 200*104; i += 256) wA[i] = 0.f;
    if (tid < 104) {
        hb_s[tid] = (tid < Dn) ? glu1_b[tid] + g_hsg[b*Dn + tid] : 0.f;
        w2s[tid]  = (tid < Dn) ? w_2[tid] : 0.f;
    }
    __syncthreads();
    for (int i = tid; i < 200*100; i += 256) {
        int k = i / 100, n = i % 100;
        wA[k*104 + n] = to_tf32(w_1[i]);
    }
    for (int idx = tid; idx < 32*25; idx += 256) {
        int r = idx / 25, c4 = (idx % 25) * 4;
        size_t row = row0 + r;
        int l = (int)(row % Ldim);
        float4 vp = *(const float4*)(pos_emb + l*Dn + c4);
        float4 vs = *(const float4*)(g_seq + row*Dn + c4);
        float* d = ins + r*204;
        d[c4+0] = to_tf32(vp.x); d[c4+1] = to_tf32(vp.y);
        d[c4+2] = to_tf32(vp.z); d[c4+3] = to_tf32(vp.w);
        d[100+c4+0] = to_tf32(vs.x); d[100+c4+1] = to_tf32(vs.y);
        d[100+c4+2] = to_tf32(vs.z); d[100+c4+3] = to_tf32(vs.w);
    }
    if (tid < 32) {
        float* d = ins + tid*204 + 200;
        d[0] = 0.f; d[1] = 0.f; d[2] = 0.f; d[3] = 0.f;
        float* d2 = nh + tid*108 + 100;
        #pragma unroll
        for (int q = 0; q < 8; q++) d2[q] = 0.f;
    }
    __syncthreads();

    int g = lane >> 2, tg = lane & 3;
    int mt = warp & 1;
    int ng = warp >> 1;
    int rl = mt*16 + g, rh = rl + 8;   // local row ids in 0..31

    // GEMM1: [32 x 200] @ w_1 -> tanh -> nh
    {
        float acc[4][4];
        #pragma unroll
        for (int j = 0; j < 4; j++)
            #pragma unroll
            for (int q = 0; q < 4; q++) acc[j][q] = 0.f;
        const float* Arow = ins + mt*16*204;
        #pragma unroll 1
        for (int kt = 0; kt < 25; kt++) {
            int ak = kt*8;
            uint32_t a0 = __float_as_uint(Arow[ g   *204 + ak + tg    ]);
            uint32_t a1 = __float_as_uint(Arow[(g+8)*204 + ak + tg    ]);
            uint32_t a2 = __float_as_uint(Arow[ g   *204 + ak + tg + 4]);
            uint32_t a3 = __float_as_uint(Arow[(g+8)*204 + ak + tg + 4]);
            #pragma unroll
            for (int j = 0; j < 4; j++) {
                int nt = ng*4 + j;
                if (nt < 13) {
                    uint32_t b0 = __float_as_uint(wA[(ak + tg    )*104 + nt*8 + g]);
                    uint32_t b1 = __float_as_uint(wA[(ak + tg + 4)*104 + nt*8 + g]);
                    asm volatile(
                        "mma.sync.aligned.m16n8k8.row.col.f32.tf32.tf32.f32 "
                        "{%0,%1,%2,%3}, {%4,%5,%6,%7}, {%8,%9}, {%0,%1,%2,%3};"
                        : "+f"(acc[j][0]), "+f"(acc[j][1]), "+f"(acc[j][2]), "+f"(acc[j][3])
                        : "r"(a0), "r"(a1), "r"(a2), "r"(a3), "r"(b0), "r"(b1));
                }
            }
        }
        #pragma unroll
        for (int j = 0; j < 4; j++) {
            int nt = ng*4 + j;
            if (nt < 13) {
                int c = nt*8 + tg*2;
                if (c < 100) {
                    nh[rl*108 + c] = to_tf32(tanhf(acc[j][0]));
                    nh[rh*108 + c] = to_tf32(tanhf(acc[j][2]));
                }
                if (c + 1 < 100) {
                    nh[rl*108 + c + 1] = to_tf32(tanhf(acc[j][1]));
                    nh[rh*108 + c + 1] = to_tf32(tanhf(acc[j][3]));
                }
            }
        }
    }
    __syncthreads();
    // reload wA with glu1_w (rows 0..103 used by GEMM2)
    for (int i = tid; i < 104*104; i += 256) wA[i] = 0.f;
    __syncthreads();
    for (int i = tid; i < 100*100; i += 256) {
        int k = i / 100, n = i % 100;
        wA[k*104 + n] = to_tf32(glu1_w[i]);
    }
    __syncthreads();

    // GEMM2: t = nh @ glu1_w; sigmoid(t + hb); beta partials
    {
        float t[4][4];
        #pragma unroll
        for (int j = 0; j < 4; j++)
            #pragma unroll
            for (int q = 0; q < 4; q++) t[j][q] = 0.f;
        const float* A2 = nh + mt*16*108;
        #pragma unroll 1
        for (int kt = 0; kt < 13; kt++) {
            int ak = kt*8;
            uint32_t a0 = __float_as_uint(A2[ g   *108 + ak + tg    ]);
            uint32_t a1 = __float_as_uint(A2[(g+8)*108 + ak + tg    ]);
            uint32_t a2 = __float_as_uint(A2[ g   *108 + ak + tg + 4]);
            uint32_t a3 = __float_as_uint(A2[(g+8)*108 + ak + tg + 4]);
            #pragma unroll
            for (int j = 0; j < 4; j++) {
                int nt = ng*4 + j;
                if (nt < 13) {
                    uint32_t b0 = __float_as_uint(wA[(ak + tg    )*104 + nt*8 + g]);
                    uint32_t b1 = __float_as_uint(wA[(ak + tg + 4)*104 + nt*8 + g]);
                    asm volatile(
                        "mma.sync.aligned.m16n8k8.row.col.f32.tf32.tf32.f32 "
                        "{%0,%1,%2,%3}, {%4,%5,%6,%7}, {%8,%9}, {%0,%1,%2,%3};"
                        : "+f"(t[j][0]), "+f"(t[j][1]), "+f"(t[j][2]), "+f"(t[j][3])
                        : "r"(a0), "r"(a1), "r"(a2), "r"(a3), "r"(b0), "r"(b1));
                }
            }
        }
        float p_lo = 0.f, p_hi = 0.f;
        #pragma unroll
        for (int j = 0; j < 4; j++) {
            int nt = ng*4 + j;
            if (nt < 13) {
                int c = nt*8 + tg*2;
                if (c < 100) {
                    float s0 = 1.f / (1.f + __expf(-(t[j][0] + hb_s[c])));
                    float s2 = 1.f / (1.f + __expf(-(t[j][2] + hb_s[c])));
                    p_lo = fmaf(s0, w2s[c], p_lo);
                    p_hi = fmaf(s2, w2s[c], p_hi);
                }
                if (c + 1 < 100) {
                    float s1 = 1.f / (1.f + __expf(-(t[j][1] + hb_s[c+1])));
                    float s3 = 1.f / (1.f + __expf(-(t[j][3] + hb_s[c+1])));
                    p_lo = fmaf(s1, w2s[c+1], p_lo);
                    p_hi = fmaf(s3, w2s[c+1], p_hi);
                }
            }
        }
        p_lo += __shfl_xor_sync(0xffffffffu, p_lo, 1);
        p_lo += __shfl_xor_sync(0xffffffffu, p_lo, 2);
        p_hi += __shfl_xor_sync(0xffffffffu, p_hi, 1);
        p_hi += __shfl_xor_sync(0xffffffffu, p_hi, 2);
        if (tg == 0) {
            red[rl*4 + ng] = p_lo;
            red[rh*4 + ng] = p_hi;
        }
    }
    __syncthreads();
    if (tid < 32) {
        float s = red[tid*4] + red[tid*4+1] + red[tid*4+2] + red[tid*4+3];
        beta_s[tid] = s * mask[b*Ldim + lbase + tid];
    }
    __syncthreads();

    if (tid < Dn) {
        float sel = 0.f;
        #pragma unroll 8
        for (int r = 0; r < 32; r++)
            sel = fmaf(beta_s[r], ins[r*204 + 100 + tid], sel);
        g_selpart[blockIdx.x*Dn + tid] = sel;
    }
}

// ---------------- K6a: score (tf32 mma, row-major B direct loads) -----------
#define SC_EMB  3328
#define SC_TOT  (3328 + 128*104)
__global__ __launch_bounds__(256) void k_score(
    const float* __restrict__ emb, float* __restrict__ out)
{
    extern __shared__ float sm[];
    float* sel_s = sm;
    float* emb_s = sm + SC_EMB;
    int n0 = blockIdx.x * 128, b0 = blockIdx.y * 32;
    int tid = threadIdx.x;
    int lane = tid & 31, warp = tid >> 5;

    for (int idx = tid; idx < 32*25; idx += 256) {
        int r = idx / 25, c4 = (idx % 25) * 4;
        int bb = b0 + r;
        float4 v0 = *(const float4*)(g_selpart + (2*bb)*Dn + c4);
        float4 v1 = *(const float4*)(g_selpart + (2*bb+1)*Dn + c4);
        float* d = sel_s + r*104 + c4;
        d[0] = to_tf32(v0.x + v1.x); d[1] = to_tf32(v0.y + v1.y);
        d[2] = to_tf32(v0.z + v1.z); d[3] = to_tf32(v0.w + v1.w);
    }
    if (tid < 32) {
        float* d = sel_s + tid*104 + 100;
        d[0] = 0.f; d[1] = 0.f; d[2] = 0.f; d[3] = 0.f;
    }
    for (int idx = tid; idx < 128*25; idx += 256) {
        int r = idx / 25, c4 = (idx % 25) * 4;
        int n = n0 + r;
        float4 v = make_float4(0.f,0.f,0.f,0.f);
        if (n < NOUT) v = *(const float4*)(emb + (size_t)(n + 1)*Dn + c4);
        float* d = emb_s + r*104 + c4;
        d[0] = to_tf32(v.x); d[1] = to_tf32(v.y);
        d[2] = to_tf32(v.z); d[3] = to_tf32(v.w);
    }
    if (tid < 128) {
        float* d = emb_s + tid*104 + 100;
        d[0] = 0.f; d[1] = 0.f; d[2] = 0.f; d[3] = 0.f;
    }
    __syncthreads();

    int g = lane >> 2, tg = lane & 3;
    int mt = warp & 1;
    int nb = warp >> 1;
    const float* Arow = sel_s + mt*16*104;

    float acc[4][4];
    #pragma unroll
    for (int j = 0; j < 4; j++)
        #pragma unroll
        for (int q = 0; q < 4; q++) acc[j][q] = 0.f;

    #pragma unroll 1
    for (int kt = 0; kt < 13; kt++) {
        int ak = kt*8;
        uint32_t a0 = __float_as_uint(Arow[ g   *104 + ak + tg    ]);
        uint32_t a1 = __float_as_uint(Arow[(g+8)*104 + ak + tg    ]);
        uint32_t a2 = __float_as_uint(Arow[ g   *104 + ak + tg + 4]);
        uint32_t a3 = __float_as_uint(Arow[(g+8)*104 + ak + tg + 4]);
        #pragma unroll
        for (int j = 0; j < 4; j++) {
            int nt = nb*4 + j;
            uint32_t bb0 = __float_as_uint(emb_s[(nt*8 + g)*104 + ak + tg    ]);
            uint32_t bb1 = __float_as_uint(emb_s[(nt*8 + g)*104 + ak + tg + 4]);
            asm volatile(
                "mma.sync.aligned.m16n8k8.row.col.f32.tf32.tf32.f32 "
                "{%0,%1,%2,%3}, {%4,%5,%6,%7}, {%8,%9}, {%0,%1,%2,%3};"
                : "+f"(acc[j][0]), "+f"(acc[j][1]), "+f"(acc[j][2]), "+f"(acc[j][3])
                : "r"(a0), "r"(a1), "r"(a2), "r"(a3), "r"(bb0), "r"(bb1));
        }
    }

    int row_lo = b0 + mt*16 + g;
    int row_hi = row_lo + 8;
    float rmax_lo = -3.0e38f, rmax_hi = -3.0e38f;
    #pragma unroll
    for (int j = 0; j < 4; j++) {
        int nt = nb*4 + j;
        int ncol = n0 + nt*8 + tg*2;
        if (ncol < NOUT) {
            out[(size_t)row_lo*NOUT + ncol] = acc[j][0];
            out[(size_t)row_hi*NOUT + ncol] = acc[j][2];
            rmax_lo = fmaxf(rmax_lo, acc[j][0]);
            rmax_hi = fmaxf(rmax_hi, acc[j][2]);
        }
        if (ncol + 1 < NOUT) {
            out[(size_t)row_lo*NOUT + ncol + 1] = acc[j][1];
            out[(size_t)row_hi*NOUT + ncol + 1] = acc[j][3];
            rmax_lo = fmaxf(rmax_lo, acc[j][1]);
            rmax_hi = fmaxf(rmax_hi, acc[j][3]);
        }
    }
    rmax_lo = fmaxf(rmax_lo, __shfl_xor_sync(0xffffffffu, rmax_lo, 1));
    rmax_lo = fmaxf(rmax_lo, __shfl_xor_sync(0xffffffffu, rmax_lo, 2));
    rmax_hi = fmaxf(rmax_hi, __shfl_xor_sync(0xffffffffu, rmax_hi, 1));
    rmax_hi = fmaxf(rmax_hi, __shfl_xor_sync(0xffffffffu, rmax_hi, 2));
    if (tg == 0) {
        atomicMax(&g_rmaxbits[row_lo], fkey(rmax_lo));
        atomicMax(&g_rmaxbits[row_hi], fkey(rmax_hi));
    }
}

// ---------------- K6b: per-chunk sum of exp ----------------
__global__ __launch_bounds__(256) void k_expsum(const float* __restrict__ out)
{
    int b = blockIdx.y, chunk = blockIdx.x, tid = threadIdx.x;
    int start = chunk * CHUNKSZ;
    int end = start + CHUNKSZ; if (end > NOUT) end = NOUT;
    float m = funkey(g_rmaxbits[b]);
    float s = 0.f;
    for (int n = start + tid; n < end; n += 256)
        s += fexp(out[(size_t)b*NOUT + n] - m);
    __shared__ float red[256];
    red[tid] = s;
    __syncthreads();
    for (int st = 128; st > 0; st >>= 1) {
        if (tid < st) red[tid] += red[tid + st];
        __syncthreads();
    }
    if (tid == 0) g_rpart[b*NCHUNK + chunk] = red[0];
}

// ---------------- K6c: exp + scale ----------------
__global__ __launch_bounds__(256) void k_scale(float* __restrict__ out)
{
    int b = blockIdx.y;
    int n = blockIdx.x * 256 + threadIdx.x;
    if (n < NOUT) {
        float ssum = 0.f;
        #pragma unroll
        for (int j = 0; j < NCHUNK; j++) ssum += g_rpart[b*NCHUNK + j];
        float m = funkey(g_rmaxbits[b]);
        float inv = __fdividef(1.f, ssum);
        size_t idx = (size_t)b*NOUT + n;
        out[idx] = fexp(out[idx] - m) * inv;
    }
}

// ---------------- launch ----------------
extern "C" void kernel_launch(void* const* d_in, const int* in_sizes, int n_in,
                              void* d_out, int out_size)
{
    const int*   alias_inputs = (const int*)  d_in[0];
    const int*   items        = (const int*)  d_in[1];
    const int*   adj          = (const int*)  d_in[2];
    const float* mask_item    = (const float*)d_in[3];
    const int*   seq_features = (const int*)  d_in[4];
    const int*   adj_all      = (const int*)  d_in[5];
    const float* num_w        = (const float*)d_in[6];
    const float* emb          = (const float*)d_in[7];
    const float* pos_emb      = (const float*)d_in[8];
    const float* a0           = (const float*)d_in[9];
    const float* a1           = (const float*)d_in[10];
    const float* a2           = (const float*)d_in[11];
    const float* a3           = (const float*)d_in[12];
    const float* g_w1         = (const float*)d_in[13];
    const float* g_w2         = (const float*)d_in[14];
    const float* g_w3         = (const float*)d_in[15];
    const float* w_1          = (const float*)d_in[16];
    const float* w_2          = (const float*)d_in[17];
    const float* glu1_w       = (const float*)d_in[18];
    const float* glu1_b       = (const float*)d_in[19];
    const float* glu2_w       = (const float*)d_in[20];
    const float* glu2_b       = (const float*)d_in[21];
    float* out = (float*)d_out;

    const int GSMEM = GT_TOT * 4;                  // ~86.3 KB
    const int CSMEM = CB_TOT * 4;                  // ~109.3 KB
    const int NSMEM = NS_TOT * 4;                  // ~124.6 KB
    const int SSMEM = SC_TOT * 4;                  // ~66.6 KB
    cudaFuncSetAttribute(k_global,  cudaFuncAttributeMaxDynamicSharedMemorySize, GSMEM);
    cudaFuncSetAttribute(k_combine, cudaFuncAttributeMaxDynamicSharedMemorySize, CSMEM);
    cudaFuncSetAttribute(k_nhsel,   cudaFuncAttributeMaxDynamicSharedMemorySize, NSMEM);
    cudaFuncSetAttribute(k_score,   cudaFuncAttributeMaxDynamicSharedMemorySize, SSMEM);

    k_init   <<<1, 256>>>();
    k_local  <<<Bn*2, 256>>>(items, adj, emb, a0, a1, a2, a3);
    k_sess   <<<Bn, 128>>>(seq_features, mask_item, emb);
    k_global <<<Bn*2, 256, GSMEM>>>(items, adj_all, num_w, emb, g_w1, g_w2);
    k_combine<<<(Bn*Ldim)/64, 256, CSMEM>>>(g_w3);
    k_seqhs  <<<Bn, 256>>>(alias_inputs, mask_item, glu2_w, glu2_b);
    k_nhsel  <<<(Bn*Ldim)/32, 256, NSMEM>>>(pos_emb, w_1, glu1_w, glu1_b, w_2, mask_item);
    dim3 gs((NOUT + 127)/128, Bn/32);
    k_score  <<<gs, 256, SSMEM>>>(emb, out);
    dim3 ge(NCHUNK, Bn);
    k_expsum <<<ge, 256>>>(out);
    dim3 gn((NOUT + 255)/256, Bn);
    k_scale  <<<gn, 256>>>(out);
}

// round 13
// speedup vs baseline: 2.2836x; 1.0396x over previous
#include <cuda_runtime.h>
#include <math.h>
#include <stdint.h>

#define Bn 256
#define Ldim 64
#define Sn 12
#define Dn 100
#define NUM_NODE 43098
#define NOUT 43097
#define NEGV -9000000000000000.0f
#define NCHUNK 8
#define CHUNKSZ 5388   // ceil(43097/8)

// ---------------- scratch (device globals; no allocation) ----------------
__device__ float g_h[Bn*Ldim*Dn];
__device__ float g_hlocal[Bn*Ldim*Dn];
__device__ float g_nb[Bn*Ldim*Dn];
__device__ float g_hcomb[Bn*Ldim*Dn];
__device__ float g_seq[Bn*Ldim*Dn];
__device__ float g_hsg[Bn*Dn];
__device__ float g_selpart[2*Bn*Dn];
__device__ unsigned g_rmaxbits[Bn];
__device__ float g_rpart[Bn*NCHUNK];

__device__ __forceinline__ unsigned fkey(float f) {
    unsigned u = __float_as_uint(f);
    return (u & 0x80000000u) ? ~u : (u | 0x80000000u);
}
__device__ __forceinline__ float funkey(unsigned k) {
    return (k & 0x80000000u) ? __uint_as_float(k ^ 0x80000000u)
                             : __uint_as_float(~k);
}

__device__ __forceinline__ float fexp(float x) {
    float y = x * 1.44269504088896340736f;
    y = fmaxf(y, -126.0f);
    float t = y + 12582912.0f;
    float i = t - 12582912.0f;
    float f = y - i;
    int ii = (int)i;
    float p = 1.54035303933816e-4f;
    p = fmaf(p, f, 1.33335581464284e-3f);
    p = fmaf(p, f, 9.61812910762848e-3f);
    p = fmaf(p, f, 5.55041086648216e-2f);
    p = fmaf(p, f, 2.40226506959101e-1f);
    p = fmaf(p, f, 6.93147180559945e-1f);
    p = fmaf(p, f, 1.0f);
    return p * __int_as_float((ii + 127) << 23);
}

__device__ __forceinline__ float to_tf32(float x) {
    uint32_t r;
    asm("cvt.rna.tf32.f32 %0, %1;" : "=r"(r) : "f"(x));
    return __uint_as_float(r);
}

// ---------------- K0 ----------------
__global__ void k_init() {
    int t = threadIdx.x;
    if (t < Bn) g_rmaxbits[t] = 0u;
}

// ---------------- K1: local graph attention (float4, 2 CTAs/row) -----------
__global__ __launch_bounds__(256) void k_local(
    const int* __restrict__ items, const int* __restrict__ adj,
    const float* __restrict__ emb,
    const float* __restrict__ a0, const float* __restrict__ a1,
    const float* __restrict__ a2, const float* __restrict__ a3)
{
    int b = blockIdx.x >> 1;
    int half = blockIdx.x & 1;
    int i0 = half * 32;
    __shared__ float hs[Ldim][108];
    __shared__ float alpha[32][Ldim+1];
    __shared__ float At[4][108];
    int tid = threadIdx.x;

    for (int i = tid; i < Dn; i += 256) {
        At[0][i] = a0[i]; At[1][i] = a1[i]; At[2][i] = a2[i]; At[3][i] = a3[i];
    }
    for (int idx = tid; idx < Ldim*25; idx += 256) {
        int l = idx / 25, c4 = (idx % 25) * 4;
        float4 v = *(const float4*)(emb + (size_t)items[b*Ldim + l]*Dn + c4);
        *(float4*)(&hs[l][c4]) = v;
    }
    __syncthreads();
    for (int idx = tid; idx < 32*25; idx += 256) {
        int l = i0 + idx / 25, c4 = (idx % 25) * 4;
        *(float4*)(g_h + ((size_t)b*Ldim + l)*Dn + c4) = *(const float4*)(&hs[l][c4]);
    }

    for (int p = tid; p < 32*Ldim; p += 256) {
        int il = p >> 6, j = p & 63;
        int i = i0 + il;
        int a = adj[((size_t)b*Ldim + i)*Ldim + j];
        float val = NEGV;
        if (a >= 1 && a <= 4) {
            int k = a - 1;
            const float4* hi = (const float4*)hs[i];
            const float4* hj = (const float4*)hs[j];
            const float4* at = (const float4*)At[k];
            float acc = 0.f;
            #pragma unroll 5
            for (int d4 = 0; d4 < 25; d4++) {
                float4 x = hi[d4], y = hj[d4], w = at[d4];
                acc = fmaf(x.x*y.x, w.x, acc);
                acc = fmaf(x.y*y.y, w.y, acc);
                acc = fmaf(x.z*y.z, w.z, acc);
                acc = fmaf(x.w*y.w, w.w, acc);
            }
            val = acc > 0.f ? acc : 0.2f * acc;
        }
        alpha[il][j] = val;
    }
    __syncthreads();

    int warp = tid >> 5, lane = tid & 31;
    for (int il = warp; il < 32; il += 8) {
        float x0 = alpha[il][lane], x1 = alpha[il][lane+32];
        float m = fmaxf(x0, x1);
        #pragma unroll
        for (int o = 16; o > 0; o >>= 1) m = fmaxf(m, __shfl_xor_sync(0xffffffffu, m, o));
        float e0 = __expf(fmaxf(x0 - m, -87.f));
        float e1 = __expf(fmaxf(x1 - m, -87.f));
        float s = e0 + e1;
        #pragma unroll
        for (int o = 16; o > 0; o >>= 1) s += __shfl_xor_sync(0xffffffffu, s, o);
        float inv = 1.f / s;
        alpha[il][lane] = e0 * inv;
        alpha[il][lane+32] = e1 * inv;
    }
    __syncthreads();

    for (int idx = tid; idx < 32*25; idx += 256) {
        int il = idx / 25, c4 = (idx % 25) * 4;
        float ax = 0.f, ay = 0.f, az = 0.f, aw = 0.f;
        for (int j = 0; j < Ldim; j++) {
            float al = alpha[il][j];
            float4 v = *(const float4*)(&hs[j][c4]);
            ax = fmaf(al, v.x, ax);
            ay = fmaf(al, v.y, ay);
            az = fmaf(al, v.z, az);
            aw = fmaf(al, v.w, aw);
        }
        *(float4*)(g_hlocal + ((size_t)b*Ldim + i0 + il)*Dn + c4)
            = make_float4(ax, ay, az, aw);
    }
}

// ---------------- K3: global neighbor aggregation (tf32 mma; in-CTA sess) --
#define GT_W1   0        // 104*104 = 10816
#define GT_FEAT 10816    // 96*108  = 10368
#define GT_W2   21184    // 104
#define GT_SESS 21288    // 100
#define GT_ALSC 21388    // 96
#define GT_NBR  21484    // 96 ints
#define GT_TOT  21580
__global__ __launch_bounds__(256, 2) void k_global(
    const int* __restrict__ items, const int* __restrict__ adj_all,
    const float* __restrict__ num_w, const float* __restrict__ emb,
    const float* __restrict__ g_w1, const float* __restrict__ g_w2,
    const int* __restrict__ seq_features, const float* __restrict__ mask)
{
    extern __shared__ float sm[];
    float* w1s   = sm + GT_W1;
    float* feat  = sm + GT_FEAT;
    float* w2s   = sm + GT_W2;
    float* sesss = sm + GT_SESS;
    float* alsc  = sm + GT_ALSC;
    int*   nbrs  = (int*)(sm + GT_NBR);

    int blk = blockIdx.x;
    int b = blk >> 1;
    int l0 = (blk & 1) * 32;
    int tid = threadIdx.x;
    int lane = tid & 31, warp = tid >> 5;

    // phase 0: zero w1, stage seq_features gather into feat + mask into alsc
    for (int i = tid; i < 104*104; i += 256) w1s[i] = 0.f;
    if (tid < 104) w2s[tid] = (tid < Dn) ? g_w2[tid] : 0.f;
    if (tid < Ldim) alsc[tid] = mask[b*Ldim + tid];
    for (int idx = tid; idx < Ldim*25; idx += 256) {
        int r = idx / 25, c4 = (idx % 25) * 4;
        float4 v = *(const float4*)(emb + (size_t)seq_features[b*Ldim + r]*Dn + c4);
        *(float4*)(feat + r*108 + c4) = v;
    }
    __syncthreads();
    // phase 1: sess = masked mean
    if (tid < Dn) {
        float s = 0.f, ms = 0.f;
        for (int l = 0; l < Ldim; l++) {
            s = fmaf(feat[l*108 + tid], alsc[l], s);
            ms += alsc[l];
        }
        sesss[tid] = s / ms;
    }
    __syncthreads();
    // phase 2: w1 (sess-folded, tf32)
    for (int i = tid; i < 101*100; i += 256) {
        int k = i / 100, n = i % 100;
        float scale = (k < 100) ? sesss[k] : 1.f;
        w1s[k*104 + n] = to_tf32(g_w1[i] * scale);
    }
    __syncthreads();

    int g = lane >> 2, tg = lane & 3;

    for (int it = 0; it < 4; it++) {
        int lbase = l0 + it*8;
        if (tid < 96) {
            int l = tid / 12, s = tid % 12;
            int node = items[b*Ldim + lbase + l];
            nbrs[tid] = adj_all[(size_t)node*Sn + s];
            feat[tid*108 + 100] = to_tf32(num_w[(size_t)node*Sn + s]);
            feat[tid*108 + 101] = 0.f;
            feat[tid*108 + 102] = 0.f;
            feat[tid*108 + 103] = 0.f;
        }
        for (int idx = tid; idx < 96*25; idx += 256) {
            int r = idx / 25, c4 = (idx % 25) * 4;
            int node = items[b*Ldim + lbase + r/12];
            int nbr  = adj_all[(size_t)node*Sn + (r%12)];
            float4 e = *(const float4*)(emb + (size_t)nbr*Dn + c4);
            float* dst = feat + r*108 + c4;
            dst[0] = to_tf32(e.x);
            dst[1] = to_tf32(e.y);
            dst[2] = to_tf32(e.z);
            dst[3] = to_tf32(e.w);
        }
        __syncthreads();

        if (warp < 6) {
            const float* Ab = feat + warp*16*108;
            float acc[13][4];
            #pragma unroll
            for (int nt = 0; nt < 13; nt++)
                #pragma unroll
                for (int q = 0; q < 4; q++) acc[nt][q] = 0.f;

            #pragma unroll 1
            for (int kt = 0; kt < 13; kt++) {
                int ak = kt*8;
                uint32_t a0 = __float_as_uint(Ab[ g   *108 + ak + tg    ]);
                uint32_t a1 = __float_as_uint(Ab[(g+8)*108 + ak + tg    ]);
                uint32_t a2 = __float_as_uint(Ab[ g   *108 + ak + tg + 4]);
                uint32_t a3 = __float_as_uint(Ab[(g+8)*108 + ak + tg + 4]);
                const float* wrow0 = w1s + (ak + tg)*104;
                const float* wrow1 = w1s + (ak + tg + 4)*104;
                #pragma unroll
                for (int nt = 0; nt < 13; nt++) {
                    uint32_t b0 = __float_as_uint(wrow0[nt*8 + g]);
                    uint32_t b1 = __float_as_uint(wrow1[nt*8 + g]);
                    asm volatile(
                        "mma.sync.aligned.m16n8k8.row.col.f32.tf32.tf32.f32 "
                        "{%0,%1,%2,%3}, {%4,%5,%6,%7}, {%8,%9}, {%0,%1,%2,%3};"
                        : "+f"(acc[nt][0]), "+f"(acc[nt][1]), "+f"(acc[nt][2]), "+f"(acc[nt][3])
                        : "r"(a0), "r"(a1), "r"(a2), "r"(a3), "r"(b0), "r"(b1));
                }
            }

            float score_a = 0.f, score_b = 0.f;
            #pragma unroll
            for (int nt = 0; nt < 13; nt++) {
                int j0 = nt*8 + tg*2;
                float w20 = w2s[j0], w21 = w2s[j0+1];
                float v0 = acc[nt][0] > 0.f ? acc[nt][0] : 0.2f*acc[nt][0];
                float v1 = acc[nt][1] > 0.f ? acc[nt][1] : 0.2f*acc[nt][1];
                float v2 = acc[nt][2] > 0.f ? acc[nt][2] : 0.2f*acc[nt][2];
                float v3 = acc[nt][3] > 0.f ? acc[nt][3] : 0.2f*acc[nt][3];
                score_a = fmaf(v0, w20, fmaf(v1, w21, score_a));
                score_b = fmaf(v2, w20, fmaf(v3, w21, score_b));
            }
            score_a += __shfl_xor_sync(0xffffffffu, score_a, 1);
            score_a += __shfl_xor_sync(0xffffffffu, score_a, 2);
            score_b += __shfl_xor_sync(0xffffffffu, score_b, 1);
            score_b += __shfl_xor_sync(0xffffffffu, score_b, 2);
            if (tg == 0) {
                alsc[warp*16 + g]     = score_a;
                alsc[warp*16 + g + 8] = score_b;
            }
        }
        __syncthreads();

        if (tid < 8) {
            float* a = alsc + tid*12;
            float m = a[0];
            #pragma unroll
            for (int s = 1; s < Sn; s++) m = fmaxf(m, a[s]);
            float ssum = 0.f;
            float e[Sn];
            #pragma unroll
            for (int s = 0; s < Sn; s++) { e[s] = __expf(a[s] - m); ssum += e[s]; }
            float inv = 1.f / ssum;
            #pragma unroll
            for (int s = 0; s < Sn; s++) a[s] = e[s] * inv;
        }
        __syncthreads();

        for (int idx = tid; idx < 800; idx += 256) {
            int l = idx / 100, c = idx % 100;
            const float* fr = feat + (l*12)*108 + c;
            const float* al = alsc + l*12;
            float acc2 = 0.f;
            #pragma unroll
            for (int s = 0; s < Sn; s++)
                acc2 = fmaf(al[s], fr[s*108], acc2);
            g_nb[((size_t)b*Ldim + lbase + l)*Dn + c] = acc2;
        }
        __syncthreads();
    }
}

// ---------------- K4: h_combine = relu([h,nb]@g_w3) + h_local (tf32 mma) ----
#define CB_W3  0             // 200*104 = 20800
#define CB_INS 20800         // 32*204  = 6528
#define CB_TOT 27328
__global__ __launch_bounds__(256) void k_combine(const float* __restrict__ g_w3)
{
    extern __shared__ float sm[];
    float* w3s = sm + CB_W3;
    float* ins = sm + CB_INS;
    int tid = threadIdx.x;
    int lane = tid & 31, warp = tid >> 5;

    for (int i = tid; i < 200*104; i += 256) w3s[i] = 0.f;
    __syncthreads();
    for (int i = tid; i < 200*100; i += 256) {
        int k = i / 100, n = i % 100;
        w3s[k*104 + n] = to_tf32(g_w3[i]);
    }
    __syncthreads();

    int g = lane >> 2, tg = lane & 3;
    int mt = warp & 1;
    int ng = warp >> 1;

    for (int it = 0; it < 2; it++) {
        int row0 = blockIdx.x * 64 + it * 32;
        for (int idx = tid; idx < 32*25; idx += 256) {
            int r = idx / 25, c4 = (idx % 25) * 4;
            size_t row = row0 + r;
            float4 vh = *(const float4*)(g_h  + row*Dn + c4);
            float4 vn = *(const float4*)(g_nb + row*Dn + c4);
            float* d = ins + r*204;
            d[c4+0]   = to_tf32(vh.x); d[c4+1]   = to_tf32(vh.y);
            d[c4+2]   = to_tf32(vh.z); d[c4+3]   = to_tf32(vh.w);
            d[100+c4+0] = to_tf32(vn.x); d[100+c4+1] = to_tf32(vn.y);
            d[100+c4+2] = to_tf32(vn.z); d[100+c4+3] = to_tf32(vn.w);
        }
        if (tid < 32) {
            float* d = ins + tid*204 + 200;
            d[0] = 0.f; d[1] = 0.f; d[2] = 0.f; d[3] = 0.f;
        }
        __syncthreads();

        float acc[4][4];
        #pragma unroll
        for (int j = 0; j < 4; j++)
            #pragma unroll
            for (int q = 0; q < 4; q++) acc[j][q] = 0.f;

        const float* Arow = ins + mt*16*204;
        #pragma unroll 1
        for (int kt = 0; kt < 25; kt++) {
            int ak = kt*8;
            uint32_t a0 = __float_as_uint(Arow[ g   *204 + ak + tg    ]);
            uint32_t a1 = __float_as_uint(Arow[(g+8)*204 + ak + tg    ]);
            uint32_t a2 = __float_as_uint(Arow[ g   *204 + ak + tg + 4]);
            uint32_t a3 = __float_as_uint(Arow[(g+8)*204 + ak + tg + 4]);
            #pragma unroll
            for (int j = 0; j < 4; j++) {
                int nt = ng*4 + j;
                if (nt < 13) {
                    uint32_t b0 = __float_as_uint(w3s[(ak + tg    )*104 + nt*8 + g]);
                    uint32_t b1 = __float_as_uint(w3s[(ak + tg + 4)*104 + nt*8 + g]);
                    asm volatile(
                        "mma.sync.aligned.m16n8k8.row.col.f32.tf32.tf32.f32 "
                        "{%0,%1,%2,%3}, {%4,%5,%6,%7}, {%8,%9}, {%0,%1,%2,%3};"
                        : "+f"(acc[j][0]), "+f"(acc[j][1]), "+f"(acc[j][2]), "+f"(acc[j][3])
                        : "r"(a0), "r"(a1), "r"(a2), "r"(a3), "r"(b0), "r"(b1));
                }
            }
        }

        size_t row_lo = row0 + mt*16 + g;
        size_t row_hi = row_lo + 8;
        #pragma unroll
        for (int j = 0; j < 4; j++) {
            int nt = ng*4 + j;
            if (nt < 13) {
                int c = nt*8 + tg*2;
                if (c < 100) {
                    g_hcomb[row_lo*Dn + c] = g_hlocal[row_lo*Dn + c] + fmaxf(acc[j][0], 0.f);
                    g_hcomb[row_hi*Dn + c] = g_hlocal[row_hi*Dn + c] + fmaxf(acc[j][2], 0.f);
                }
                if (c + 1 < 100) {
                    g_hcomb[row_lo*Dn + c + 1] = g_hlocal[row_lo*Dn + c + 1] + fmaxf(acc[j][1], 0.f);
                    g_hcomb[row_hi*Dn + c + 1] = g_hlocal[row_hi*Dn + c + 1] + fmaxf(acc[j][3], 0.f);
                }
            }
        }
        __syncthreads();
    }
}

// ---------------- K5a: seq gather (parallel), hs, hsg ----------------
__global__ __launch_bounds__(256) void k_seqhs(
    const int* __restrict__ alias, const float* __restrict__ mask,
    const float* __restrict__ glu2_w, const float* __restrict__ glu2_b)
{
    int b = blockIdx.x, tid = threadIdx.x;
    __shared__ float seqs[Ldim][Dn];
    __shared__ float hs_s[Dn];
    __shared__ int alias_s[Ldim];
    __shared__ float mk_s[Ldim];
    if (tid < Ldim) { alias_s[tid] = alias[b*Ldim + tid]; mk_s[tid] = mask[b*Ldim + tid]; }
    __syncthreads();
    for (int idx = tid; idx < Ldim*Dn; idx += 256) {
        int l = idx / Dn, c = idx % Dn;
        float v = g_hcomb[((size_t)b*Ldim + alias_s[l])*Dn + c];
        seqs[l][c] = v;
        g_seq[((size_t)b*Ldim + l)*Dn + c] = v;
    }
    __syncthreads();
    if (tid < Dn) {
        float acc = 0.f, msum = 0.f;
        for (int l = 0; l < Ldim; l++) {
            acc = fmaf(seqs[l][tid], mk_s[l], acc);
            msum += mk_s[l];
        }
        hs_s[tid] = acc / msum;
    }
    __syncthreads();
    if (tid < Dn) {
        float t = glu2_b[tid];
        for (int c = 0; c < Dn; c++) t = fmaf(hs_s[c], __ldg(&glu2_w[c*Dn + tid]), t);
        g_hsg[b*Dn + tid] = t;
    }
}

// ---------------- K5b: fused nh + GLU + select (tf32 mma x2) ----------------
#define NS_WA   0        // 200*104 = 20800
#define NS_INS  20800    // 32*204  = 6528  -> 27328
#define NS_NH   27328    // 32*108  = 3456  -> 30784
#define NS_HB   30784    // 104
#define NS_W2   30888    // 104
#define NS_RED  30992    // 32*4 = 128
#define NS_BETA 31120    // 32
#define NS_TOT  31152
__global__ __launch_bounds__(256) void k_nhsel(
    const float* __restrict__ pos_emb, const float* __restrict__ w_1,
    const float* __restrict__ glu1_w, const float* __restrict__ glu1_b,
    const float* __restrict__ w_2, const float* __restrict__ mask)
{
    extern __shared__ float sm[];
    float* wA    = sm + NS_WA;
    float* ins   = sm + NS_INS;
    float* nh    = sm + NS_NH;
    float* hb_s  = sm + NS_HB;
    float* w2s   = sm + NS_W2;
    float* red   = sm + NS_RED;
    float* beta_s= sm + NS_BETA;
    int tid = threadIdx.x;
    int lane = tid & 31, warp = tid >> 5;
    int row0 = blockIdx.x * 32;
    int b = row0 >> 6;
    int lbase = row0 & 63;

    for (int i = tid; i < 200*104; i += 256) wA[i] = 0.f;
    if (tid < 104) {
        hb_s[tid] = (tid < Dn) ? glu1_b[tid] + g_hsg[b*Dn + tid] : 0.f;
        w2s[tid]  = (tid < Dn) ? w_2[tid] : 0.f;
    }
    __syncthreads();
    for (int i = tid; i < 200*100; i += 256) {
        int k = i / 100, n = i % 100;
        wA[k*104 + n] = to_tf32(w_1[i]);
    }
    for (int idx = tid; idx < 32*25; idx += 256) {
        int r = idx / 25, c4 = (idx % 25) * 4;
        size_t row = row0 + r;
        int l = (int)(row % Ldim);
        float4 vp = *(const float4*)(pos_emb + l*Dn + c4);
        float4 vs = *(const float4*)(g_seq + row*Dn + c4);
        float* d = ins + r*204;
        d[c4+0] = to_tf32(vp.x); d[c4+1] = to_tf32(vp.y);
        d[c4+2] = to_tf32(vp.z); d[c4+3] = to_tf32(vp.w);
        d[100+c4+0] = to_tf32(vs.x); d[100+c4+1] = to_tf32(vs.y);
        d[100+c4+2] = to_tf32(vs.z); d[100+c4+3] = to_tf32(vs.w);
    }
    if (tid < 32) {
        float* d = ins + tid*204 + 200;
        d[0] = 0.f; d[1] = 0.f; d[2] = 0.f; d[3] = 0.f;
        float* d2 = nh + tid*108 + 100;
        #pragma unroll
        for (int q = 0; q < 8; q++) d2[q] = 0.f;
    }
    __syncthreads();

    int g = lane >> 2, tg = lane & 3;
    int mt = warp & 1;
    int ng = warp >> 1;
    int rl = mt*16 + g, rh = rl + 8;

    // GEMM1: [32 x 200] @ w_1 -> tanh -> nh
    {
        float acc[4][4];
        #pragma unroll
        for (int j = 0; j < 4; j++)
            #pragma unroll
            for (int q = 0; q < 4; q++) acc[j][q] = 0.f;
        const float* Arow = ins + mt*16*204;
        #pragma unroll 1
        for (int kt = 0; kt < 25; kt++) {
            int ak = kt*8;
            uint32_t a0 = __float_as_uint(Arow[ g   *204 + ak + tg    ]);
            uint32_t a1 = __float_as_uint(Arow[(g+8)*204 + ak + tg    ]);
            uint32_t a2 = __float_as_uint(Arow[ g   *204 + ak + tg + 4]);
            uint32_t a3 = __float_as_uint(Arow[(g+8)*204 + ak + tg + 4]);
            #pragma unroll
            for (int j = 0; j < 4; j++) {
                int nt = ng*4 + j;
                if (nt < 13) {
                    uint32_t b0 = __float_as_uint(wA[(ak + tg    )*104 + nt*8 + g]);
                    uint32_t b1 = __float_as_uint(wA[(ak + tg + 4)*104 + nt*8 + g]);
                    asm volatile(
                        "mma.sync.aligned.m16n8k8.row.col.f32.tf32.tf32.f32 "
                        "{%0,%1,%2,%3}, {%4,%5,%6,%7}, {%8,%9}, {%0,%1,%2,%3};"
                        : "+f"(acc[j][0]), "+f"(acc[j][1]), "+f"(acc[j][2]), "+f"(acc[j][3])
                        : "r"(a0), "r"(a1), "r"(a2), "r"(a3), "r"(b0), "r"(b1));
                }
            }
        }
        #pragma unroll
        for (int j = 0; j < 4; j++) {
            int nt = ng*4 + j;
            if (nt < 13) {
                int c = nt*8 + tg*2;
                if (c < 100) {
                    nh[rl*108 + c] = to_tf32(tanhf(acc[j][0]));
                    nh[rh*108 + c] = to_tf32(tanhf(acc[j][2]));
                }
                if (c + 1 < 100) {
                    nh[rl*108 + c + 1] = to_tf32(tanhf(acc[j][1]));
                    nh[rh*108 + c + 1] = to_tf32(tanhf(acc[j][3]));
                }
            }
        }
    }
    __syncthreads();
    for (int i = tid; i < 104*104; i += 256) wA[i] = 0.f;
    __syncthreads();
    for (int i = tid; i < 100*100; i += 256) {
        int k = i / 100, n = i % 100;
        wA[k*104 + n] = to_tf32(glu1_w[i]);
    }
    __syncthreads();

    // GEMM2: t = nh @ glu1_w; sigmoid(t + hb); beta partials
    {
        float t[4][4];
        #pragma unroll
        for (int j = 0; j < 4; j++)
            #pragma unroll
            for (int q = 0; q < 4; q++) t[j][q] = 0.f;
        const float* A2 = nh + mt*16*108;
        #pragma unroll 1
        for (int kt = 0; kt < 13; kt++) {
            int ak = kt*8;
            uint32_t a0 = __float_as_uint(A2[ g   *108 + ak + tg    ]);
            uint32_t a1 = __float_as_uint(A2[(g+8)*108 + ak + tg    ]);
            uint32_t a2 = __float_as_uint(A2[ g   *108 + ak + tg + 4]);
            uint32_t a3 = __float_as_uint(A2[(g+8)*108 + ak + tg + 4]);
            #pragma unroll
            for (int j = 0; j < 4; j++) {
                int nt = ng*4 + j;
                if (nt < 13) {
                    uint32_t b0 = __float_as_uint(wA[(ak + tg    )*104 + nt*8 + g]);
                    uint32_t b1 = __float_as_uint(wA[(ak + tg + 4)*104 + nt*8 + g]);
                    asm volatile(
                        "mma.sync.aligned.m16n8k8.row.col.f32.tf32.tf32.f32 "
                        "{%0,%1,%2,%3}, {%4,%5,%6,%7}, {%8,%9}, {%0,%1,%2,%3};"
                        : "+f"(t[j][0]), "+f"(t[j][1]), "+f"(t[j][2]), "+f"(t[j][3])
                        : "r"(a0), "r"(a1), "r"(a2), "r"(a3), "r"(b0), "r"(b1));
                }
            }
        }
        float p_lo = 0.f, p_hi = 0.f;
        #pragma unroll
        for (int j = 0; j < 4; j++) {
            int nt = ng*4 + j;
            if (nt < 13) {
                int c = nt*8 + tg*2;
                if (c < 100) {
                    float s0 = 1.f / (1.f + __expf(-(t[j][0] + hb_s[c])));
                    float s2 = 1.f / (1.f + __expf(-(t[j][2] + hb_s[c])));
                    p_lo = fmaf(s0, w2s[c], p_lo);
                    p_hi = fmaf(s2, w2s[c], p_hi);
                }
                if (c + 1 < 100) {
                    float s1 = 1.f / (1.f + __expf(-(t[j][1] + hb_s[c+1])));
                    float s3 = 1.f / (1.f + __expf(-(t[j][3] + hb_s[c+1])));
                    p_lo = fmaf(s1, w2s[c+1], p_lo);
                    p_hi = fmaf(s3, w2s[c+1], p_hi);
                }
            }
        }
        p_lo += __shfl_xor_sync(0xffffffffu, p_lo, 1);
        p_lo += __shfl_xor_sync(0xffffffffu, p_lo, 2);
        p_hi += __shfl_xor_sync(0xffffffffu, p_hi, 1);
        p_hi += __shfl_xor_sync(0xffffffffu, p_hi, 2);
        if (tg == 0) {
            red[rl*4 + ng] = p_lo;
            red[rh*4 + ng] = p_hi;
        }
    }
    __syncthreads();
    if (tid < 32) {
        float s = red[tid*4] + red[tid*4+1] + red[tid*4+2] + red[tid*4+3];
        beta_s[tid] = s * mask[b*Ldim + lbase + tid];
    }
    __syncthreads();

    if (tid < Dn) {
        float sel = 0.f;
        #pragma unroll 8
        for (int r = 0; r < 32; r++)
            sel = fmaf(beta_s[r], ins[r*204 + 100 + tid], sel);
        g_selpart[blockIdx.x*Dn + tid] = sel;
    }
}

// ---------------- K6a: score (tf32 mma, row-major B direct loads) -----------
#define SC_EMB  3328
#define SC_TOT  (3328 + 128*104)
__global__ __launch_bounds__(256) void k_score(
    const float* __restrict__ emb, float* __restrict__ out)
{
    extern __shared__ float sm[];
    float* sel_s = sm;
    float* emb_s = sm + SC_EMB;
    int n0 = blockIdx.x * 128, b0 = blockIdx.y * 32;
    int tid = threadIdx.x;
    int lane = tid & 31, warp = tid >> 5;

    for (int idx = tid; idx < 32*25; idx += 256) {
        int r = idx / 25, c4 = (idx % 25) * 4;
        int bb = b0 + r;
        float4 v0 = *(const float4*)(g_selpart + (2*bb)*Dn + c4);
        float4 v1 = *(const float4*)(g_selpart + (2*bb+1)*Dn + c4);
        float* d = sel_s + r*104 + c4;
        d[0] = to_tf32(v0.x + v1.x); d[1] = to_tf32(v0.y + v1.y);
        d[2] = to_tf32(v0.z + v1.z); d[3] = to_tf32(v0.w + v1.w);
    }
    if (tid < 32) {
        float* d = sel_s + tid*104 + 100;
        d[0] = 0.f; d[1] = 0.f; d[2] = 0.f; d[3] = 0.f;
    }
    for (int idx = tid; idx < 128*25; idx += 256) {
        int r = idx / 25, c4 = (idx % 25) * 4;
        int n = n0 + r;
        float4 v = make_float4(0.f,0.f,0.f,0.f);
        if (n < NOUT) v = *(const float4*)(emb + (size_t)(n + 1)*Dn + c4);
        float* d = emb_s + r*104 + c4;
        d[0] = to_tf32(v.x); d[1] = to_tf32(v.y);
        d[2] = to_tf32(v.z); d[3] = to_tf32(v.w);
    }
    if (tid < 128) {
        float* d = emb_s + tid*104 + 100;
        d[0] = 0.f; d[1] = 0.f; d[2] = 0.f; d[3] = 0.f;
    }
    __syncthreads();

    int g = lane >> 2, tg = lane & 3;
    int mt = warp & 1;
    int nb = warp >> 1;
    const float* Arow = sel_s + mt*16*104;

    float acc[4][4];
    #pragma unroll
    for (int j = 0; j < 4; j++)
        #pragma unroll
        for (int q = 0; q < 4; q++) acc[j][q] = 0.f;

    #pragma unroll 1
    for (int kt = 0; kt < 13; kt++) {
        int ak = kt*8;
        uint32_t a0 = __float_as_uint(Arow[ g   *104 + ak + tg    ]);
        uint32_t a1 = __float_as_uint(Arow[(g+8)*104 + ak + tg    ]);
        uint32_t a2 = __float_as_uint(Arow[ g   *104 + ak + tg + 4]);
        uint32_t a3 = __float_as_uint(Arow[(g+8)*104 + ak + tg + 4]);
        #pragma unroll
        for (int j = 0; j < 4; j++) {
            int nt = nb*4 + j;
            uint32_t bb0 = __float_as_uint(emb_s[(nt*8 + g)*104 + ak + tg    ]);
            uint32_t bb1 = __float_as_uint(emb_s[(nt*8 + g)*104 + ak + tg + 4]);
            asm volatile(
                "mma.sync.aligned.m16n8k8.row.col.f32.tf32.tf32.f32 "
                "{%0,%1,%2,%3}, {%4,%5,%6,%7}, {%8,%9}, {%0,%1,%2,%3};"
                : "+f"(acc[j][0]), "+f"(acc[j][1]), "+f"(acc[j][2]), "+f"(acc[j][3])
                : "r"(a0), "r"(a1), "r"(a2), "r"(a3), "r"(bb0), "r"(bb1));
        }
    }

    int row_lo = b0 + mt*16 + g;
    int row_hi = row_lo + 8;
    float rmax_lo = -3.0e38f, rmax_hi = -3.0e38f;
    #pragma unroll
    for (int j = 0; j < 4; j++) {
        int nt = nb*4 + j;
        int ncol = n0 + nt*8 + tg*2;
        if (ncol < NOUT) {
            out[(size_t)row_lo*NOUT + ncol] = acc[j][0];
            out[(size_t)row_hi*NOUT + ncol] = acc[j][2];
            rmax_lo = fmaxf(rmax_lo, acc[j][0]);
            rmax_hi = fmaxf(rmax_hi, acc[j][2]);
        }
        if (ncol + 1 < NOUT) {
            out[(size_t)row_lo*NOUT + ncol + 1] = acc[j][1];
            out[(size_t)row_hi*NOUT + ncol + 1] = acc[j][3];
            rmax_lo = fmaxf(rmax_lo, acc[j][1]);
            rmax_hi = fmaxf(rmax_hi, acc[j][3]);
        }
    }
    rmax_lo = fmaxf(rmax_lo, __shfl_xor_sync(0xffffffffu, rmax_lo, 1));
    rmax_lo = fmaxf(rmax_lo, __shfl_xor_sync(0xffffffffu, rmax_lo, 2));
    rmax_hi = fmaxf(rmax_hi, __shfl_xor_sync(0xffffffffu, rmax_hi, 1));
    rmax_hi = fmaxf(rmax_hi, __shfl_xor_sync(0xffffffffu, rmax_hi, 2));
    if (tg == 0) {
        atomicMax(&g_rmaxbits[row_lo], fkey(rmax_lo));
        atomicMax(&g_rmaxbits[row_hi], fkey(rmax_hi));
    }
}

// ---------------- K6b: per-chunk sum of exp ----------------
__global__ __launch_bounds__(256) void k_expsum(const float* __restrict__ out)
{
    int b = blockIdx.y, chunk = blockIdx.x, tid = threadIdx.x;
    int start = chunk * CHUNKSZ;
    int end = start + CHUNKSZ; if (end > NOUT) end = NOUT;
    float m = funkey(g_rmaxbits[b]);
    float s = 0.f;
    for (int n = start + tid; n < end; n += 256)
        s += fexp(out[(size_t)b*NOUT + n] - m);
    __shared__ float red[256];
    red[tid] = s;
    __syncthreads();
    for (int st = 128; st > 0; st >>= 1) {
        if (tid < st) red[tid] += red[tid + st];
        __syncthreads();
    }
    if (tid == 0) g_rpart[b*NCHUNK + chunk] = red[0];
}

// ---------------- K6c: exp + scale ----------------
__global__ __launch_bounds__(256) void k_scale(float* __restrict__ out)
{
    int b = blockIdx.y;
    int n = blockIdx.x * 256 + threadIdx.x;
    if (n < NOUT) {
        float ssum = 0.f;
        #pragma unroll
        for (int j = 0; j < NCHUNK; j++) ssum += g_rpart[b*NCHUNK + j];
        float m = funkey(g_rmaxbits[b]);
        float inv = __fdividef(1.f, ssum);
        size_t idx = (size_t)b*NOUT + n;
        out[idx] = fexp(out[idx] - m) * inv;
    }
}

// ---------------- launch ----------------
extern "C" void kernel_launch(void* const* d_in, const int* in_sizes, int n_in,
                              void* d_out, int out_size)
{
    const int*   alias_inputs = (const int*)  d_in[0];
    const int*   items        = (const int*)  d_in[1];
    const int*   adj          = (const int*)  d_in[2];
    const float* mask_item    = (const float*)d_in[3];
    const int*   seq_features = (const int*)  d_in[4];
    const int*   adj_all      = (const int*)  d_in[5];
    const float* num_w        = (const float*)d_in[6];
    const float* emb          = (const float*)d_in[7];
    const float* pos_emb      = (const float*)d_in[8];
    const float* a0           = (const float*)d_in[9];
    const float* a1           = (const float*)d_in[10];
    const float* a2           = (const float*)d_in[11];
    const float* a3           = (const float*)d_in[12];
    const float* g_w1         = (const float*)d_in[13];
    const float* g_w2         = (const float*)d_in[14];
    const float* g_w3         = (const float*)d_in[15];
    const float* w_1          = (const float*)d_in[16];
    const float* w_2          = (const float*)d_in[17];
    const float* glu1_w       = (const float*)d_in[18];
    const float* glu1_b       = (const float*)d_in[19];
    const float* glu2_w       = (const float*)d_in[20];
    const float* glu2_b       = (const float*)d_in[21];
    float* out = (float*)d_out;

    static cudaStream_t s2 = nullptr;
    static cudaEvent_t ev_fork = nullptr, ev_join = nullptr;
    static bool attr_done = false;
    if (!s2) {
        cudaStreamCreateWithFlags(&s2, cudaStreamNonBlocking);
        cudaEventCreateWithFlags(&ev_fork, cudaEventDisableTiming);
        cudaEventCreateWithFlags(&ev_join, cudaEventDisableTiming);
    }

    const int GSMEM = GT_TOT * 4;                  // ~86.3 KB
    const int CSMEM = CB_TOT * 4;                  // ~109.3 KB
    const int NSMEM = NS_TOT * 4;                  // ~124.6 KB
    const int SSMEM = SC_TOT * 4;                  // ~66.6 KB
    if (!attr_done) {
        cudaFuncSetAttribute(k_global,  cudaFuncAttributeMaxDynamicSharedMemorySize, GSMEM);
        cudaFuncSetAttribute(k_combine, cudaFuncAttributeMaxDynamicSharedMemorySize, CSMEM);
        cudaFuncSetAttribute(k_nhsel,   cudaFuncAttributeMaxDynamicSharedMemorySize, NSMEM);
        cudaFuncSetAttribute(k_score,   cudaFuncAttributeMaxDynamicSharedMemorySize, SSMEM);
        attr_done = true;
    }

    k_init   <<<1, 256>>>();
    // fork: k_local on s2, concurrent with k_global on the main stream
    cudaEventRecord(ev_fork, 0);
    cudaStreamWaitEvent(s2, ev_fork, 0);
    k_local  <<<Bn*2, 256, 0, s2>>>(items, adj, emb, a0, a1, a2, a3);
    k_global <<<Bn*2, 256, GSMEM>>>(items, adj_all, num_w, emb, g_w1, g_w2,
                                    seq_features, mask_item);
    cudaEventRecord(ev_join, s2);
    cudaStreamWaitEvent(0, ev_join, 0);
    // join: combine needs both local and global results
    k_combine<<<(Bn*Ldim)/64, 256, CSMEM>>>(g_w3);
    k_seqhs  <<<Bn, 256>>>(alias_inputs, mask_item, glu2_w, glu2_b);
    k_nhsel  <<<(Bn*Ldim)/32, 256, NSMEM>>>(pos_emb, w_1, glu1_w, glu1_b, w_2, mask_item);
    dim3 gs((NOUT + 127)/128, Bn/32);
    k_score  <<<gs, 256, SSMEM>>>(emb, out);
    dim3 ge(NCHUNK, Bn);
    k_expsum <<<ge, 256>>>(out);
    dim3 gn((NOUT + 255)/256, Bn);
    k_scale  <<<gn, 256>>>(out);
}